// round 1
// baseline (speedup 1.0000x reference)
#include <cuda_runtime.h>
#include <cuda_bf16.h>
#include <math.h>

// Problem constants
#define BATCH   2
#define NSEQ    2048
#define CDIM    768
#define HEADS_H 12
#define DHEAD   64
#define TOKENS  (BATCH * NSEQ)          // 4096
#define C3      (3 * CDIM)              // 2304
#define BH      (BATCH * HEADS_H)       // 24

#define SCALE_F 0.125f                  // D^-0.5 = 64^-0.5
#define STEP_F  0.1f
#define LAMBD_F 0.5f
#define EPS_F   1e-12f

// Scratch (static device globals — no allocation)
__device__ float g_qkv[TOKENS * C3];                    // [token, 3C]  (q|k|v), q/k normalized in place
__device__ float g_mpart[4 * BH * 3 * DHEAD * DHEAD];   // split-K partials of M1,M2,M3
__device__ float g_mc[BH * DHEAD * DHEAD];              // combined Mc per head
__device__ float g_ao[TOKENS * CDIM];                   // relu(v + K@Mc - step*lambd), [B,N,H*D]

// ---------------------------------------------------------------------------
// Generic NT GEMM:  C[M,N] = A[M,K] @ B[N,K]^T (+ bias)
// 128x128 block tile, 16 K-chunk, 256 threads, 8x8 microtile, fp32
// Requires M%128==0, N%128==0, K%16==0 (holds for all our shapes)
// ---------------------------------------------------------------------------
__global__ void __launch_bounds__(256) gemm_nt128(
    const float* __restrict__ A, const float* __restrict__ Bw,
    const float* __restrict__ bias, float* __restrict__ C,
    int M, int N, int K)
{
    __shared__ float As[16][128];
    __shared__ float Bs[16][128];

    const int tid  = threadIdx.x;
    const int row0 = blockIdx.y * 128;
    const int col0 = blockIdx.x * 128;
    const int tr   = tid >> 4;          // 0..15
    const int tc   = tid & 15;          // 0..15
    const int lr   = tid >> 2;          // 0..63
    const int lk   = (tid & 3) << 2;    // 0,4,8,12

    float acc[8][8];
    #pragma unroll
    for (int i = 0; i < 8; i++)
        #pragma unroll
        for (int j = 0; j < 8; j++) acc[i][j] = 0.0f;

    const float* Aptr = A  + (size_t)(row0 + lr) * K + lk;
    const float* Bptr = Bw + (size_t)(col0 + lr) * K + lk;

    for (int k0 = 0; k0 < K; k0 += 16) {
        #pragma unroll
        for (int s = 0; s < 2; s++) {
            float4 av = *(const float4*)(Aptr + (size_t)s * 64 * K + k0);
            As[lk + 0][lr + s * 64] = av.x;
            As[lk + 1][lr + s * 64] = av.y;
            As[lk + 2][lr + s * 64] = av.z;
            As[lk + 3][lr + s * 64] = av.w;
            float4 bv = *(const float4*)(Bptr + (size_t)s * 64 * K + k0);
            Bs[lk + 0][lr + s * 64] = bv.x;
            Bs[lk + 1][lr + s * 64] = bv.y;
            Bs[lk + 2][lr + s * 64] = bv.z;
            Bs[lk + 3][lr + s * 64] = bv.w;
        }
        __syncthreads();

        #pragma unroll
        for (int kk = 0; kk < 16; kk++) {
            float a[8], b[8];
            *(float4*)&a[0] = *(const float4*)&As[kk][tr * 8];
            *(float4*)&a[4] = *(const float4*)&As[kk][tr * 8 + 4];
            *(float4*)&b[0] = *(const float4*)&Bs[kk][tc * 8];
            *(float4*)&b[4] = *(const float4*)&Bs[kk][tc * 8 + 4];
            #pragma unroll
            for (int i = 0; i < 8; i++)
                #pragma unroll
                for (int j = 0; j < 8; j++)
                    acc[i][j] += a[i] * b[j];
        }
        __syncthreads();
    }

    #pragma unroll
    for (int i = 0; i < 8; i++) {
        const int r = row0 + tr * 8 + i;
        float* crow = C + (size_t)r * N + col0 + tc * 8;
        if (bias) {
            const float* brow = bias + col0 + tc * 8;
            #pragma unroll
            for (int j = 0; j < 8; j++) acc[i][j] += brow[j];
        }
        *(float4*)(crow + 0) = make_float4(acc[i][0], acc[i][1], acc[i][2], acc[i][3]);
        *(float4*)(crow + 4) = make_float4(acc[i][4], acc[i][5], acc[i][6], acc[i][7]);
    }
}

// ---------------------------------------------------------------------------
// L2-normalize q and k heads in place (per 64-element segment).
// Segments per token: 24 (12 q heads at col s*64, 12 k heads at col 768+(s-12)*64
// which equals s*64 for s in 12..23). One warp per segment, 8 warps per block.
// ---------------------------------------------------------------------------
__global__ void __launch_bounds__(256) norm_qk_kernel()
{
    const int seg   = blockIdx.x * 8 + (threadIdx.x >> 5);
    const int lane  = threadIdx.x & 31;
    const int token = seg / 24;
    const int s     = seg % 24;

    float* p = g_qkv + (size_t)token * C3 + s * 64;
    float v0 = p[lane];
    float v1 = p[lane + 32];
    float ss = v0 * v0 + v1 * v1;
    #pragma unroll
    for (int o = 16; o; o >>= 1) ss += __shfl_xor_sync(0xffffffffu, ss, o);
    float inv = 1.0f / fmaxf(sqrtf(ss), EPS_F);
    p[lane]      = v0 * inv;
    p[lane + 32] = v1 * inv;
}

// ---------------------------------------------------------------------------
// Per (b,h): partial M1 = K^T V, M2 = Q^T V, M3 = Q^T Q over a 512-row chunk.
// grid (BH, 4), 256 threads, each thread a 4x4 patch of each 64x64 output.
// ---------------------------------------------------------------------------
__global__ void __launch_bounds__(256) moments_kernel()
{
    const int bh    = blockIdx.x;     // 0..23
    const int chunk = blockIdx.y;     // 0..3
    const int b = bh / HEADS_H, h = bh % HEADS_H;
    const int tid = threadIdx.x;

    __shared__ float Qs[16][64];
    __shared__ float Ks[16][64];
    __shared__ float Vs[16][64];

    float m1[4][4], m2[4][4], m3[4][4];
    #pragma unroll
    for (int i = 0; i < 4; i++)
        #pragma unroll
        for (int j = 0; j < 4; j++) { m1[i][j] = 0.f; m2[i][j] = 0.f; m3[i][j] = 0.f; }

    const int tr   = tid >> 4;            // 0..15
    const int tc   = tid & 15;            // 0..15
    const int lrow = tid >> 4;            // 0..15 (load row)
    const int lcb  = (tid & 15) << 2;     // 0..60 (load col base)
    const size_t base = (size_t)(b * NSEQ + chunk * 512) * C3 + h * 64;

    for (int n0 = 0; n0 < 512; n0 += 16) {
        const float* p = g_qkv + base + (size_t)(n0 + lrow) * C3 + lcb;
        *(float4*)&Qs[lrow][lcb] = *(const float4*)(p);
        *(float4*)&Ks[lrow][lcb] = *(const float4*)(p + 768);
        *(float4*)&Vs[lrow][lcb] = *(const float4*)(p + 1536);
        __syncthreads();

        #pragma unroll
        for (int kk = 0; kk < 16; kk++) {
            float qr[4], kr[4], vc[4], qc[4];
            #pragma unroll
            for (int i = 0; i < 4; i++) {
                qr[i] = Qs[kk][tr * 4 + i];
                kr[i] = Ks[kk][tr * 4 + i];
            }
            #pragma unroll
            for (int j = 0; j < 4; j++) {
                vc[j] = Vs[kk][tc * 4 + j];
                qc[j] = Qs[kk][tc * 4 + j];
            }
            #pragma unroll
            for (int i = 0; i < 4; i++)
                #pragma unroll
                for (int j = 0; j < 4; j++) {
                    m1[i][j] += kr[i] * vc[j];
                    m2[i][j] += qr[i] * vc[j];
                    m3[i][j] += qr[i] * qc[j];
                }
        }
        __syncthreads();
    }

    const size_t obase = ((size_t)(chunk * BH + bh) * 3) * 4096;
    #pragma unroll
    for (int i = 0; i < 4; i++)
        #pragma unroll
        for (int j = 0; j < 4; j++) {
            const int idx = (tr * 4 + i) * 64 + (tc * 4 + j);
            g_mpart[obase + idx]        = m1[i][j];
            g_mpart[obase + 4096 + idx] = m2[i][j];
            g_mpart[obase + 8192 + idx] = m3[i][j];
        }
}

// ---------------------------------------------------------------------------
// Per head: sum split-K partials, compute Mc = STEP*(SCALE*M2 - SCALE^2*M3@M1)
// ---------------------------------------------------------------------------
__global__ void __launch_bounds__(256) combine_kernel()
{
    const int bh  = blockIdx.x;
    const int tid = threadIdx.x;
    __shared__ float m1s[4096];
    __shared__ float m2s[4096];
    __shared__ float m3s[4096];

    #pragma unroll
    for (int i = 0; i < 16; i++) {
        const int o = tid + i * 256;
        float s1 = 0.f, s2 = 0.f, s3 = 0.f;
        #pragma unroll
        for (int ch = 0; ch < 4; ch++) {
            const size_t ob = ((size_t)(ch * BH + bh) * 3) * 4096;
            s1 += g_mpart[ob + o];
            s2 += g_mpart[ob + 4096 + o];
            s3 += g_mpart[ob + 8192 + o];
        }
        m1s[o] = s1; m2s[o] = s2; m3s[o] = s3;
    }
    __syncthreads();

    const int tr = tid >> 4, tc = tid & 15;
    float p[4][4];
    #pragma unroll
    for (int i = 0; i < 4; i++)
        #pragma unroll
        for (int j = 0; j < 4; j++) p[i][j] = 0.f;

    for (int e = 0; e < 64; e++) {
        float a[4], bb[4];
        #pragma unroll
        for (int i = 0; i < 4; i++) a[i] = m3s[(tr * 4 + i) * 64 + e];
        #pragma unroll
        for (int j = 0; j < 4; j++) bb[j] = m1s[e * 64 + tc * 4 + j];
        #pragma unroll
        for (int i = 0; i < 4; i++)
            #pragma unroll
            for (int j = 0; j < 4; j++) p[i][j] += a[i] * bb[j];
    }

    const float c1 = STEP_F * SCALE_F;
    const float c2 = STEP_F * SCALE_F * SCALE_F;
    #pragma unroll
    for (int i = 0; i < 4; i++)
        #pragma unroll
        for (int j = 0; j < 4; j++) {
            const int idx = (tr * 4 + i) * 64 + (tc * 4 + j);
            g_mc[(size_t)bh * 4096 + idx] = c1 * m2s[idx] - c2 * p[i][j];
        }
}

// ---------------------------------------------------------------------------
// out_head = relu(V + K @ Mc - STEP*LAMBD) written into [B,N,H*D] layout.
// grid (64 n-tiles of 32, BH), 256 threads.
// ---------------------------------------------------------------------------
__global__ void __launch_bounds__(256) outhead_kernel()
{
    const int bh = blockIdx.y;
    const int nt = blockIdx.x;
    const int b = bh / HEADS_H, h = bh % HEADS_H;
    const int tid = threadIdx.x;

    __shared__ float mcs[4096];
    __shared__ float ks[32][64];

    // load Mc (16 floats / thread)
    {
        const float4* src = (const float4*)(g_mc + (size_t)bh * 4096);
        float4* dst = (float4*)mcs;
        #pragma unroll
        for (int i = 0; i < 4; i++) dst[tid + i * 256] = src[tid + i * 256];
    }
    // load K tile (normalized k): rows n0..n0+31
    const int n0 = nt * 32;
    {
        const int r  = tid >> 3;          // 0..31
        const int cb = (tid & 7) << 3;    // 0,8,...,56
        const float* p = g_qkv + (size_t)(b * NSEQ + n0 + r) * C3 + 768 + h * 64 + cb;
        *(float4*)&ks[r][cb]     = *(const float4*)(p);
        *(float4*)&ks[r][cb + 4] = *(const float4*)(p + 4);
    }
    __syncthreads();

    const float cadd = -STEP_F * LAMBD_F;
    #pragma unroll
    for (int i = 0; i < 8; i++) {
        const int o  = tid + i * 256;      // 0..2047 over a 32x64 tile
        const int nl = o >> 6;
        const int d  = o & 63;
        float s = 0.f;
        #pragma unroll
        for (int e = 0; e < 64; e++) s += ks[nl][e] * mcs[e * 64 + d];
        const int tok = b * NSEQ + n0 + nl;
        const float v = g_qkv[(size_t)tok * C3 + 1536 + h * 64 + d];
        g_ao[(size_t)tok * CDIM + h * 64 + d] = fmaxf(v + s + cadd, 0.0f);
    }
}

// ---------------------------------------------------------------------------
extern "C" void kernel_launch(void* const* d_in, const int* in_sizes, int n_in,
                              void* d_out, int out_size)
{
    const float* x     = (const float*)d_in[0];   // [B,N,C]
    const float* Wqkv  = (const float*)d_in[1];   // [3C,C]
    const float* Wproj = (const float*)d_in[2];   // [C,C]
    const float* bproj = (const float*)d_in[3];   // [C]
    float* out = (float*)d_out;                   // [B,N,C]

    float* qkv; cudaGetSymbolAddress((void**)&qkv, g_qkv);
    float* ao;  cudaGetSymbolAddress((void**)&ao,  g_ao);

    // 1. qkv = x @ Wqkv^T
    gemm_nt128<<<dim3(C3 / 128, TOKENS / 128), 256>>>(x, Wqkv, nullptr, qkv,
                                                      TOKENS, C3, CDIM);
    // 2. L2-normalize q,k per head in place
    norm_qk_kernel<<<(TOKENS * 24) / 8, 256>>>();
    // 3. Per-head moment matrices M1=K^T V, M2=Q^T V, M3=Q^T Q (split-K x4)
    moments_kernel<<<dim3(BH, 4), 256>>>();
    // 4. Mc = STEP*(SCALE*M2 - SCALE^2 * M3@M1)
    combine_kernel<<<BH, 256>>>();
    // 5. relu(V + K@Mc - STEP*LAMBD) -> [B,N,C] layout
    outhead_kernel<<<dim3(NSEQ / 32, BH), 256>>>();
    // 6. out = ao @ Wproj^T + bproj
    gemm_nt128<<<dim3(CDIM / 128, TOKENS / 128), 256>>>(ao, Wproj, bproj, out,
                                                        TOKENS, CDIM, CDIM);
}

// round 3
// speedup vs baseline: 1.3605x; 1.3605x over previous
#include <cuda_runtime.h>
#include <cuda_bf16.h>
#include <cstdint>
#include <math.h>

// Problem constants
#define BATCH   2
#define NSEQ    2048
#define CDIM    768
#define HEADS_H 12
#define DHEAD   64
#define TOKENS  (BATCH * NSEQ)          // 4096
#define C3      (3 * CDIM)              // 2304
#define BH      (BATCH * HEADS_H)       // 24

#define SCALE_F 0.125f
#define STEP_F  0.1f
#define LAMBD_F 0.5f
#define EPS_F   1e-12f

// Scratch (static device globals — no allocation)
__device__ float g_qkv[TOKENS * C3];
__device__ float g_mpart[4 * BH * 3 * DHEAD * DHEAD];
__device__ float g_mc[BH * DHEAD * DHEAD];
__device__ float g_ao[TOKENS * CDIM];

__device__ __forceinline__ uint32_t f2tf32(float f) {
    uint32_t u;
    asm("cvt.rna.tf32.f32 %0, %1;" : "=r"(u) : "f"(f));
    return u;
}

__device__ __forceinline__ void mma_tf32_16x8x8(
    float& c0, float& c1, float& c2, float& c3,
    uint32_t a0, uint32_t a1, uint32_t a2, uint32_t a3,
    uint32_t b0, uint32_t b1)
{
    asm volatile(
        "mma.sync.aligned.m16n8k8.row.col.f32.tf32.tf32.f32 "
        "{%0,%1,%2,%3}, {%4,%5,%6,%7}, {%8,%9}, {%0,%1,%2,%3};"
        : "+f"(c0), "+f"(c1), "+f"(c2), "+f"(c3)
        : "r"(a0), "r"(a1), "r"(a2), "r"(a3), "r"(b0), "r"(b1));
}

// ---------------------------------------------------------------------------
// tf32 mma.sync NT GEMM:  C[M,N] = A[M,K] @ B[N,K]^T (+ bias)
// CTA 128x128, K-chunk 16, double-buffered smem, 8 warps, warp tile 64x32.
// smem pitch 20 floats -> conflict-free fragment loads.
// Requires M%128==0, N%128==0, K%16==0.
// ---------------------------------------------------------------------------
#define PITCH 20

__global__ void __launch_bounds__(256, 2) gemm_tf32_mma(
    const float* __restrict__ A, const float* __restrict__ Bw,
    const float* __restrict__ bias, float* __restrict__ C,
    int M, int N, int K)
{
    __shared__ uint32_t As[2][128 * PITCH];
    __shared__ uint32_t Bs[2][128 * PITCH];

    const int tid  = threadIdx.x;
    const int wid  = tid >> 5;
    const int lane = tid & 31;
    const int g    = lane >> 2;        // 0..7
    const int t    = lane & 3;         // 0..3
    const int row0 = blockIdx.y * 128;
    const int col0 = blockIdx.x * 128;
    const int wm0  = (wid >> 2) * 64;  // warp m offset (0 or 64)
    const int wn0  = (wid & 3) * 32;   // warp n offset (0,32,64,96)

    float acc[4][4][4];                // [mi][ni][c0..c3]
    #pragma unroll
    for (int mi = 0; mi < 4; mi++)
        #pragma unroll
        for (int ni = 0; ni < 4; ni++)
            #pragma unroll
            for (int c = 0; c < 4; c++) acc[mi][ni][c] = 0.0f;

    // Loader mapping: 512 float4 slots per tile, 2 per thread.
    const int lr0 = tid >> 2;              // 0..63  (row for slot tid)
    const int ls0 = (tid & 3) << 2;        // 0,4,8,12 (float offset)

    const int nc = K >> 4;
    float4 ra[2], rb[2];

    // Prefetch chunk 0
    #pragma unroll
    for (int i = 0; i < 2; i++) {
        const int row = lr0 + i * 64;
        ra[i] = *(const float4*)(A  + (size_t)(row0 + row) * K + ls0);
        rb[i] = *(const float4*)(Bw + (size_t)(col0 + row) * K + ls0);
    }
    #pragma unroll
    for (int i = 0; i < 2; i++) {
        const int row = lr0 + i * 64;
        uint32_t* ap = &As[0][row * PITCH + ls0];
        ap[0] = f2tf32(ra[i].x); ap[1] = f2tf32(ra[i].y);
        ap[2] = f2tf32(ra[i].z); ap[3] = f2tf32(ra[i].w);
        uint32_t* bp = &Bs[0][row * PITCH + ls0];
        bp[0] = f2tf32(rb[i].x); bp[1] = f2tf32(rb[i].y);
        bp[2] = f2tf32(rb[i].z); bp[3] = f2tf32(rb[i].w);
    }

    for (int c = 0; c < nc; c++) {
        __syncthreads();
        if (c + 1 < nc) {
            const int k0 = (c + 1) << 4;
            #pragma unroll
            for (int i = 0; i < 2; i++) {
                const int row = lr0 + i * 64;
                ra[i] = *(const float4*)(A  + (size_t)(row0 + row) * K + k0 + ls0);
                rb[i] = *(const float4*)(Bw + (size_t)(col0 + row) * K + k0 + ls0);
            }
        }

        const uint32_t* as = As[c & 1];
        const uint32_t* bs = Bs[c & 1];
        #pragma unroll
        for (int ks = 0; ks < 2; ks++) {
            const int kk = ks * 8;
            uint32_t af[4][4], bf[4][2];
            #pragma unroll
            for (int mi = 0; mi < 4; mi++) {
                const int mrow = wm0 + mi * 16;
                af[mi][0] = as[(mrow + g)     * PITCH + kk + t];
                af[mi][1] = as[(mrow + g + 8) * PITCH + kk + t];
                af[mi][2] = as[(mrow + g)     * PITCH + kk + t + 4];
                af[mi][3] = as[(mrow + g + 8) * PITCH + kk + t + 4];
            }
            #pragma unroll
            for (int ni = 0; ni < 4; ni++) {
                const int nrow = wn0 + ni * 8 + g;
                bf[ni][0] = bs[nrow * PITCH + kk + t];
                bf[ni][1] = bs[nrow * PITCH + kk + t + 4];
            }
            #pragma unroll
            for (int mi = 0; mi < 4; mi++)
                #pragma unroll
                for (int ni = 0; ni < 4; ni++)
                    mma_tf32_16x8x8(acc[mi][ni][0], acc[mi][ni][1],
                                    acc[mi][ni][2], acc[mi][ni][3],
                                    af[mi][0], af[mi][1], af[mi][2], af[mi][3],
                                    bf[ni][0], bf[ni][1]);
        }

        if (c + 1 < nc) {
            __syncthreads();
            uint32_t* asn = As[(c + 1) & 1];
            uint32_t* bsn = Bs[(c + 1) & 1];
            #pragma unroll
            for (int i = 0; i < 2; i++) {
                const int row = lr0 + i * 64;
                uint32_t* ap = &asn[row * PITCH + ls0];
                ap[0] = f2tf32(ra[i].x); ap[1] = f2tf32(ra[i].y);
                ap[2] = f2tf32(ra[i].z); ap[3] = f2tf32(ra[i].w);
                uint32_t* bp = &bsn[row * PITCH + ls0];
                bp[0] = f2tf32(rb[i].x); bp[1] = f2tf32(rb[i].y);
                bp[2] = f2tf32(rb[i].z); bp[3] = f2tf32(rb[i].w);
            }
        }
    }

    // Epilogue: C[row][col], c0:(g,2t) c1:(g,2t+1) c2:(g+8,2t) c3:(g+8,2t+1)
    #pragma unroll
    for (int mi = 0; mi < 4; mi++) {
        #pragma unroll
        for (int ni = 0; ni < 4; ni++) {
            const int col = col0 + wn0 + ni * 8 + 2 * t;
            float b0 = 0.f, b1 = 0.f;
            if (bias) { b0 = bias[col]; b1 = bias[col + 1]; }
            const int r0 = row0 + wm0 + mi * 16 + g;
            float2* p0 = (float2*)(C + (size_t)r0 * N + col);
            *p0 = make_float2(acc[mi][ni][0] + b0, acc[mi][ni][1] + b1);
            float2* p1 = (float2*)(C + (size_t)(r0 + 8) * N + col);
            *p1 = make_float2(acc[mi][ni][2] + b0, acc[mi][ni][3] + b1);
        }
    }
}

// ---------------------------------------------------------------------------
// L2-normalize q and k heads in place
// ---------------------------------------------------------------------------
__global__ void __launch_bounds__(256) norm_qk_kernel()
{
    const int seg   = blockIdx.x * 8 + (threadIdx.x >> 5);
    const int lane  = threadIdx.x & 31;
    const int token = seg / 24;
    const int s     = seg % 24;

    float* p = g_qkv + (size_t)token * C3 + s * 64;
    float v0 = p[lane];
    float v1 = p[lane + 32];
    float ss = v0 * v0 + v1 * v1;
    #pragma unroll
    for (int o = 16; o; o >>= 1) ss += __shfl_xor_sync(0xffffffffu, ss, o);
    float inv = 1.0f / fmaxf(sqrtf(ss), EPS_F);
    p[lane]      = v0 * inv;
    p[lane + 32] = v1 * inv;
}

// ---------------------------------------------------------------------------
// Per (b,h) partial moments M1=K^T V, M2=Q^T V, M3=Q^T Q
// ---------------------------------------------------------------------------
__global__ void __launch_bounds__(256) moments_kernel()
{
    const int bh    = blockIdx.x;
    const int chunk = blockIdx.y;
    const int b = bh / HEADS_H, h = bh % HEADS_H;
    const int tid = threadIdx.x;

    __shared__ float Qs[16][64];
    __shared__ float Ks[16][64];
    __shared__ float Vs[16][64];

    float m1[4][4], m2[4][4], m3[4][4];
    #pragma unroll
    for (int i = 0; i < 4; i++)
        #pragma unroll
        for (int j = 0; j < 4; j++) { m1[i][j] = 0.f; m2[i][j] = 0.f; m3[i][j] = 0.f; }

    const int tr   = tid >> 4;
    const int tc   = tid & 15;
    const int lrow = tid >> 4;
    const int lcb  = (tid & 15) << 2;
    const size_t base = (size_t)(b * NSEQ + chunk * 512) * C3 + h * 64;

    for (int n0 = 0; n0 < 512; n0 += 16) {
        const float* p = g_qkv + base + (size_t)(n0 + lrow) * C3 + lcb;
        *(float4*)&Qs[lrow][lcb] = *(const float4*)(p);
        *(float4*)&Ks[lrow][lcb] = *(const float4*)(p + 768);
        *(float4*)&Vs[lrow][lcb] = *(const float4*)(p + 1536);
        __syncthreads();

        #pragma unroll
        for (int kk = 0; kk < 16; kk++) {
            float qr[4], kr[4], vc[4], qc[4];
            #pragma unroll
            for (int i = 0; i < 4; i++) {
                qr[i] = Qs[kk][tr * 4 + i];
                kr[i] = Ks[kk][tr * 4 + i];
            }
            #pragma unroll
            for (int j = 0; j < 4; j++) {
                vc[j] = Vs[kk][tc * 4 + j];
                qc[j] = Qs[kk][tc * 4 + j];
            }
            #pragma unroll
            for (int i = 0; i < 4; i++)
                #pragma unroll
                for (int j = 0; j < 4; j++) {
                    m1[i][j] += kr[i] * vc[j];
                    m2[i][j] += qr[i] * vc[j];
                    m3[i][j] += qr[i] * qc[j];
                }
        }
        __syncthreads();
    }

    const size_t obase = ((size_t)(chunk * BH + bh) * 3) * 4096;
    #pragma unroll
    for (int i = 0; i < 4; i++)
        #pragma unroll
        for (int j = 0; j < 4; j++) {
            const int idx = (tr * 4 + i) * 64 + (tc * 4 + j);
            g_mpart[obase + idx]        = m1[i][j];
            g_mpart[obase + 4096 + idx] = m2[i][j];
            g_mpart[obase + 8192 + idx] = m3[i][j];
        }
}

// ---------------------------------------------------------------------------
// Combine: Mc = STEP*(SCALE*M2 - SCALE^2*M3@M1)
// ---------------------------------------------------------------------------
__global__ void __launch_bounds__(256) combine_kernel()
{
    const int bh  = blockIdx.x;
    const int tid = threadIdx.x;
    __shared__ float m1s[4096];
    __shared__ float m2s[4096];
    __shared__ float m3s[4096];

    #pragma unroll
    for (int i = 0; i < 16; i++) {
        const int o = tid + i * 256;
        float s1 = 0.f, s2 = 0.f, s3 = 0.f;
        #pragma unroll
        for (int ch = 0; ch < 4; ch++) {
            const size_t ob = ((size_t)(ch * BH + bh) * 3) * 4096;
            s1 += g_mpart[ob + o];
            s2 += g_mpart[ob + 4096 + o];
            s3 += g_mpart[ob + 8192 + o];
        }
        m1s[o] = s1; m2s[o] = s2; m3s[o] = s3;
    }
    __syncthreads();

    const int tr = tid >> 4, tc = tid & 15;
    float p[4][4];
    #pragma unroll
    for (int i = 0; i < 4; i++)
        #pragma unroll
        for (int j = 0; j < 4; j++) p[i][j] = 0.f;

    for (int e = 0; e < 64; e++) {
        float a[4], bb[4];
        #pragma unroll
        for (int i = 0; i < 4; i++) a[i] = m3s[(tr * 4 + i) * 64 + e];
        #pragma unroll
        for (int j = 0; j < 4; j++) bb[j] = m1s[e * 64 + tc * 4 + j];
        #pragma unroll
        for (int i = 0; i < 4; i++)
            #pragma unroll
            for (int j = 0; j < 4; j++) p[i][j] += a[i] * bb[j];
    }

    const float c1 = STEP_F * SCALE_F;
    const float c2 = STEP_F * SCALE_F * SCALE_F;
    #pragma unroll
    for (int i = 0; i < 4; i++)
        #pragma unroll
        for (int j = 0; j < 4; j++) {
            const int idx = (tr * 4 + i) * 64 + (tc * 4 + j);
            g_mc[(size_t)bh * 4096 + idx] = c1 * m2s[idx] - c2 * p[i][j];
        }
}

// ---------------------------------------------------------------------------
// out_head = relu(V + K @ Mc - STEP*LAMBD) into [B,N,H*D]
// ---------------------------------------------------------------------------
__global__ void __launch_bounds__(256) outhead_kernel()
{
    const int bh = blockIdx.y;
    const int nt = blockIdx.x;
    const int b = bh / HEADS_H, h = bh % HEADS_H;
    const int tid = threadIdx.x;

    __shared__ float mcs[4096];
    __shared__ float ks[32][64];

    {
        const float4* src = (const float4*)(g_mc + (size_t)bh * 4096);
        float4* dst = (float4*)mcs;
        #pragma unroll
        for (int i = 0; i < 4; i++) dst[tid + i * 256] = src[tid + i * 256];
    }
    const int n0 = nt * 32;
    {
        const int r  = tid >> 3;
        const int cb = (tid & 7) << 3;
        const float* p = g_qkv + (size_t)(b * NSEQ + n0 + r) * C3 + 768 + h * 64 + cb;
        *(float4*)&ks[r][cb]     = *(const float4*)(p);
        *(float4*)&ks[r][cb + 4] = *(const float4*)(p + 4);
    }
    __syncthreads();

    const float cadd = -STEP_F * LAMBD_F;
    #pragma unroll
    for (int i = 0; i < 8; i++) {
        const int o  = tid + i * 256;
        const int nl = o >> 6;
        const int d  = o & 63;
        float s = 0.f;
        #pragma unroll
        for (int e = 0; e < 64; e++) s += ks[nl][e] * mcs[e * 64 + d];
        const int tok = b * NSEQ + n0 + nl;
        const float v = g_qkv[(size_t)tok * C3 + 1536 + h * 64 + d];
        g_ao[(size_t)tok * CDIM + h * 64 + d] = fmaxf(v + s + cadd, 0.0f);
    }
}

// ---------------------------------------------------------------------------
extern "C" void kernel_launch(void* const* d_in, const int* in_sizes, int n_in,
                              void* d_out, int out_size)
{
    const float* x     = (const float*)d_in[0];   // [B,N,C]
    const float* Wqkv  = (const float*)d_in[1];   // [3C,C]
    const float* Wproj = (const float*)d_in[2];   // [C,C]
    const float* bproj = (const float*)d_in[3];   // [C]
    float* out = (float*)d_out;                   // [B,N,C]

    float* qkv; cudaGetSymbolAddress((void**)&qkv, g_qkv);
    float* ao;  cudaGetSymbolAddress((void**)&ao,  g_ao);

    // 1. qkv = x @ Wqkv^T  (tf32 mma.sync)
    gemm_tf32_mma<<<dim3(C3 / 128, TOKENS / 128), 256>>>(
        x, Wqkv, nullptr, qkv, TOKENS, C3, CDIM);
    // 2. L2-normalize q,k per head in place
    norm_qk_kernel<<<(TOKENS * 24) / 8, 256>>>();
    // 3. Per-head moment matrices (split-K x4)
    moments_kernel<<<dim3(BH, 4), 256>>>();
    // 4. Mc = STEP*(SCALE*M2 - SCALE^2 * M3@M1)
    combine_kernel<<<BH, 256>>>();
    // 5. relu(V + K@Mc - STEP*LAMBD) -> [B,N,C] layout
    outhead_kernel<<<dim3(NSEQ / 32, BH), 256>>>();
    // 6. out = ao @ Wproj^T + bproj  (tf32 mma.sync)
    gemm_tf32_mma<<<dim3(CDIM / 128, TOKENS / 128), 256>>>(
        ao, Wproj, bproj, out, TOKENS, CDIM, CDIM);
}

// round 4
// speedup vs baseline: 2.2104x; 1.6247x over previous
#include <cuda_runtime.h>
#include <cuda_bf16.h>
#include <cstdint>
#include <math.h>

// Problem constants
#define BATCH   2
#define NSEQ    2048
#define CDIM    768
#define HEADS_H 12
#define DHEAD   64
#define TOKENS  (BATCH * NSEQ)          // 4096
#define C3      (3 * CDIM)              // 2304
#define BH      (BATCH * HEADS_H)       // 24

#define SCALE_F 0.125f
#define STEP_F  0.1f
#define LAMBD_F 0.5f
#define EPS_F   1e-12f

// Scratch (static device globals — no allocation)
__device__ float g_qkv[TOKENS * C3];
__device__ float g_mpart[4 * BH * 3 * DHEAD * DHEAD];
__device__ float g_mc[BH * DHEAD * DHEAD];
__device__ float g_ao[TOKENS * CDIM];
// Pre-rounded tf32 operands (fp32 bit patterns with low mantissa zeroed)
__device__ float g_xr[TOKENS * CDIM];
__device__ float g_wqkvr[C3 * CDIM];
__device__ float g_wprojr[CDIM * CDIM];

__device__ __forceinline__ uint32_t f2tf32(float f) {
    uint32_t u;
    asm("cvt.rna.tf32.f32 %0, %1;" : "=r"(u) : "f"(f));
    return u;
}
__device__ __forceinline__ uint32_t smem_u32(const void* p) {
    uint32_t a;
    asm("{ .reg .u64 t; cvta.to.shared.u64 t, %1; cvt.u32.u64 %0, t; }"
        : "=r"(a) : "l"(p));
    return a;
}

__device__ __forceinline__ void mma_tf32_16x8x8(
    float& c0, float& c1, float& c2, float& c3,
    uint32_t a0, uint32_t a1, uint32_t a2, uint32_t a3,
    uint32_t b0, uint32_t b1)
{
    asm volatile(
        "mma.sync.aligned.m16n8k8.row.col.f32.tf32.tf32.f32 "
        "{%0,%1,%2,%3}, {%4,%5,%6,%7}, {%8,%9}, {%0,%1,%2,%3};"
        : "+f"(c0), "+f"(c1), "+f"(c2), "+f"(c3)
        : "r"(a0), "r"(a1), "r"(a2), "r"(a3), "r"(b0), "r"(b1));
}

// ---------------------------------------------------------------------------
// Pre-round fp32 -> tf32-representable fp32 (vectorized)
// ---------------------------------------------------------------------------
__global__ void __launch_bounds__(256) round_tf32_kernel(
    const float* __restrict__ src, float* __restrict__ dst, int n4)
{
    const int i = blockIdx.x * 256 + threadIdx.x;
    if (i < n4) {
        float4 v = ((const float4*)src)[i];
        float4 o;
        o.x = __uint_as_float(f2tf32(v.x));
        o.y = __uint_as_float(f2tf32(v.y));
        o.z = __uint_as_float(f2tf32(v.z));
        o.w = __uint_as_float(f2tf32(v.w));
        ((float4*)dst)[i] = o;
    }
}

// ---------------------------------------------------------------------------
// tf32 mma.sync NT GEMM with cp.async 4-stage pipeline.
// C[M,N] = A[M,K] @ B[N,K]^T (+bias). A,B must be pre-rounded to tf32 grid.
// CTA 128x128, K-chunk 16, 8 warps (warp tile 64x32), pitch-20 smem.
// One __syncthreads per chunk.
// ---------------------------------------------------------------------------
#define PITCH   20
#define STAGES  4
#define STG_U32 (128 * PITCH)                       // u32 per matrix stage
#define GSMEM_BYTES (STAGES * STG_U32 * 4 * 2)      // 81920

__global__ void __launch_bounds__(256, 2) gemm_tf32_pipe(
    const float* __restrict__ A, const float* __restrict__ Bw,
    const float* __restrict__ bias, float* __restrict__ C,
    int M, int N, int K)
{
    extern __shared__ uint32_t sm[];
    uint32_t* As = sm;
    uint32_t* Bs = sm + STAGES * STG_U32;

    const int tid  = threadIdx.x;
    const int wid  = tid >> 5;
    const int lane = tid & 31;
    const int g    = lane >> 2;
    const int t    = lane & 3;
    const int row0 = blockIdx.y * 128;
    const int col0 = blockIdx.x * 128;
    const int wm0  = (wid >> 2) * 64;
    const int wn0  = (wid & 3) * 32;

    float acc[4][4][4];
    #pragma unroll
    for (int mi = 0; mi < 4; mi++)
        #pragma unroll
        for (int ni = 0; ni < 4; ni++)
            #pragma unroll
            for (int c = 0; c < 4; c++) acc[mi][ni][c] = 0.0f;

    // Loader mapping: 512 float4 per tile; thread covers rows lrow, lrow+64.
    const int lrow = tid >> 2;            // 0..63
    const int lseg = (tid & 3) << 2;      // 0,4,8,12

    const float* aptr = A  + (size_t)(row0 + lrow) * K + lseg;
    const float* bptr = Bw + (size_t)(col0 + lrow) * K + lseg;
    const uint32_t a_sb = smem_u32(As) + (lrow * PITCH + lseg) * 4;
    const uint32_t b_sb = smem_u32(Bs) + (lrow * PITCH + lseg) * 4;

    const int nc = K >> 4;

    // --- prologue: fill STAGES-1 stages ---
    #pragma unroll
    for (int s = 0; s < STAGES - 1; s++) {
        const int k0 = s << 4;
        #pragma unroll
        for (int i = 0; i < 2; i++) {
            const uint32_t so = s * STG_U32 * 4 + i * 64 * PITCH * 4;
            asm volatile("cp.async.cg.shared.global [%0], [%1], 16;"
                :: "r"(a_sb + so), "l"(aptr + (size_t)i * 64 * K + k0) : "memory");
            asm volatile("cp.async.cg.shared.global [%0], [%1], 16;"
                :: "r"(b_sb + so), "l"(bptr + (size_t)i * 64 * K + k0) : "memory");
        }
        asm volatile("cp.async.commit_group;" ::: "memory");
    }

    for (int c = 0; c < nc; c++) {
        asm volatile("cp.async.wait_group %0;" :: "n"(STAGES - 2) : "memory");
        __syncthreads();

        // issue chunk c+STAGES-1 into stage (c+STAGES-1)%STAGES (safe: barrier
        // above guarantees all warps finished computing that stage last iter)
        const int cn = c + STAGES - 1;
        if (cn < nc) {
            const int s  = cn & (STAGES - 1);
            const int k0 = cn << 4;
            #pragma unroll
            for (int i = 0; i < 2; i++) {
                const uint32_t so = s * STG_U32 * 4 + i * 64 * PITCH * 4;
                asm volatile("cp.async.cg.shared.global [%0], [%1], 16;"
                    :: "r"(a_sb + so), "l"(aptr + (size_t)i * 64 * K + k0) : "memory");
                asm volatile("cp.async.cg.shared.global [%0], [%1], 16;"
                    :: "r"(b_sb + so), "l"(bptr + (size_t)i * 64 * K + k0) : "memory");
            }
        }
        asm volatile("cp.async.commit_group;" ::: "memory");

        // compute stage c%STAGES
        const uint32_t* as = As + (c & (STAGES - 1)) * STG_U32;
        const uint32_t* bs = Bs + (c & (STAGES - 1)) * STG_U32;
        #pragma unroll
        for (int ks = 0; ks < 2; ks++) {
            const int kk = ks * 8;
            uint32_t af[4][4], bf[4][2];
            #pragma unroll
            for (int mi = 0; mi < 4; mi++) {
                const int mrow = wm0 + mi * 16;
                af[mi][0] = as[(mrow + g)     * PITCH + kk + t];
                af[mi][1] = as[(mrow + g + 8) * PITCH + kk + t];
                af[mi][2] = as[(mrow + g)     * PITCH + kk + t + 4];
                af[mi][3] = as[(mrow + g + 8) * PITCH + kk + t + 4];
            }
            #pragma unroll
            for (int ni = 0; ni < 4; ni++) {
                const int nrow = wn0 + ni * 8 + g;
                bf[ni][0] = bs[nrow * PITCH + kk + t];
                bf[ni][1] = bs[nrow * PITCH + kk + t + 4];
            }
            #pragma unroll
            for (int mi = 0; mi < 4; mi++)
                #pragma unroll
                for (int ni = 0; ni < 4; ni++)
                    mma_tf32_16x8x8(acc[mi][ni][0], acc[mi][ni][1],
                                    acc[mi][ni][2], acc[mi][ni][3],
                                    af[mi][0], af[mi][1], af[mi][2], af[mi][3],
                                    bf[ni][0], bf[ni][1]);
        }
    }

    // Epilogue
    #pragma unroll
    for (int mi = 0; mi < 4; mi++) {
        #pragma unroll
        for (int ni = 0; ni < 4; ni++) {
            const int col = col0 + wn0 + ni * 8 + 2 * t;
            float b0 = 0.f, b1 = 0.f;
            if (bias) { b0 = bias[col]; b1 = bias[col + 1]; }
            const int r0 = row0 + wm0 + mi * 16 + g;
            *(float2*)(C + (size_t)r0 * N + col) =
                make_float2(acc[mi][ni][0] + b0, acc[mi][ni][1] + b1);
            *(float2*)(C + (size_t)(r0 + 8) * N + col) =
                make_float2(acc[mi][ni][2] + b0, acc[mi][ni][3] + b1);
        }
    }
}

// ---------------------------------------------------------------------------
// L2-normalize q and k heads in place
// ---------------------------------------------------------------------------
__global__ void __launch_bounds__(256) norm_qk_kernel()
{
    const int seg   = blockIdx.x * 8 + (threadIdx.x >> 5);
    const int lane  = threadIdx.x & 31;
    const int token = seg / 24;
    const int s     = seg % 24;

    float* p = g_qkv + (size_t)token * C3 + s * 64;
    float v0 = p[lane];
    float v1 = p[lane + 32];
    float ss = v0 * v0 + v1 * v1;
    #pragma unroll
    for (int o = 16; o; o >>= 1) ss += __shfl_xor_sync(0xffffffffu, ss, o);
    float inv = 1.0f / fmaxf(sqrtf(ss), EPS_F);
    p[lane]      = v0 * inv;
    p[lane + 32] = v1 * inv;
}

// ---------------------------------------------------------------------------
// Per (b,h) partial moments M1=K^T V, M2=Q^T V, M3=Q^T Q
// ---------------------------------------------------------------------------
__global__ void __launch_bounds__(256) moments_kernel()
{
    const int bh    = blockIdx.x;
    const int chunk = blockIdx.y;
    const int b = bh / HEADS_H, h = bh % HEADS_H;
    const int tid = threadIdx.x;

    __shared__ float Qs[16][64];
    __shared__ float Ks[16][64];
    __shared__ float Vs[16][64];

    float m1[4][4], m2[4][4], m3[4][4];
    #pragma unroll
    for (int i = 0; i < 4; i++)
        #pragma unroll
        for (int j = 0; j < 4; j++) { m1[i][j] = 0.f; m2[i][j] = 0.f; m3[i][j] = 0.f; }

    const int tr   = tid >> 4;
    const int tc   = tid & 15;
    const int lrow = tid >> 4;
    const int lcb  = (tid & 15) << 2;
    const size_t base = (size_t)(b * NSEQ + chunk * 512) * C3 + h * 64;

    for (int n0 = 0; n0 < 512; n0 += 16) {
        const float* p = g_qkv + base + (size_t)(n0 + lrow) * C3 + lcb;
        *(float4*)&Qs[lrow][lcb] = *(const float4*)(p);
        *(float4*)&Ks[lrow][lcb] = *(const float4*)(p + 768);
        *(float4*)&Vs[lrow][lcb] = *(const float4*)(p + 1536);
        __syncthreads();

        #pragma unroll
        for (int kk = 0; kk < 16; kk++) {
            float qr[4], kr[4], vc[4], qc[4];
            #pragma unroll
            for (int i = 0; i < 4; i++) {
                qr[i] = Qs[kk][tr * 4 + i];
                kr[i] = Ks[kk][tr * 4 + i];
            }
            #pragma unroll
            for (int j = 0; j < 4; j++) {
                vc[j] = Vs[kk][tc * 4 + j];
                qc[j] = Qs[kk][tc * 4 + j];
            }
            #pragma unroll
            for (int i = 0; i < 4; i++)
                #pragma unroll
                for (int j = 0; j < 4; j++) {
                    m1[i][j] += kr[i] * vc[j];
                    m2[i][j] += qr[i] * vc[j];
                    m3[i][j] += qr[i] * qc[j];
                }
        }
        __syncthreads();
    }

    const size_t obase = ((size_t)(chunk * BH + bh) * 3) * 4096;
    #pragma unroll
    for (int i = 0; i < 4; i++)
        #pragma unroll
        for (int j = 0; j < 4; j++) {
            const int idx = (tr * 4 + i) * 64 + (tc * 4 + j);
            g_mpart[obase + idx]        = m1[i][j];
            g_mpart[obase + 4096 + idx] = m2[i][j];
            g_mpart[obase + 8192 + idx] = m3[i][j];
        }
}

// ---------------------------------------------------------------------------
// Combine: Mc = STEP*(SCALE*M2 - SCALE^2*M3@M1)
// ---------------------------------------------------------------------------
__global__ void __launch_bounds__(256) combine_kernel()
{
    const int bh  = blockIdx.x;
    const int tid = threadIdx.x;
    __shared__ float m1s[4096];
    __shared__ float m2s[4096];
    __shared__ float m3s[4096];

    #pragma unroll
    for (int i = 0; i < 16; i++) {
        const int o = tid + i * 256;
        float s1 = 0.f, s2 = 0.f, s3 = 0.f;
        #pragma unroll
        for (int ch = 0; ch < 4; ch++) {
            const size_t ob = ((size_t)(ch * BH + bh) * 3) * 4096;
            s1 += g_mpart[ob + o];
            s2 += g_mpart[ob + 4096 + o];
            s3 += g_mpart[ob + 8192 + o];
        }
        m1s[o] = s1; m2s[o] = s2; m3s[o] = s3;
    }
    __syncthreads();

    const int tr = tid >> 4, tc = tid & 15;
    float p[4][4];
    #pragma unroll
    for (int i = 0; i < 4; i++)
        #pragma unroll
        for (int j = 0; j < 4; j++) p[i][j] = 0.f;

    for (int e = 0; e < 64; e++) {
        float a[4], bb[4];
        #pragma unroll
        for (int i = 0; i < 4; i++) a[i] = m3s[(tr * 4 + i) * 64 + e];
        #pragma unroll
        for (int j = 0; j < 4; j++) bb[j] = m1s[e * 64 + tc * 4 + j];
        #pragma unroll
        for (int i = 0; i < 4; i++)
            #pragma unroll
            for (int j = 0; j < 4; j++) p[i][j] += a[i] * bb[j];
    }

    const float c1 = STEP_F * SCALE_F;
    const float c2 = STEP_F * SCALE_F * SCALE_F;
    #pragma unroll
    for (int i = 0; i < 4; i++)
        #pragma unroll
        for (int j = 0; j < 4; j++) {
            const int idx = (tr * 4 + i) * 64 + (tc * 4 + j);
            g_mc[(size_t)bh * 4096 + idx] = c1 * m2s[idx] - c2 * p[i][j];
        }
}

// ---------------------------------------------------------------------------
// out_head = relu(V + K @ Mc - STEP*LAMBD), tf32-rounded, into [B,N,H*D]
// ---------------------------------------------------------------------------
__global__ void __launch_bounds__(256) outhead_kernel()
{
    const int bh = blockIdx.y;
    const int nt = blockIdx.x;
    const int b = bh / HEADS_H, h = bh % HEADS_H;
    const int tid = threadIdx.x;

    __shared__ float mcs[4096];
    __shared__ float ks[32][64];

    {
        const float4* src = (const float4*)(g_mc + (size_t)bh * 4096);
        float4* dst = (float4*)mcs;
        #pragma unroll
        for (int i = 0; i < 4; i++) dst[tid + i * 256] = src[tid + i * 256];
    }
    const int n0 = nt * 32;
    {
        const int r  = tid >> 3;
        const int cb = (tid & 7) << 3;
        const float* p = g_qkv + (size_t)(b * NSEQ + n0 + r) * C3 + 768 + h * 64 + cb;
        *(float4*)&ks[r][cb]     = *(const float4*)(p);
        *(float4*)&ks[r][cb + 4] = *(const float4*)(p + 4);
    }
    __syncthreads();

    const float cadd = -STEP_F * LAMBD_F;
    #pragma unroll
    for (int i = 0; i < 8; i++) {
        const int o  = tid + i * 256;
        const int nl = o >> 6;
        const int d  = o & 63;
        float s = 0.f;
        #pragma unroll
        for (int e = 0; e < 64; e++) s += ks[nl][e] * mcs[e * 64 + d];
        const int tok = b * NSEQ + n0 + nl;
        const float v = g_qkv[(size_t)tok * C3 + 1536 + h * 64 + d];
        const float r = fmaxf(v + s + cadd, 0.0f);
        // tf32-round so GEMM2 can consume via cp.async directly
        g_ao[(size_t)tok * CDIM + h * 64 + d] = __uint_as_float(f2tf32(r));
    }
}

// ---------------------------------------------------------------------------
extern "C" void kernel_launch(void* const* d_in, const int* in_sizes, int n_in,
                              void* d_out, int out_size)
{
    const float* x     = (const float*)d_in[0];   // [B,N,C]
    const float* Wqkv  = (const float*)d_in[1];   // [3C,C]
    const float* Wproj = (const float*)d_in[2];   // [C,C]
    const float* bproj = (const float*)d_in[3];   // [C]
    float* out = (float*)d_out;                   // [B,N,C]

    float* qkv;  cudaGetSymbolAddress((void**)&qkv,  g_qkv);
    float* ao;   cudaGetSymbolAddress((void**)&ao,   g_ao);
    float* xr;   cudaGetSymbolAddress((void**)&xr,   g_xr);
    float* wqr;  cudaGetSymbolAddress((void**)&wqr,  g_wqkvr);
    float* wpr;  cudaGetSymbolAddress((void**)&wpr,  g_wprojr);

    cudaFuncSetAttribute(gemm_tf32_pipe,
                         cudaFuncAttributeMaxDynamicSharedMemorySize,
                         GSMEM_BYTES);

    // 0. Pre-round operands to tf32 grid
    round_tf32_kernel<<<(TOKENS * CDIM / 4 + 255) / 256, 256>>>(x, xr, TOKENS * CDIM / 4);
    round_tf32_kernel<<<(C3 * CDIM / 4 + 255) / 256, 256>>>(Wqkv, wqr, C3 * CDIM / 4);
    round_tf32_kernel<<<(CDIM * CDIM / 4 + 255) / 256, 256>>>(Wproj, wpr, CDIM * CDIM / 4);

    // 1. qkv = x @ Wqkv^T (tf32 mma, cp.async pipeline)
    gemm_tf32_pipe<<<dim3(C3 / 128, TOKENS / 128), 256, GSMEM_BYTES>>>(
        xr, wqr, nullptr, qkv, TOKENS, C3, CDIM);
    // 2. L2-normalize q,k per head in place
    norm_qk_kernel<<<(TOKENS * 24) / 8, 256>>>();
    // 3. Per-head moment matrices (split-K x4)
    moments_kernel<<<dim3(BH, 4), 256>>>();
    // 4. Mc = STEP*(SCALE*M2 - SCALE^2 * M3@M1)
    combine_kernel<<<BH, 256>>>();
    // 5. relu(V + K@Mc - STEP*LAMBD) -> [B,N,C], tf32-rounded
    outhead_kernel<<<dim3(NSEQ / 32, BH), 256>>>();
    // 6. out = ao @ Wproj^T + bproj
    gemm_tf32_pipe<<<dim3(CDIM / 128, TOKENS / 128), 256, GSMEM_BYTES>>>(
        ao, wpr, bproj, out, TOKENS, CDIM, CDIM);
}

// round 7
// speedup vs baseline: 2.5104x; 1.1358x over previous
#include <cuda_runtime.h>
#include <cuda_bf16.h>
#include <cstdint>
#include <math.h>

// Problem constants
#define BATCH   2
#define NSEQ    2048
#define CDIM    768
#define HEADS_H 12
#define DHEAD   64
#define TOKENS  (BATCH * NSEQ)          // 4096
#define C3      (3 * CDIM)              // 2304
#define BH      (BATCH * HEADS_H)       // 24
#define MCH     8                       // moments token-split chunks

#define SCALE_F 0.125f
#define STEP_F  0.1f
#define LAMBD_F 0.5f
#define EPS_F   1e-12f

// Scratch (static device globals — no allocation)
__device__ float g_qkv[TOKENS * C3];
__device__ float g_mpart[MCH * BH * 3 * DHEAD * DHEAD];
__device__ float g_mc[BH * DHEAD * DHEAD];
__device__ float g_ao[TOKENS * CDIM];
__device__ float g_xr[TOKENS * CDIM];
__device__ float g_wqkvr[C3 * CDIM];
__device__ float g_wprojr[CDIM * CDIM];

__device__ __forceinline__ uint32_t f2tf32(float f) {
    uint32_t u;
    asm("cvt.rna.tf32.f32 %0, %1;" : "=r"(u) : "f"(f));
    return u;
}
__device__ __forceinline__ uint32_t smem_u32(const void* p) {
    uint32_t a;
    asm("{ .reg .u64 t; cvta.to.shared.u64 t, %1; cvt.u32.u64 %0, t; }"
        : "=r"(a) : "l"(p));
    return a;
}

__device__ __forceinline__ void mma_tf32_16x8x8(
    float& c0, float& c1, float& c2, float& c3,
    uint32_t a0, uint32_t a1, uint32_t a2, uint32_t a3,
    uint32_t b0, uint32_t b1)
{
    asm volatile(
        "mma.sync.aligned.m16n8k8.row.col.f32.tf32.tf32.f32 "
        "{%0,%1,%2,%3}, {%4,%5,%6,%7}, {%8,%9}, {%0,%1,%2,%3};"
        : "+f"(c0), "+f"(c1), "+f"(c2), "+f"(c3)
        : "r"(a0), "r"(a1), "r"(a2), "r"(a3), "r"(b0), "r"(b1));
}

// ---------------------------------------------------------------------------
// Pre-round fp32 -> tf32-representable fp32
// ---------------------------------------------------------------------------
__global__ void __launch_bounds__(256) round_tf32_kernel(
    const float* __restrict__ src, float* __restrict__ dst, int n4)
{
    const int i = blockIdx.x * 256 + threadIdx.x;
    if (i < n4) {
        float4 v = ((const float4*)src)[i];
        float4 o;
        o.x = __uint_as_float(f2tf32(v.x));
        o.y = __uint_as_float(f2tf32(v.y));
        o.z = __uint_as_float(f2tf32(v.z));
        o.w = __uint_as_float(f2tf32(v.w));
        ((float4*)dst)[i] = o;
    }
}

// ---------------------------------------------------------------------------
// tf32 mma.sync NT GEMM, cp.async 4-stage pipeline.
// CTA 128x128, 4 warps, warp tile 64x64, K-chunk 16, pitch-20 smem.
// ---------------------------------------------------------------------------
#define PITCH   20
#define STAGES  4
#define STG_U32 (128 * PITCH)
#define GSMEM_BYTES (STAGES * STG_U32 * 4 * 2)      // 81920

__global__ void __launch_bounds__(128, 2) gemm_tf32_pipe(
    const float* __restrict__ A, const float* __restrict__ Bw,
    const float* __restrict__ bias, float* __restrict__ C,
    int M, int N, int K)
{
    extern __shared__ uint32_t sm[];
    uint32_t* As = sm;
    uint32_t* Bs = sm + STAGES * STG_U32;

    const int tid  = threadIdx.x;
    const int wid  = tid >> 5;
    const int lane = tid & 31;
    const int g    = lane >> 2;
    const int t    = lane & 3;
    const int row0 = blockIdx.y * 128;
    const int col0 = blockIdx.x * 128;
    const int wm0  = (wid >> 1) * 64;
    const int wn0  = (wid & 1) * 64;

    float acc[4][8][4];
    #pragma unroll
    for (int mi = 0; mi < 4; mi++)
        #pragma unroll
        for (int ni = 0; ni < 8; ni++)
            #pragma unroll
            for (int c = 0; c < 4; c++) acc[mi][ni][c] = 0.0f;

    // Loader: 512 float4 per matrix tile; 128 threads -> 4 each (rows +32i)
    const int lrow = tid >> 2;            // 0..31
    const int lseg = (tid & 3) << 2;      // 0,4,8,12

    const float* aptr = A  + (size_t)(row0 + lrow) * K + lseg;
    const float* bptr = Bw + (size_t)(col0 + lrow) * K + lseg;
    const uint32_t a_sb = smem_u32(As) + (lrow * PITCH + lseg) * 4;
    const uint32_t b_sb = smem_u32(Bs) + (lrow * PITCH + lseg) * 4;

    const int nc = K >> 4;

    #pragma unroll
    for (int s = 0; s < STAGES - 1; s++) {
        const int k0 = s << 4;
        #pragma unroll
        for (int i = 0; i < 4; i++) {
            const uint32_t so = s * STG_U32 * 4 + i * 32 * PITCH * 4;
            asm volatile("cp.async.cg.shared.global [%0], [%1], 16;"
                :: "r"(a_sb + so), "l"(aptr + (size_t)i * 32 * K + k0) : "memory");
            asm volatile("cp.async.cg.shared.global [%0], [%1], 16;"
                :: "r"(b_sb + so), "l"(bptr + (size_t)i * 32 * K + k0) : "memory");
        }
        asm volatile("cp.async.commit_group;" ::: "memory");
    }

    for (int c = 0; c < nc; c++) {
        asm volatile("cp.async.wait_group %0;" :: "n"(STAGES - 2) : "memory");
        __syncthreads();

        const int cn = c + STAGES - 1;
        if (cn < nc) {
            const int s  = cn & (STAGES - 1);
            const int k0 = cn << 4;
            #pragma unroll
            for (int i = 0; i < 4; i++) {
                const uint32_t so = s * STG_U32 * 4 + i * 32 * PITCH * 4;
                asm volatile("cp.async.cg.shared.global [%0], [%1], 16;"
                    :: "r"(a_sb + so), "l"(aptr + (size_t)i * 32 * K + k0) : "memory");
                asm volatile("cp.async.cg.shared.global [%0], [%1], 16;"
                    :: "r"(b_sb + so), "l"(bptr + (size_t)i * 32 * K + k0) : "memory");
            }
        }
        asm volatile("cp.async.commit_group;" ::: "memory");

        const uint32_t* as = As + (c & (STAGES - 1)) * STG_U32;
        const uint32_t* bs = Bs + (c & (STAGES - 1)) * STG_U32;
        #pragma unroll
        for (int ks = 0; ks < 2; ks++) {
            const int kk = ks * 8;
            uint32_t af[4][4], bf[8][2];
            #pragma unroll
            for (int mi = 0; mi < 4; mi++) {
                const int mrow = wm0 + mi * 16;
                af[mi][0] = as[(mrow + g)     * PITCH + kk + t];
                af[mi][1] = as[(mrow + g + 8) * PITCH + kk + t];
                af[mi][2] = as[(mrow + g)     * PITCH + kk + t + 4];
                af[mi][3] = as[(mrow + g + 8) * PITCH + kk + t + 4];
            }
            #pragma unroll
            for (int ni = 0; ni < 8; ni++) {
                const int nrow = wn0 + ni * 8 + g;
                bf[ni][0] = bs[nrow * PITCH + kk + t];
                bf[ni][1] = bs[nrow * PITCH + kk + t + 4];
            }
            #pragma unroll
            for (int mi = 0; mi < 4; mi++)
                #pragma unroll
                for (int ni = 0; ni < 8; ni++)
                    mma_tf32_16x8x8(acc[mi][ni][0], acc[mi][ni][1],
                                    acc[mi][ni][2], acc[mi][ni][3],
                                    af[mi][0], af[mi][1], af[mi][2], af[mi][3],
                                    bf[ni][0], bf[ni][1]);
        }
    }

    #pragma unroll
    for (int mi = 0; mi < 4; mi++) {
        #pragma unroll
        for (int ni = 0; ni < 8; ni++) {
            const int col = col0 + wn0 + ni * 8 + 2 * t;
            float b0 = 0.f, b1 = 0.f;
            if (bias) { b0 = bias[col]; b1 = bias[col + 1]; }
            const int r0 = row0 + wm0 + mi * 16 + g;
            *(float2*)(C + (size_t)r0 * N + col) =
                make_float2(acc[mi][ni][0] + b0, acc[mi][ni][1] + b1);
            *(float2*)(C + (size_t)(r0 + 8) * N + col) =
                make_float2(acc[mi][ni][2] + b0, acc[mi][ni][3] + b1);
        }
    }
}

// ---------------------------------------------------------------------------
// L2-normalize q and k heads in place
// ---------------------------------------------------------------------------
__global__ void __launch_bounds__(256) norm_qk_kernel()
{
    const int seg   = blockIdx.x * 8 + (threadIdx.x >> 5);
    const int lane  = threadIdx.x & 31;
    const int token = seg / 24;
    const int s     = seg % 24;

    float* p = g_qkv + (size_t)token * C3 + s * 64;
    float v0 = p[lane];
    float v1 = p[lane + 32];
    float ss = v0 * v0 + v1 * v1;
    #pragma unroll
    for (int o = 16; o; o >>= 1) ss += __shfl_xor_sync(0xffffffffu, ss, o);
    float inv = 1.0f / fmaxf(sqrtf(ss), EPS_F);
    p[lane]      = v0 * inv;
    p[lane + 32] = v1 * inv;
}

// ---------------------------------------------------------------------------
// Moments via tf32 mma: per (b,h,chunk of 256 tokens), partial
// M1 = K^T V, M2 = Q^T V, M3 = Q^T Q. grid (BH, MCH), 192 threads (6 warps).
// Warp w: output o=w>>1, m-half (w&1)*32. Tiles staged transposed: T[d][tok].
// ---------------------------------------------------------------------------
__global__ void __launch_bounds__(192) moments_mma_kernel()
{
    __shared__ float QT[64][17];
    __shared__ float KT[64][17];
    __shared__ float VT[64][17];

    const int bh = blockIdx.x;
    const int ch = blockIdx.y;
    const int b = bh / HEADS_H, h = bh % HEADS_H;
    const int tid  = threadIdx.x;
    const int wid  = tid >> 5;           // 0..5
    const int lane = tid & 31;
    const int g    = lane >> 2;
    const int t    = lane & 3;
    const int o    = wid >> 1;           // 0=M1,1=M2,2=M3
    const int mhalf = (wid & 1) * 32;

    // load mapping: mat = tid/64 (0=Q,1=K,2=V), idx = tid%64
    const int mat = tid >> 6;
    const int idx = tid & 63;
    const int ltok = idx >> 2;           // 0..15
    const int ldg  = (idx & 3) << 4;     // 0,16,32,48

    float (*Tdst)[17] = (mat == 0) ? QT : (mat == 1) ? KT : VT;
    const size_t base = (size_t)(b * NSEQ + ch * (NSEQ / MCH)) * C3 + mat * 768 + h * 64;

    float acc[2][8][4];
    #pragma unroll
    for (int mi = 0; mi < 2; mi++)
        #pragma unroll
        for (int ni = 0; ni < 8; ni++)
            #pragma unroll
            for (int c = 0; c < 4; c++) acc[mi][ni][c] = 0.0f;

    for (int it = 0; it < (NSEQ / MCH) / 16; it++) {
        const float* src = g_qkv + base + (size_t)(it * 16 + ltok) * C3 + ldg;
        float4 v[4];
        #pragma unroll
        for (int j = 0; j < 4; j++) v[j] = *(const float4*)(src + j * 4);
        __syncthreads();    // previous compute done before overwrite
        #pragma unroll
        for (int j = 0; j < 4; j++) {
            Tdst[ldg + j * 4 + 0][ltok] = __uint_as_float(f2tf32(v[j].x));
            Tdst[ldg + j * 4 + 1][ltok] = __uint_as_float(f2tf32(v[j].y));
            Tdst[ldg + j * 4 + 2][ltok] = __uint_as_float(f2tf32(v[j].z));
            Tdst[ldg + j * 4 + 3][ltok] = __uint_as_float(f2tf32(v[j].w));
        }
        __syncthreads();

        const float (*Am)[17] = (o == 0) ? KT : QT;
        const float (*Bm)[17] = (o == 2) ? QT : VT;
        #pragma unroll
        for (int kk = 0; kk < 16; kk += 8) {
            uint32_t af[2][4], bf[8][2];
            #pragma unroll
            for (int mi = 0; mi < 2; mi++) {
                const int mrow = mhalf + mi * 16;
                af[mi][0] = __float_as_uint(Am[mrow + g][kk + t]);
                af[mi][1] = __float_as_uint(Am[mrow + g + 8][kk + t]);
                af[mi][2] = __float_as_uint(Am[mrow + g][kk + t + 4]);
                af[mi][3] = __float_as_uint(Am[mrow + g + 8][kk + t + 4]);
            }
            #pragma unroll
            for (int ni = 0; ni < 8; ni++) {
                bf[ni][0] = __float_as_uint(Bm[ni * 8 + g][kk + t]);
                bf[ni][1] = __float_as_uint(Bm[ni * 8 + g][kk + t + 4]);
            }
            #pragma unroll
            for (int mi = 0; mi < 2; mi++)
                #pragma unroll
                for (int ni = 0; ni < 8; ni++)
                    mma_tf32_16x8x8(acc[mi][ni][0], acc[mi][ni][1],
                                    acc[mi][ni][2], acc[mi][ni][3],
                                    af[mi][0], af[mi][1], af[mi][2], af[mi][3],
                                    bf[ni][0], bf[ni][1]);
        }
    }

    float* outp = g_mpart + ((size_t)(ch * BH + bh) * 3 + o) * 4096;
    #pragma unroll
    for (int mi = 0; mi < 2; mi++) {
        #pragma unroll
        for (int ni = 0; ni < 8; ni++) {
            const int row = mhalf + mi * 16 + g;
            const int col = ni * 8 + 2 * t;
            *(float2*)(outp + row * 64 + col) =
                make_float2(acc[mi][ni][0], acc[mi][ni][1]);
            *(float2*)(outp + (row + 8) * 64 + col) =
                make_float2(acc[mi][ni][2], acc[mi][ni][3]);
        }
    }
}

// ---------------------------------------------------------------------------
// Combine: Mc = STEP*(SCALE*M2 - SCALE^2*M3@M1), summing MCH partials
// ---------------------------------------------------------------------------
__global__ void __launch_bounds__(256) combine_kernel()
{
    const int bh  = blockIdx.x;
    const int tid = threadIdx.x;
    __shared__ float m1s[4096];
    __shared__ float m2s[4096];
    __shared__ float m3s[4096];

    #pragma unroll
    for (int i = 0; i < 4; i++) {
        const int o4 = tid + i * 256;     // float4 index 0..1023
        float4 s1 = make_float4(0, 0, 0, 0);
        float4 s2 = make_float4(0, 0, 0, 0);
        float4 s3 = make_float4(0, 0, 0, 0);
        #pragma unroll
        for (int ch = 0; ch < MCH; ch++) {
            const float* ob = g_mpart + (size_t)(ch * BH + bh) * 3 * 4096;
            float4 v1 = ((const float4*)ob)[o4];
            float4 v2 = ((const float4*)(ob + 4096))[o4];
            float4 v3 = ((const float4*)(ob + 8192))[o4];
            s1.x += v1.x; s1.y += v1.y; s1.z += v1.z; s1.w += v1.w;
            s2.x += v2.x; s2.y += v2.y; s2.z += v2.z; s2.w += v2.w;
            s3.x += v3.x; s3.y += v3.y; s3.z += v3.z; s3.w += v3.w;
        }
        ((float4*)m1s)[o4] = s1;
        ((float4*)m2s)[o4] = s2;
        ((float4*)m3s)[o4] = s3;
    }
    __syncthreads();

    const int tr = tid >> 4, tc = tid & 15;
    float p[4][4];
    #pragma unroll
    for (int i = 0; i < 4; i++)
        #pragma unroll
        for (int j = 0; j < 4; j++) p[i][j] = 0.f;

    for (int e = 0; e < 64; e++) {
        float a[4], bb[4];
        #pragma unroll
        for (int i = 0; i < 4; i++) a[i] = m3s[(tr * 4 + i) * 64 + e];
        #pragma unroll
        for (int j = 0; j < 4; j++) bb[j] = m1s[e * 64 + tc * 4 + j];
        #pragma unroll
        for (int i = 0; i < 4; i++)
            #pragma unroll
            for (int j = 0; j < 4; j++) p[i][j] += a[i] * bb[j];
    }

    const float c1 = STEP_F * SCALE_F;
    const float c2 = STEP_F * SCALE_F * SCALE_F;
    #pragma unroll
    for (int i = 0; i < 4; i++)
        #pragma unroll
        for (int j = 0; j < 4; j++) {
            const int idx = (tr * 4 + i) * 64 + (tc * 4 + j);
            g_mc[(size_t)bh * 4096 + idx] = c1 * m2s[idx] - c2 * p[i][j];
        }
}

// ---------------------------------------------------------------------------
// outhead via tf32 mma: relu(V + K@Mc - STEP*LAMBD), tf32-rounded, to [B,N,C]
// grid (16 token-tiles of 128, BH), 128 threads (4 warps, warp tile 32x64).
// Dynamic smem: Ks[128][68] + McT[64][68]  (pitch 68 -> conflict-free frags)
// ---------------------------------------------------------------------------
#define OH_KPITCH   68
#define OH_KS_FL    (128 * OH_KPITCH)
#define OH_MC_FL    (64 * OH_KPITCH)
#define OH_SMEM_BYTES ((OH_KS_FL + OH_MC_FL) * 4)   // 52224

__global__ void __launch_bounds__(128) outhead_mma_kernel()
{
    extern __shared__ float osm[];
    float* Ks  = osm;                    // [128][OH_KPITCH]  (tok, d)
    float* McT = osm + OH_KS_FL;         // [64][OH_KPITCH]   (d2, d1)

    const int bh   = blockIdx.y;
    const int tile = blockIdx.x;
    const int b = bh / HEADS_H, h = bh % HEADS_H;
    const int tid  = threadIdx.x;
    const int wid  = tid >> 5;
    const int lane = tid & 31;
    const int g    = lane >> 2;
    const int t    = lane & 3;
    const int n0   = tile * 128;

    // Load Mc transposed (tf32-rounded): McT[d2][d1] = Mc[d1][d2]
    {
        const int d1  = tid >> 1;            // 0..63
        const int d2g = (tid & 1) * 32;      // 0 or 32
        const float* src = g_mc + (size_t)bh * 4096 + d1 * 64 + d2g;
        #pragma unroll
        for (int j = 0; j < 8; j++) {
            float4 v = *(const float4*)(src + j * 4);
            McT[(d2g + j * 4 + 0) * OH_KPITCH + d1] = __uint_as_float(f2tf32(v.x));
            McT[(d2g + j * 4 + 1) * OH_KPITCH + d1] = __uint_as_float(f2tf32(v.y));
            McT[(d2g + j * 4 + 2) * OH_KPITCH + d1] = __uint_as_float(f2tf32(v.z));
            McT[(d2g + j * 4 + 3) * OH_KPITCH + d1] = __uint_as_float(f2tf32(v.w));
        }
    }
    // Load K tile rows (normalized k), tf32-rounded
    {
        const float* src = g_qkv + (size_t)(b * NSEQ + n0 + tid) * C3 + 768 + h * 64;
        #pragma unroll
        for (int j = 0; j < 16; j++) {
            float4 v = *(const float4*)(src + j * 4);
            Ks[tid * OH_KPITCH + j * 4 + 0] = __uint_as_float(f2tf32(v.x));
            Ks[tid * OH_KPITCH + j * 4 + 1] = __uint_as_float(f2tf32(v.y));
            Ks[tid * OH_KPITCH + j * 4 + 2] = __uint_as_float(f2tf32(v.z));
            Ks[tid * OH_KPITCH + j * 4 + 3] = __uint_as_float(f2tf32(v.w));
        }
    }
    __syncthreads();

    const int mrow0 = wid * 32;
    float acc[2][8][4];
    #pragma unroll
    for (int mi = 0; mi < 2; mi++)
        #pragma unroll
        for (int ni = 0; ni < 8; ni++)
            #pragma unroll
            for (int c = 0; c < 4; c++) acc[mi][ni][c] = 0.0f;

    #pragma unroll
    for (int kk = 0; kk < 64; kk += 8) {
        uint32_t af[2][4], bf[8][2];
        #pragma unroll
        for (int mi = 0; mi < 2; mi++) {
            const int mrow = mrow0 + mi * 16;
            af[mi][0] = __float_as_uint(Ks[(mrow + g)     * OH_KPITCH + kk + t]);
            af[mi][1] = __float_as_uint(Ks[(mrow + g + 8) * OH_KPITCH + kk + t]);
            af[mi][2] = __float_as_uint(Ks[(mrow + g)     * OH_KPITCH + kk + t + 4]);
            af[mi][3] = __float_as_uint(Ks[(mrow + g + 8) * OH_KPITCH + kk + t + 4]);
        }
        #pragma unroll
        for (int ni = 0; ni < 8; ni++) {
            bf[ni][0] = __float_as_uint(McT[(ni * 8 + g) * OH_KPITCH + kk + t]);
            bf[ni][1] = __float_as_uint(McT[(ni * 8 + g) * OH_KPITCH + kk + t + 4]);
        }
        #pragma unroll
        for (int mi = 0; mi < 2; mi++)
            #pragma unroll
            for (int ni = 0; ni < 8; ni++)
                mma_tf32_16x8x8(acc[mi][ni][0], acc[mi][ni][1],
                                acc[mi][ni][2], acc[mi][ni][3],
                                af[mi][0], af[mi][1], af[mi][2], af[mi][3],
                                bf[ni][0], bf[ni][1]);
    }

    const float cadd = -STEP_F * LAMBD_F;
    #pragma unroll
    for (int mi = 0; mi < 2; mi++) {
        #pragma unroll
        for (int ni = 0; ni < 8; ni++) {
            const int d = ni * 8 + 2 * t;
            #pragma unroll
            for (int half = 0; half < 2; half++) {
                const int tok = b * NSEQ + n0 + mrow0 + mi * 16 + g + half * 8;
                const float2 v = *(const float2*)(
                    g_qkv + (size_t)tok * C3 + 1536 + h * 64 + d);
                const float r0 = fmaxf(v.x + acc[mi][ni][half * 2 + 0] + cadd, 0.0f);
                const float r1 = fmaxf(v.y + acc[mi][ni][half * 2 + 1] + cadd, 0.0f);
                *(float2*)(g_ao + (size_t)tok * CDIM + h * 64 + d) =
                    make_float2(__uint_as_float(f2tf32(r0)),
                                __uint_as_float(f2tf32(r1)));
            }
        }
    }
}

// ---------------------------------------------------------------------------
extern "C" void kernel_launch(void* const* d_in, const int* in_sizes, int n_in,
                              void* d_out, int out_size)
{
    const float* x     = (const float*)d_in[0];
    const float* Wqkv  = (const float*)d_in[1];
    const float* Wproj = (const float*)d_in[2];
    const float* bproj = (const float*)d_in[3];
    float* out = (float*)d_out;

    float* qkv;  cudaGetSymbolAddress((void**)&qkv,  g_qkv);
    float* ao;   cudaGetSymbolAddress((void**)&ao,   g_ao);
    float* xr;   cudaGetSymbolAddress((void**)&xr,   g_xr);
    float* wqr;  cudaGetSymbolAddress((void**)&wqr,  g_wqkvr);
    float* wpr;  cudaGetSymbolAddress((void**)&wpr,  g_wprojr);

    cudaFuncSetAttribute(gemm_tf32_pipe,
                         cudaFuncAttributeMaxDynamicSharedMemorySize,
                         GSMEM_BYTES);
    cudaFuncSetAttribute(outhead_mma_kernel,
                         cudaFuncAttributeMaxDynamicSharedMemorySize,
                         OH_SMEM_BYTES);

    // 0. Pre-round operands to tf32 grid
    round_tf32_kernel<<<(TOKENS * CDIM / 4 + 255) / 256, 256>>>(x, xr, TOKENS * CDIM / 4);
    round_tf32_kernel<<<(C3 * CDIM / 4 + 255) / 256, 256>>>(Wqkv, wqr, C3 * CDIM / 4);
    round_tf32_kernel<<<(CDIM * CDIM / 4 + 255) / 256, 256>>>(Wproj, wpr, CDIM * CDIM / 4);

    // 1. qkv = x @ Wqkv^T
    gemm_tf32_pipe<<<dim3(C3 / 128, TOKENS / 128), 128, GSMEM_BYTES>>>(
        xr, wqr, nullptr, qkv, TOKENS, C3, CDIM);
    // 2. L2-normalize q,k per head in place
    norm_qk_kernel<<<(TOKENS * 24) / 8, 256>>>();
    // 3. Per-head moments via mma (split over MCH token chunks)
    moments_mma_kernel<<<dim3(BH, MCH), 192>>>();
    // 4. Mc = STEP*(SCALE*M2 - SCALE^2 * M3@M1)
    combine_kernel<<<BH, 256>>>();
    // 5. relu(V + K@Mc - STEP*LAMBD) via mma, tf32-rounded
    outhead_mma_kernel<<<dim3(NSEQ / 128, BH), 128, OH_SMEM_BYTES>>>();
    // 6. out = ao @ Wproj^T + bproj
    gemm_tf32_pipe<<<dim3(CDIM / 128, TOKENS / 128), 128, GSMEM_BYTES>>>(
        ao, wpr, bproj, out, TOKENS, CDIM, CDIM);
}

// round 8
// speedup vs baseline: 2.7412x; 1.0919x over previous
#include <cuda_runtime.h>
#include <cuda_bf16.h>
#include <cstdint>
#include <math.h>

// Problem constants
#define BATCH   2
#define NSEQ    2048
#define CDIM    768
#define HEADS_H 12
#define DHEAD   64
#define TOKENS  (BATCH * NSEQ)          // 4096
#define C3      (3 * CDIM)              // 2304
#define BH      (BATCH * HEADS_H)       // 24
#define MCH     8                       // moments token-split chunks

#define SCALE_F 0.125f
#define STEP_F  0.1f
#define LAMBD_F 0.5f
#define EPS_F   1e-12f

// Scratch (static device globals — no allocation)
__device__ float g_qkv[TOKENS * C3];
__device__ float g_mpart[MCH * BH * 3 * DHEAD * DHEAD];
__device__ float g_mc[BH * DHEAD * DHEAD];
__device__ float g_ao[TOKENS * CDIM];       // K-permuted layout for GEMM2
__device__ float g_xr[TOKENS * CDIM];       // K-permuted, tf32-rounded
__device__ float g_wqkvr[C3 * CDIM];        // K-permuted, tf32-rounded
__device__ float g_wprojr[CDIM * CDIM];     // K-permuted, tf32-rounded

__device__ __forceinline__ uint32_t f2tf32(float f) {
    uint32_t u;
    asm("cvt.rna.tf32.f32 %0, %1;" : "=r"(u) : "f"(f));
    return u;
}
__device__ __forceinline__ float rtf(float f) {
    return __uint_as_float(f2tf32(f));
}
__device__ __forceinline__ uint32_t smem_u32(const void* p) {
    uint32_t a;
    asm("{ .reg .u64 t; cvta.to.shared.u64 t, %1; cvt.u32.u64 %0, t; }"
        : "=r"(a) : "l"(p));
    return a;
}
// K-permutation within an 8-column group: col c -> (c&3)*2 + (c>>2)
__device__ __forceinline__ int perm8(int d) {
    return (d & ~7) | (((d & 3) << 1) | ((d >> 2) & 1));
}

__device__ __forceinline__ void mma_tf32_16x8x8(
    float& c0, float& c1, float& c2, float& c3,
    uint32_t a0, uint32_t a1, uint32_t a2, uint32_t a3,
    uint32_t b0, uint32_t b1)
{
    asm volatile(
        "mma.sync.aligned.m16n8k8.row.col.f32.tf32.tf32.f32 "
        "{%0,%1,%2,%3}, {%4,%5,%6,%7}, {%8,%9}, {%0,%1,%2,%3};"
        : "+f"(c0), "+f"(c1), "+f"(c2), "+f"(c3)
        : "r"(a0), "r"(a1), "r"(a2), "r"(a3), "r"(b0), "r"(b1));
}

// ---------------------------------------------------------------------------
// Fused pre-round + K-permute for x, Wqkv, Wproj.
// Each thread handles one 8-float group: out[2i] interleaves (even4, odd4).
//   positions: p(c) = (c&3)*2 + (c>>2)  within each 8-group
// ---------------------------------------------------------------------------
#define RG1 (TOKENS * CDIM / 8)              // 393216
#define RG2 (RG1 + C3 * CDIM / 8)            // 614400
#define RG3 (RG2 + CDIM * CDIM / 8)          // 688128

__global__ void __launch_bounds__(256) round_perm_kernel(
    const float* __restrict__ x, const float* __restrict__ wq,
    const float* __restrict__ wp)
{
    const int gidx = blockIdx.x * 256 + threadIdx.x;
    const float* src; float* dst; int off;
    if (gidx < RG1)      { src = x;  dst = g_xr;     off = gidx; }
    else if (gidx < RG2) { src = wq; dst = g_wqkvr;  off = gidx - RG1; }
    else if (gidx < RG3) { src = wp; dst = g_wprojr; off = gidx - RG2; }
    else return;

    const float4 a = ((const float4*)src)[off * 2];
    const float4 b = ((const float4*)src)[off * 2 + 1];
    float4 o0, o1;
    o0.x = rtf(a.x); o0.y = rtf(b.x); o0.z = rtf(a.y); o0.w = rtf(b.y);
    o1.x = rtf(a.z); o1.y = rtf(b.z); o1.z = rtf(a.w); o1.w = rtf(b.w);
    ((float4*)dst)[off * 2]     = o0;
    ((float4*)dst)[off * 2 + 1] = o1;
}

// ---------------------------------------------------------------------------
// tf32 mma.sync NT GEMM, cp.async 4-stage pipeline, K-PERMUTED operands.
// CTA 128x128, 4 warps, warp tile 64x64, K-chunk 16, pitch-24 smem.
// Fragment loads are LDS.64 (cols t,t+4 adjacent after permutation).
// ---------------------------------------------------------------------------
#define PITCH   24
#define STAGES  4
#define STG_U32 (128 * PITCH)
#define GSMEM_BYTES (STAGES * STG_U32 * 4 * 2)      // 98304

__global__ void __launch_bounds__(128, 2) gemm_tf32_pipe(
    const float* __restrict__ A, const float* __restrict__ Bw,
    const float* __restrict__ bias, float* __restrict__ C,
    int M, int N, int K)
{
    extern __shared__ uint32_t sm[];
    uint32_t* As = sm;
    uint32_t* Bs = sm + STAGES * STG_U32;

    const int tid  = threadIdx.x;
    const int wid  = tid >> 5;
    const int lane = tid & 31;
    const int g    = lane >> 2;
    const int t    = lane & 3;
    const int row0 = blockIdx.y * 128;
    const int col0 = blockIdx.x * 128;
    const int wm0  = (wid >> 1) * 64;
    const int wn0  = (wid & 1) * 64;

    float acc[4][8][4];
    #pragma unroll
    for (int mi = 0; mi < 4; mi++)
        #pragma unroll
        for (int ni = 0; ni < 8; ni++)
            #pragma unroll
            for (int c = 0; c < 4; c++) acc[mi][ni][c] = 0.0f;

    // Loader: 512 float4 per matrix tile; 128 threads -> 4 each (rows +32i)
    const int lrow = tid >> 2;            // 0..31
    const int lseg = (tid & 3) << 2;      // 0,4,8,12

    const float* aptr = A  + (size_t)(row0 + lrow) * K + lseg;
    const float* bptr = Bw + (size_t)(col0 + lrow) * K + lseg;
    const uint32_t a_sb = smem_u32(As) + (lrow * PITCH + lseg) * 4;
    const uint32_t b_sb = smem_u32(Bs) + (lrow * PITCH + lseg) * 4;

    const int nc = K >> 4;

    #pragma unroll
    for (int s = 0; s < STAGES - 1; s++) {
        const int k0 = s << 4;
        #pragma unroll
        for (int i = 0; i < 4; i++) {
            const uint32_t so = s * STG_U32 * 4 + i * 32 * PITCH * 4;
            asm volatile("cp.async.cg.shared.global [%0], [%1], 16;"
                :: "r"(a_sb + so), "l"(aptr + (size_t)i * 32 * K + k0) : "memory");
            asm volatile("cp.async.cg.shared.global [%0], [%1], 16;"
                :: "r"(b_sb + so), "l"(bptr + (size_t)i * 32 * K + k0) : "memory");
        }
        asm volatile("cp.async.commit_group;" ::: "memory");
    }

    for (int c = 0; c < nc; c++) {
        asm volatile("cp.async.wait_group %0;" :: "n"(STAGES - 2) : "memory");
        __syncthreads();

        const int cn = c + STAGES - 1;
        if (cn < nc) {
            const int s  = cn & (STAGES - 1);
            const int k0 = cn << 4;
            #pragma unroll
            for (int i = 0; i < 4; i++) {
                const uint32_t so = s * STG_U32 * 4 + i * 32 * PITCH * 4;
                asm volatile("cp.async.cg.shared.global [%0], [%1], 16;"
                    :: "r"(a_sb + so), "l"(aptr + (size_t)i * 32 * K + k0) : "memory");
                asm volatile("cp.async.cg.shared.global [%0], [%1], 16;"
                    :: "r"(b_sb + so), "l"(bptr + (size_t)i * 32 * K + k0) : "memory");
            }
        }
        asm volatile("cp.async.commit_group;" ::: "memory");

        const uint32_t* as = As + (c & (STAGES - 1)) * STG_U32;
        const uint32_t* bs = Bs + (c & (STAGES - 1)) * STG_U32;
        #pragma unroll
        for (int ks = 0; ks < 2; ks++) {
            const int kk = ks * 8;
            uint32_t af[4][4], bf[8][2];
            #pragma unroll
            for (int mi = 0; mi < 4; mi++) {
                const int mrow = wm0 + mi * 16;
                // permuted layout: (col t, col t+4) adjacent -> LDS.64
                const uint2 av0 = *(const uint2*)&as[(mrow + g)     * PITCH + kk + 2 * t];
                const uint2 av1 = *(const uint2*)&as[(mrow + g + 8) * PITCH + kk + 2 * t];
                af[mi][0] = av0.x; af[mi][2] = av0.y;
                af[mi][1] = av1.x; af[mi][3] = av1.y;
            }
            #pragma unroll
            for (int ni = 0; ni < 8; ni++) {
                const int nrow = wn0 + ni * 8 + g;
                const uint2 bv = *(const uint2*)&bs[nrow * PITCH + kk + 2 * t];
                bf[ni][0] = bv.x; bf[ni][1] = bv.y;
            }
            #pragma unroll
            for (int mi = 0; mi < 4; mi++)
                #pragma unroll
                for (int ni = 0; ni < 8; ni++)
                    mma_tf32_16x8x8(acc[mi][ni][0], acc[mi][ni][1],
                                    acc[mi][ni][2], acc[mi][ni][3],
                                    af[mi][0], af[mi][1], af[mi][2], af[mi][3],
                                    bf[ni][0], bf[ni][1]);
        }
    }

    #pragma unroll
    for (int mi = 0; mi < 4; mi++) {
        #pragma unroll
        for (int ni = 0; ni < 8; ni++) {
            const int col = col0 + wn0 + ni * 8 + 2 * t;
            float b0 = 0.f, b1 = 0.f;
            if (bias) { b0 = bias[col]; b1 = bias[col + 1]; }
            const int r0 = row0 + wm0 + mi * 16 + g;
            *(float2*)(C + (size_t)r0 * N + col) =
                make_float2(acc[mi][ni][0] + b0, acc[mi][ni][1] + b1);
            *(float2*)(C + (size_t)(r0 + 8) * N + col) =
                make_float2(acc[mi][ni][2] + b0, acc[mi][ni][3] + b1);
        }
    }
}

// ---------------------------------------------------------------------------
// L2-normalize q and k heads in place
// ---------------------------------------------------------------------------
__global__ void __launch_bounds__(256) norm_qk_kernel()
{
    const int seg   = blockIdx.x * 8 + (threadIdx.x >> 5);
    const int lane  = threadIdx.x & 31;
    const int token = seg / 24;
    const int s     = seg % 24;

    float* p = g_qkv + (size_t)token * C3 + s * 64;
    float v0 = p[lane];
    float v1 = p[lane + 32];
    float ss = v0 * v0 + v1 * v1;
    #pragma unroll
    for (int o = 16; o; o >>= 1) ss += __shfl_xor_sync(0xffffffffu, ss, o);
    float inv = 1.0f / fmaxf(sqrtf(ss), EPS_F);
    p[lane]      = v0 * inv;
    p[lane + 32] = v1 * inv;
}

// ---------------------------------------------------------------------------
// Moments via tf32 mma: per (b,h,chunk of 256 tokens), partial
// M1 = K^T V, M2 = Q^T V, M3 = Q^T Q. grid (BH, MCH), 192 threads (6 warps).
// ---------------------------------------------------------------------------
__global__ void __launch_bounds__(192) moments_mma_kernel()
{
    __shared__ float QT[64][17];
    __shared__ float KT[64][17];
    __shared__ float VT[64][17];

    const int bh = blockIdx.x;
    const int ch = blockIdx.y;
    const int b = bh / HEADS_H, h = bh % HEADS_H;
    const int tid  = threadIdx.x;
    const int wid  = tid >> 5;           // 0..5
    const int lane = tid & 31;
    const int g    = lane >> 2;
    const int t    = lane & 3;
    const int o    = wid >> 1;           // 0=M1,1=M2,2=M3
    const int mhalf = (wid & 1) * 32;

    const int mat = tid >> 6;
    const int idx = tid & 63;
    const int ltok = idx >> 2;           // 0..15
    const int ldg  = (idx & 3) << 4;     // 0,16,32,48

    float (*Tdst)[17] = (mat == 0) ? QT : (mat == 1) ? KT : VT;
    const size_t base = (size_t)(b * NSEQ + ch * (NSEQ / MCH)) * C3 + mat * 768 + h * 64;

    float acc[2][8][4];
    #pragma unroll
    for (int mi = 0; mi < 2; mi++)
        #pragma unroll
        for (int ni = 0; ni < 8; ni++)
            #pragma unroll
            for (int c = 0; c < 4; c++) acc[mi][ni][c] = 0.0f;

    for (int it = 0; it < (NSEQ / MCH) / 16; it++) {
        const float* src = g_qkv + base + (size_t)(it * 16 + ltok) * C3 + ldg;
        float4 v[4];
        #pragma unroll
        for (int j = 0; j < 4; j++) v[j] = *(const float4*)(src + j * 4);
        __syncthreads();
        #pragma unroll
        for (int j = 0; j < 4; j++) {
            Tdst[ldg + j * 4 + 0][ltok] = rtf(v[j].x);
            Tdst[ldg + j * 4 + 1][ltok] = rtf(v[j].y);
            Tdst[ldg + j * 4 + 2][ltok] = rtf(v[j].z);
            Tdst[ldg + j * 4 + 3][ltok] = rtf(v[j].w);
        }
        __syncthreads();

        const float (*Am)[17] = (o == 0) ? KT : QT;
        const float (*Bm)[17] = (o == 2) ? QT : VT;
        #pragma unroll
        for (int kk = 0; kk < 16; kk += 8) {
            uint32_t af[2][4], bf[8][2];
            #pragma unroll
            for (int mi = 0; mi < 2; mi++) {
                const int mrow = mhalf + mi * 16;
                af[mi][0] = __float_as_uint(Am[mrow + g][kk + t]);
                af[mi][1] = __float_as_uint(Am[mrow + g + 8][kk + t]);
                af[mi][2] = __float_as_uint(Am[mrow + g][kk + t + 4]);
                af[mi][3] = __float_as_uint(Am[mrow + g + 8][kk + t + 4]);
            }
            #pragma unroll
            for (int ni = 0; ni < 8; ni++) {
                bf[ni][0] = __float_as_uint(Bm[ni * 8 + g][kk + t]);
                bf[ni][1] = __float_as_uint(Bm[ni * 8 + g][kk + t + 4]);
            }
            #pragma unroll
            for (int mi = 0; mi < 2; mi++)
                #pragma unroll
                for (int ni = 0; ni < 8; ni++)
                    mma_tf32_16x8x8(acc[mi][ni][0], acc[mi][ni][1],
                                    acc[mi][ni][2], acc[mi][ni][3],
                                    af[mi][0], af[mi][1], af[mi][2], af[mi][3],
                                    bf[ni][0], bf[ni][1]);
        }
    }

    float* outp = g_mpart + ((size_t)(ch * BH + bh) * 3 + o) * 4096;
    #pragma unroll
    for (int mi = 0; mi < 2; mi++) {
        #pragma unroll
        for (int ni = 0; ni < 8; ni++) {
            const int row = mhalf + mi * 16 + g;
            const int col = ni * 8 + 2 * t;
            *(float2*)(outp + row * 64 + col) =
                make_float2(acc[mi][ni][0], acc[mi][ni][1]);
            *(float2*)(outp + (row + 8) * 64 + col) =
                make_float2(acc[mi][ni][2], acc[mi][ni][3]);
        }
    }
}

// ---------------------------------------------------------------------------
// Combine: Mc = STEP*(SCALE*M2 - SCALE^2*M3@M1), summing MCH partials
// ---------------------------------------------------------------------------
__global__ void __launch_bounds__(256) combine_kernel()
{
    const int bh  = blockIdx.x;
    const int tid = threadIdx.x;
    __shared__ float m1s[4096];
    __shared__ float m2s[4096];
    __shared__ float m3s[4096];

    #pragma unroll
    for (int i = 0; i < 4; i++) {
        const int o4 = tid + i * 256;
        float4 s1 = make_float4(0, 0, 0, 0);
        float4 s2 = make_float4(0, 0, 0, 0);
        float4 s3 = make_float4(0, 0, 0, 0);
        #pragma unroll
        for (int ch = 0; ch < MCH; ch++) {
            const float* ob = g_mpart + (size_t)(ch * BH + bh) * 3 * 4096;
            float4 v1 = ((const float4*)ob)[o4];
            float4 v2 = ((const float4*)(ob + 4096))[o4];
            float4 v3 = ((const float4*)(ob + 8192))[o4];
            s1.x += v1.x; s1.y += v1.y; s1.z += v1.z; s1.w += v1.w;
            s2.x += v2.x; s2.y += v2.y; s2.z += v2.z; s2.w += v2.w;
            s3.x += v3.x; s3.y += v3.y; s3.z += v3.z; s3.w += v3.w;
        }
        ((float4*)m1s)[o4] = s1;
        ((float4*)m2s)[o4] = s2;
        ((float4*)m3s)[o4] = s3;
    }
    __syncthreads();

    const int tr = tid >> 4, tc = tid & 15;
    float p[4][4];
    #pragma unroll
    for (int i = 0; i < 4; i++)
        #pragma unroll
        for (int j = 0; j < 4; j++) p[i][j] = 0.f;

    for (int e = 0; e < 64; e++) {
        float a[4], bb[4];
        #pragma unroll
        for (int i = 0; i < 4; i++) a[i] = m3s[(tr * 4 + i) * 64 + e];
        #pragma unroll
        for (int j = 0; j < 4; j++) bb[j] = m1s[e * 64 + tc * 4 + j];
        #pragma unroll
        for (int i = 0; i < 4; i++)
            #pragma unroll
            for (int j = 0; j < 4; j++) p[i][j] += a[i] * bb[j];
    }

    const float c1 = STEP_F * SCALE_F;
    const float c2 = STEP_F * SCALE_F * SCALE_F;
    #pragma unroll
    for (int i = 0; i < 4; i++)
        #pragma unroll
        for (int j = 0; j < 4; j++) {
            const int idx = (tr * 4 + i) * 64 + (tc * 4 + j);
            g_mc[(size_t)bh * 4096 + idx] = c1 * m2s[idx] - c2 * p[i][j];
        }
}

// ---------------------------------------------------------------------------
// outhead via tf32 mma: relu(V + K@Mc - STEP*LAMBD), tf32-rounded,
// written K-PERMUTED into g_ao [B,N,C] for GEMM2 consumption.
// grid (16 token-tiles of 128, BH), 128 threads (4 warps, warp tile 32x64).
// ---------------------------------------------------------------------------
#define OH_KPITCH   68
#define OH_KS_FL    (128 * OH_KPITCH)
#define OH_MC_FL    (64 * OH_KPITCH)
#define OH_SMEM_BYTES ((OH_KS_FL + OH_MC_FL) * 4)   // 52224

__global__ void __launch_bounds__(128) outhead_mma_kernel()
{
    extern __shared__ float osm[];
    float* Ks  = osm;                    // [128][OH_KPITCH]  (tok, d)
    float* McT = osm + OH_KS_FL;         // [64][OH_KPITCH]   (d2, d1)

    const int bh   = blockIdx.y;
    const int tile = blockIdx.x;
    const int b = bh / HEADS_H, h = bh % HEADS_H;
    const int tid  = threadIdx.x;
    const int wid  = tid >> 5;
    const int lane = tid & 31;
    const int g    = lane >> 2;
    const int t    = lane & 3;
    const int n0   = tile * 128;

    {
        const int d1  = tid >> 1;
        const int d2g = (tid & 1) * 32;
        const float* src = g_mc + (size_t)bh * 4096 + d1 * 64 + d2g;
        #pragma unroll
        for (int j = 0; j < 8; j++) {
            float4 v = *(const float4*)(src + j * 4);
            McT[(d2g + j * 4 + 0) * OH_KPITCH + d1] = rtf(v.x);
            McT[(d2g + j * 4 + 1) * OH_KPITCH + d1] = rtf(v.y);
            McT[(d2g + j * 4 + 2) * OH_KPITCH + d1] = rtf(v.z);
            McT[(d2g + j * 4 + 3) * OH_KPITCH + d1] = rtf(v.w);
        }
    }
    {
        const float* src = g_qkv + (size_t)(b * NSEQ + n0 + tid) * C3 + 768 + h * 64;
        #pragma unroll
        for (int j = 0; j < 16; j++) {
            float4 v = *(const float4*)(src + j * 4);
            Ks[tid * OH_KPITCH + j * 4 + 0] = rtf(v.x);
            Ks[tid * OH_KPITCH + j * 4 + 1] = rtf(v.y);
            Ks[tid * OH_KPITCH + j * 4 + 2] = rtf(v.z);
            Ks[tid * OH_KPITCH + j * 4 + 3] = rtf(v.w);
        }
    }
    __syncthreads();

    const int mrow0 = wid * 32;
    float acc[2][8][4];
    #pragma unroll
    for (int mi = 0; mi < 2; mi++)
        #pragma unroll
        for (int ni = 0; ni < 8; ni++)
            #pragma unroll
            for (int c = 0; c < 4; c++) acc[mi][ni][c] = 0.0f;

    #pragma unroll
    for (int kk = 0; kk < 64; kk += 8) {
        uint32_t af[2][4], bf[8][2];
        #pragma unroll
        for (int mi = 0; mi < 2; mi++) {
            const int mrow = mrow0 + mi * 16;
            af[mi][0] = __float_as_uint(Ks[(mrow + g)     * OH_KPITCH + kk + t]);
            af[mi][1] = __float_as_uint(Ks[(mrow + g + 8) * OH_KPITCH + kk + t]);
            af[mi][2] = __float_as_uint(Ks[(mrow + g)     * OH_KPITCH + kk + t + 4]);
            af[mi][3] = __float_as_uint(Ks[(mrow + g + 8) * OH_KPITCH + kk + t + 4]);
        }
        #pragma unroll
        for (int ni = 0; ni < 8; ni++) {
            bf[ni][0] = __float_as_uint(McT[(ni * 8 + g) * OH_KPITCH + kk + t]);
            bf[ni][1] = __float_as_uint(McT[(ni * 8 + g) * OH_KPITCH + kk + t + 4]);
        }
        #pragma unroll
        for (int mi = 0; mi < 2; mi++)
            #pragma unroll
            for (int ni = 0; ni < 8; ni++)
                mma_tf32_16x8x8(acc[mi][ni][0], acc[mi][ni][1],
                                acc[mi][ni][2], acc[mi][ni][3],
                                af[mi][0], af[mi][1], af[mi][2], af[mi][3],
                                bf[ni][0], bf[ni][1]);
    }

    const float cadd = -STEP_F * LAMBD_F;
    #pragma unroll
    for (int mi = 0; mi < 2; mi++) {
        #pragma unroll
        for (int ni = 0; ni < 8; ni++) {
            const int d0 = ni * 8 + 2 * t;
            const int p0 = perm8(d0);
            const int p1 = perm8(d0 + 1);
            #pragma unroll
            for (int half = 0; half < 2; half++) {
                const int tok = b * NSEQ + n0 + mrow0 + mi * 16 + g + half * 8;
                const float2 v = *(const float2*)(
                    g_qkv + (size_t)tok * C3 + 1536 + h * 64 + d0);
                const float r0 = fmaxf(v.x + acc[mi][ni][half * 2 + 0] + cadd, 0.0f);
                const float r1 = fmaxf(v.y + acc[mi][ni][half * 2 + 1] + cadd, 0.0f);
                float* dst = g_ao + (size_t)tok * CDIM + h * 64;
                dst[p0] = rtf(r0);
                dst[p1] = rtf(r1);
            }
        }
    }
}

// ---------------------------------------------------------------------------
extern "C" void kernel_launch(void* const* d_in, const int* in_sizes, int n_in,
                              void* d_out, int out_size)
{
    const float* x     = (const float*)d_in[0];
    const float* Wqkv  = (const float*)d_in[1];
    const float* Wproj = (const float*)d_in[2];
    const float* bproj = (const float*)d_in[3];
    float* out = (float*)d_out;

    float* qkv;  cudaGetSymbolAddress((void**)&qkv,  g_qkv);
    float* ao;   cudaGetSymbolAddress((void**)&ao,   g_ao);
    float* xr;   cudaGetSymbolAddress((void**)&xr,   g_xr);
    float* wqr;  cudaGetSymbolAddress((void**)&wqr,  g_wqkvr);
    float* wpr;  cudaGetSymbolAddress((void**)&wpr,  g_wprojr);

    cudaFuncSetAttribute(gemm_tf32_pipe,
                         cudaFuncAttributeMaxDynamicSharedMemorySize,
                         GSMEM_BYTES);
    cudaFuncSetAttribute(outhead_mma_kernel,
                         cudaFuncAttributeMaxDynamicSharedMemorySize,
                         OH_SMEM_BYTES);

    // 0. Pre-round + K-permute all GEMM operands (one fused kernel)
    round_perm_kernel<<<(RG3 + 255) / 256, 256>>>(x, Wqkv, Wproj);

    // 1. qkv = x @ Wqkv^T
    gemm_tf32_pipe<<<dim3(C3 / 128, TOKENS / 128), 128, GSMEM_BYTES>>>(
        xr, wqr, nullptr, qkv, TOKENS, C3, CDIM);
    // 2. L2-normalize q,k per head in place
    norm_qk_kernel<<<(TOKENS * 24) / 8, 256>>>();
    // 3. Per-head moments via mma (split over MCH token chunks)
    moments_mma_kernel<<<dim3(BH, MCH), 192>>>();
    // 4. Mc = STEP*(SCALE*M2 - SCALE^2 * M3@M1)
    combine_kernel<<<BH, 256>>>();
    // 5. relu(V + K@Mc - STEP*LAMBD) via mma, K-permuted tf32 output
    outhead_mma_kernel<<<dim3(NSEQ / 128, BH), 128, OH_SMEM_BYTES>>>();
    // 6. out = ao @ Wproj^T + bproj
    gemm_tf32_pipe<<<dim3(CDIM / 128, TOKENS / 128), 128, GSMEM_BYTES>>>(
        ao, wpr, bproj, out, TOKENS, CDIM, CDIM);
}

// round 9
// speedup vs baseline: 2.8545x; 1.0413x over previous
#include <cuda_runtime.h>
#include <cuda_bf16.h>
#include <cstdint>
#include <math.h>

// Problem constants
#define BATCH   2
#define NSEQ    2048
#define CDIM    768
#define HEADS_H 12
#define DHEAD   64
#define TOKENS  (BATCH * NSEQ)          // 4096
#define C3      (3 * CDIM)              // 2304
#define BH      (BATCH * HEADS_H)       // 24
#define MCH     16                      // moments token-split chunks

#define SCALE_F 0.125f
#define STEP_F  0.1f
#define LAMBD_F 0.5f
#define EPS_F   1e-12f

// Scratch (static device globals — no allocation)
__device__ float g_qkv[TOKENS * C3];    // RAW qkv (normalization fused downstream)
__device__ float g_mpart[MCH * BH * 3 * DHEAD * DHEAD];
__device__ float g_mc[BH * DHEAD * DHEAD];
__device__ float g_ao[TOKENS * CDIM];   // K-permuted layout for GEMM2
__device__ float g_xr[TOKENS * CDIM];   // K-permuted, tf32-rounded
__device__ float g_wqkvr[C3 * CDIM];
__device__ float g_wprojr[CDIM * CDIM];

__device__ __forceinline__ uint32_t f2tf32(float f) {
    uint32_t u;
    asm("cvt.rna.tf32.f32 %0, %1;" : "=r"(u) : "f"(f));
    return u;
}
__device__ __forceinline__ float rtf(float f) {
    return __uint_as_float(f2tf32(f));
}
__device__ __forceinline__ uint32_t smem_u32(const void* p) {
    uint32_t a;
    asm("{ .reg .u64 t; cvta.to.shared.u64 t, %1; cvt.u32.u64 %0, t; }"
        : "=r"(a) : "l"(p));
    return a;
}
// K-permutation within an 8-column group: col c -> (c&3)*2 + (c>>2)
__device__ __forceinline__ int perm8(int d) {
    return (d & ~7) | (((d & 3) << 1) | ((d >> 2) & 1));
}

__device__ __forceinline__ void mma_tf32_16x8x8(
    float& c0, float& c1, float& c2, float& c3,
    uint32_t a0, uint32_t a1, uint32_t a2, uint32_t a3,
    uint32_t b0, uint32_t b1)
{
    asm volatile(
        "mma.sync.aligned.m16n8k8.row.col.f32.tf32.tf32.f32 "
        "{%0,%1,%2,%3}, {%4,%5,%6,%7}, {%8,%9}, {%0,%1,%2,%3};"
        : "+f"(c0), "+f"(c1), "+f"(c2), "+f"(c3)
        : "r"(a0), "r"(a1), "r"(a2), "r"(a3), "r"(b0), "r"(b1));
}

// ---------------------------------------------------------------------------
// Fused pre-round + K-permute for x, Wqkv, Wproj.
// ---------------------------------------------------------------------------
#define RG1 (TOKENS * CDIM / 8)              // 393216
#define RG2 (RG1 + C3 * CDIM / 8)            // 614400
#define RG3 (RG2 + CDIM * CDIM / 8)          // 688128

__global__ void __launch_bounds__(256) round_perm_kernel(
    const float* __restrict__ x, const float* __restrict__ wq,
    const float* __restrict__ wp)
{
    const int gidx = blockIdx.x * 256 + threadIdx.x;
    const float* src; float* dst; int off;
    if (gidx < RG1)      { src = x;  dst = g_xr;     off = gidx; }
    else if (gidx < RG2) { src = wq; dst = g_wqkvr;  off = gidx - RG1; }
    else if (gidx < RG3) { src = wp; dst = g_wprojr; off = gidx - RG2; }
    else return;

    const float4 a = ((const float4*)src)[off * 2];
    const float4 b = ((const float4*)src)[off * 2 + 1];
    float4 o0, o1;
    o0.x = rtf(a.x); o0.y = rtf(b.x); o0.z = rtf(a.y); o0.w = rtf(b.y);
    o1.x = rtf(a.z); o1.y = rtf(b.z); o1.z = rtf(a.w); o1.w = rtf(b.w);
    ((float4*)dst)[off * 2]     = o0;
    ((float4*)dst)[off * 2 + 1] = o1;
}

// ---------------------------------------------------------------------------
// tf32 mma.sync NT GEMM, cp.async 4-stage pipeline, K-PERMUTED operands.
// CTA 128x128, 4 warps, warp tile 64x64, K-chunk 16, pitch-24 smem, LDS.64.
// ---------------------------------------------------------------------------
#define PITCH   24
#define STAGES  4
#define STG_U32 (128 * PITCH)
#define GSMEM_BYTES (STAGES * STG_U32 * 4 * 2)      // 98304

__global__ void __launch_bounds__(128, 2) gemm_tf32_pipe(
    const float* __restrict__ A, const float* __restrict__ Bw,
    const float* __restrict__ bias, float* __restrict__ C,
    int M, int N, int K)
{
    extern __shared__ uint32_t sm[];
    uint32_t* As = sm;
    uint32_t* Bs = sm + STAGES * STG_U32;

    const int tid  = threadIdx.x;
    const int wid  = tid >> 5;
    const int lane = tid & 31;
    const int g    = lane >> 2;
    const int t    = lane & 3;
    const int row0 = blockIdx.y * 128;
    const int col0 = blockIdx.x * 128;
    const int wm0  = (wid >> 1) * 64;
    const int wn0  = (wid & 1) * 64;

    float acc[4][8][4];
    #pragma unroll
    for (int mi = 0; mi < 4; mi++)
        #pragma unroll
        for (int ni = 0; ni < 8; ni++)
            #pragma unroll
            for (int c = 0; c < 4; c++) acc[mi][ni][c] = 0.0f;

    const int lrow = tid >> 2;            // 0..31
    const int lseg = (tid & 3) << 2;      // 0,4,8,12

    const float* aptr = A  + (size_t)(row0 + lrow) * K + lseg;
    const float* bptr = Bw + (size_t)(col0 + lrow) * K + lseg;
    const uint32_t a_sb = smem_u32(As) + (lrow * PITCH + lseg) * 4;
    const uint32_t b_sb = smem_u32(Bs) + (lrow * PITCH + lseg) * 4;

    const int nc = K >> 4;

    #pragma unroll
    for (int s = 0; s < STAGES - 1; s++) {
        const int k0 = s << 4;
        #pragma unroll
        for (int i = 0; i < 4; i++) {
            const uint32_t so = s * STG_U32 * 4 + i * 32 * PITCH * 4;
            asm volatile("cp.async.cg.shared.global [%0], [%1], 16;"
                :: "r"(a_sb + so), "l"(aptr + (size_t)i * 32 * K + k0) : "memory");
            asm volatile("cp.async.cg.shared.global [%0], [%1], 16;"
                :: "r"(b_sb + so), "l"(bptr + (size_t)i * 32 * K + k0) : "memory");
        }
        asm volatile("cp.async.commit_group;" ::: "memory");
    }

    for (int c = 0; c < nc; c++) {
        asm volatile("cp.async.wait_group %0;" :: "n"(STAGES - 2) : "memory");
        __syncthreads();

        const int cn = c + STAGES - 1;
        if (cn < nc) {
            const int s  = cn & (STAGES - 1);
            const int k0 = cn << 4;
            #pragma unroll
            for (int i = 0; i < 4; i++) {
                const uint32_t so = s * STG_U32 * 4 + i * 32 * PITCH * 4;
                asm volatile("cp.async.cg.shared.global [%0], [%1], 16;"
                    :: "r"(a_sb + so), "l"(aptr + (size_t)i * 32 * K + k0) : "memory");
                asm volatile("cp.async.cg.shared.global [%0], [%1], 16;"
                    :: "r"(b_sb + so), "l"(bptr + (size_t)i * 32 * K + k0) : "memory");
            }
        }
        asm volatile("cp.async.commit_group;" ::: "memory");

        const uint32_t* as = As + (c & (STAGES - 1)) * STG_U32;
        const uint32_t* bs = Bs + (c & (STAGES - 1)) * STG_U32;
        #pragma unroll
        for (int ks = 0; ks < 2; ks++) {
            const int kk = ks * 8;
            uint32_t af[4][4], bf[8][2];
            #pragma unroll
            for (int mi = 0; mi < 4; mi++) {
                const int mrow = wm0 + mi * 16;
                const uint2 av0 = *(const uint2*)&as[(mrow + g)     * PITCH + kk + 2 * t];
                const uint2 av1 = *(const uint2*)&as[(mrow + g + 8) * PITCH + kk + 2 * t];
                af[mi][0] = av0.x; af[mi][2] = av0.y;
                af[mi][1] = av1.x; af[mi][3] = av1.y;
            }
            #pragma unroll
            for (int ni = 0; ni < 8; ni++) {
                const int nrow = wn0 + ni * 8 + g;
                const uint2 bv = *(const uint2*)&bs[nrow * PITCH + kk + 2 * t];
                bf[ni][0] = bv.x; bf[ni][1] = bv.y;
            }
            #pragma unroll
            for (int mi = 0; mi < 4; mi++)
                #pragma unroll
                for (int ni = 0; ni < 8; ni++)
                    mma_tf32_16x8x8(acc[mi][ni][0], acc[mi][ni][1],
                                    acc[mi][ni][2], acc[mi][ni][3],
                                    af[mi][0], af[mi][1], af[mi][2], af[mi][3],
                                    bf[ni][0], bf[ni][1]);
        }
    }

    #pragma unroll
    for (int mi = 0; mi < 4; mi++) {
        #pragma unroll
        for (int ni = 0; ni < 8; ni++) {
            const int col = col0 + wn0 + ni * 8 + 2 * t;
            float b0 = 0.f, b1 = 0.f;
            if (bias) { b0 = bias[col]; b1 = bias[col + 1]; }
            const int r0 = row0 + wm0 + mi * 16 + g;
            *(float2*)(C + (size_t)r0 * N + col) =
                make_float2(acc[mi][ni][0] + b0, acc[mi][ni][1] + b1);
            *(float2*)(C + (size_t)(r0 + 8) * N + col) =
                make_float2(acc[mi][ni][2] + b0, acc[mi][ni][3] + b1);
        }
    }
}

// ---------------------------------------------------------------------------
// Moments via tf32 mma with FUSED L2-normalization of q,k.
// Per (b,h,chunk of 128 tokens): partial M1=K^T V, M2=Q^T V, M3=Q^T Q.
// grid (BH, MCH), 192 threads (6 warps). Double-buffered smem, 1 sync/iter.
// Each token's 64 floats live in 4 adjacent lanes -> shfl norm reduce.
// ---------------------------------------------------------------------------
#define MTOK (NSEQ / MCH)                // 128 tokens per chunk
#define MNIT (MTOK / 16)                 // 8 iters of 16 tokens

__global__ void __launch_bounds__(192) moments_mma_kernel()
{
    __shared__ float QT[2][64][17];
    __shared__ float KT[2][64][17];
    __shared__ float VT[2][64][17];

    const int bh = blockIdx.x;
    const int ch = blockIdx.y;
    const int b = bh / HEADS_H, h = bh % HEADS_H;
    const int tid  = threadIdx.x;
    const int wid  = tid >> 5;           // 0..5
    const int lane = tid & 31;
    const int g    = lane >> 2;
    const int t    = lane & 3;
    const int o    = wid >> 1;           // 0=M1,1=M2,2=M3
    const int mhalf = (wid & 1) * 32;

    const int mat  = tid >> 6;           // 0=Q,1=K,2=V (uniform per warp pair)
    const int idx  = tid & 63;
    const int ltok = idx >> 2;           // 0..15
    const int ldg  = (idx & 3) << 4;     // 0,16,32,48

    const size_t base = (size_t)(b * NSEQ + ch * MTOK) * C3 + mat * 768 + h * 64;

    float acc[2][8][4];
    #pragma unroll
    for (int mi = 0; mi < 2; mi++)
        #pragma unroll
        for (int ni = 0; ni < 8; ni++)
            #pragma unroll
            for (int c = 0; c < 4; c++) acc[mi][ni][c] = 0.0f;

    float4 v[4];
    {
        const float* src = g_qkv + base + (size_t)ltok * C3 + ldg;
        #pragma unroll
        for (int j = 0; j < 4; j++) v[j] = *(const float4*)(src + j * 4);
    }

    for (int it = 0; it < MNIT; it++) {
        // fused L2 norm for q,k: 4 lanes hold this token's 64 values
        float inv = 1.0f;
        if (mat < 2) {
            float ss = 0.f;
            #pragma unroll
            for (int j = 0; j < 4; j++)
                ss += v[j].x * v[j].x + v[j].y * v[j].y
                    + v[j].z * v[j].z + v[j].w * v[j].w;
            ss += __shfl_xor_sync(0xffffffffu, ss, 1);
            ss += __shfl_xor_sync(0xffffffffu, ss, 2);
            inv = 1.0f / fmaxf(sqrtf(ss), EPS_F);
        }
        {
            float (*Td)[17] = (mat == 0) ? QT[it & 1]
                            : (mat == 1) ? KT[it & 1] : VT[it & 1];
            #pragma unroll
            for (int j = 0; j < 4; j++) {
                Td[ldg + j * 4 + 0][ltok] = rtf(v[j].x * inv);
                Td[ldg + j * 4 + 1][ltok] = rtf(v[j].y * inv);
                Td[ldg + j * 4 + 2][ltok] = rtf(v[j].z * inv);
                Td[ldg + j * 4 + 3][ltok] = rtf(v[j].w * inv);
            }
        }
        // prefetch next 16 tokens (overlaps sync + mma)
        float4 vn[4];
        if (it + 1 < MNIT) {
            const float* src = g_qkv + base + (size_t)((it + 1) * 16 + ltok) * C3 + ldg;
            #pragma unroll
            for (int j = 0; j < 4; j++) vn[j] = *(const float4*)(src + j * 4);
        }
        __syncthreads();

        const float (*Am)[17] = (o == 0) ? KT[it & 1] : QT[it & 1];
        const float (*Bm)[17] = (o == 2) ? QT[it & 1] : VT[it & 1];
        #pragma unroll
        for (int kk = 0; kk < 16; kk += 8) {
            uint32_t af[2][4], bf[8][2];
            #pragma unroll
            for (int mi = 0; mi < 2; mi++) {
                const int mrow = mhalf + mi * 16;
                af[mi][0] = __float_as_uint(Am[mrow + g][kk + t]);
                af[mi][1] = __float_as_uint(Am[mrow + g + 8][kk + t]);
                af[mi][2] = __float_as_uint(Am[mrow + g][kk + t + 4]);
                af[mi][3] = __float_as_uint(Am[mrow + g + 8][kk + t + 4]);
            }
            #pragma unroll
            for (int ni = 0; ni < 8; ni++) {
                bf[ni][0] = __float_as_uint(Bm[ni * 8 + g][kk + t]);
                bf[ni][1] = __float_as_uint(Bm[ni * 8 + g][kk + t + 4]);
            }
            #pragma unroll
            for (int mi = 0; mi < 2; mi++)
                #pragma unroll
                for (int ni = 0; ni < 8; ni++)
                    mma_tf32_16x8x8(acc[mi][ni][0], acc[mi][ni][1],
                                    acc[mi][ni][2], acc[mi][ni][3],
                                    af[mi][0], af[mi][1], af[mi][2], af[mi][3],
                                    bf[ni][0], bf[ni][1]);
        }
        #pragma unroll
        for (int j = 0; j < 4; j++) v[j] = vn[j];
    }

    float* outp = g_mpart + ((size_t)(ch * BH + bh) * 3 + o) * 4096;
    #pragma unroll
    for (int mi = 0; mi < 2; mi++) {
        #pragma unroll
        for (int ni = 0; ni < 8; ni++) {
            const int row = mhalf + mi * 16 + g;
            const int col = ni * 8 + 2 * t;
            *(float2*)(outp + row * 64 + col) =
                make_float2(acc[mi][ni][0], acc[mi][ni][1]);
            *(float2*)(outp + (row + 8) * 64 + col) =
                make_float2(acc[mi][ni][2], acc[mi][ni][3]);
        }
    }
}

// ---------------------------------------------------------------------------
// Combine: Mc = STEP*(SCALE*M2 - SCALE^2*M3@M1), summing MCH partials
// ---------------------------------------------------------------------------
__global__ void __launch_bounds__(256) combine_kernel()
{
    const int bh  = blockIdx.x;
    const int tid = threadIdx.x;
    __shared__ float m1s[4096];
    __shared__ float m2s[4096];
    __shared__ float m3s[4096];

    #pragma unroll
    for (int i = 0; i < 4; i++) {
        const int o4 = tid + i * 256;
        float4 s1 = make_float4(0, 0, 0, 0);
        float4 s2 = make_float4(0, 0, 0, 0);
        float4 s3 = make_float4(0, 0, 0, 0);
        #pragma unroll
        for (int ch = 0; ch < MCH; ch++) {
            const float* ob = g_mpart + (size_t)(ch * BH + bh) * 3 * 4096;
            float4 v1 = ((const float4*)ob)[o4];
            float4 v2 = ((const float4*)(ob + 4096))[o4];
            float4 v3 = ((const float4*)(ob + 8192))[o4];
            s1.x += v1.x; s1.y += v1.y; s1.z += v1.z; s1.w += v1.w;
            s2.x += v2.x; s2.y += v2.y; s2.z += v2.z; s2.w += v2.w;
            s3.x += v3.x; s3.y += v3.y; s3.z += v3.z; s3.w += v3.w;
        }
        ((float4*)m1s)[o4] = s1;
        ((float4*)m2s)[o4] = s2;
        ((float4*)m3s)[o4] = s3;
    }
    __syncthreads();

    const int tr = tid >> 4, tc = tid & 15;
    float p[4][4];
    #pragma unroll
    for (int i = 0; i < 4; i++)
        #pragma unroll
        for (int j = 0; j < 4; j++) p[i][j] = 0.f;

    for (int e = 0; e < 64; e++) {
        float a[4], bb[4];
        #pragma unroll
        for (int i = 0; i < 4; i++) a[i] = m3s[(tr * 4 + i) * 64 + e];
        #pragma unroll
        for (int j = 0; j < 4; j++) bb[j] = m1s[e * 64 + tc * 4 + j];
        #pragma unroll
        for (int i = 0; i < 4; i++)
            #pragma unroll
            for (int j = 0; j < 4; j++) p[i][j] += a[i] * bb[j];
    }

    const float c1 = STEP_F * SCALE_F;
    const float c2 = STEP_F * SCALE_F * SCALE_F;
    #pragma unroll
    for (int i = 0; i < 4; i++)
        #pragma unroll
        for (int j = 0; j < 4; j++) {
            const int idx = (tr * 4 + i) * 64 + (tc * 4 + j);
            g_mc[(size_t)bh * 4096 + idx] = c1 * m2s[idx] - c2 * p[i][j];
        }
}

// ---------------------------------------------------------------------------
// outhead via tf32 mma with FUSED K-normalization:
// relu(V + norm(K)@Mc - STEP*LAMBD), tf32-rounded, K-PERMUTED into g_ao.
// grid (16 token-tiles of 128, BH), 128 threads (4 warps, warp tile 32x64).
// ---------------------------------------------------------------------------
#define OH_KPITCH   68
#define OH_KS_FL    (128 * OH_KPITCH)
#define OH_MC_FL    (64 * OH_KPITCH)
#define OH_SMEM_BYTES ((OH_KS_FL + OH_MC_FL) * 4)   // 52224

__global__ void __launch_bounds__(128) outhead_mma_kernel()
{
    extern __shared__ float osm[];
    float* Ks  = osm;                    // [128][OH_KPITCH]  (tok, d)
    float* McT = osm + OH_KS_FL;         // [64][OH_KPITCH]   (d2, d1)

    const int bh   = blockIdx.y;
    const int tile = blockIdx.x;
    const int b = bh / HEADS_H, h = bh % HEADS_H;
    const int tid  = threadIdx.x;
    const int wid  = tid >> 5;
    const int lane = tid & 31;
    const int g    = lane >> 2;
    const int t    = lane & 3;
    const int n0   = tile * 128;

    {
        const int d1  = tid >> 1;
        const int d2g = (tid & 1) * 32;
        const float* src = g_mc + (size_t)bh * 4096 + d1 * 64 + d2g;
        #pragma unroll
        for (int j = 0; j < 8; j++) {
            float4 v = *(const float4*)(src + j * 4);
            McT[(d2g + j * 4 + 0) * OH_KPITCH + d1] = rtf(v.x);
            McT[(d2g + j * 4 + 1) * OH_KPITCH + d1] = rtf(v.y);
            McT[(d2g + j * 4 + 2) * OH_KPITCH + d1] = rtf(v.z);
            McT[(d2g + j * 4 + 3) * OH_KPITCH + d1] = rtf(v.w);
        }
    }
    {
        // each thread owns one full K row: in-register L2 norm, then scale
        const float* src = g_qkv + (size_t)(b * NSEQ + n0 + tid) * C3 + 768 + h * 64;
        float4 kv[16];
        float ss = 0.f;
        #pragma unroll
        for (int j = 0; j < 16; j++) {
            kv[j] = *(const float4*)(src + j * 4);
            ss += kv[j].x * kv[j].x + kv[j].y * kv[j].y
                + kv[j].z * kv[j].z + kv[j].w * kv[j].w;
        }
        const float inv = 1.0f / fmaxf(sqrtf(ss), EPS_F);
        #pragma unroll
        for (int j = 0; j < 16; j++) {
            Ks[tid * OH_KPITCH + j * 4 + 0] = rtf(kv[j].x * inv);
            Ks[tid * OH_KPITCH + j * 4 + 1] = rtf(kv[j].y * inv);
            Ks[tid * OH_KPITCH + j * 4 + 2] = rtf(kv[j].z * inv);
            Ks[tid * OH_KPITCH + j * 4 + 3] = rtf(kv[j].w * inv);
        }
    }
    __syncthreads();

    const int mrow0 = wid * 32;
    float acc[2][8][4];
    #pragma unroll
    for (int mi = 0; mi < 2; mi++)
        #pragma unroll
        for (int ni = 0; ni < 8; ni++)
            #pragma unroll
            for (int c = 0; c < 4; c++) acc[mi][ni][c] = 0.0f;

    #pragma unroll
    for (int kk = 0; kk < 64; kk += 8) {
        uint32_t af[2][4], bf[8][2];
        #pragma unroll
        for (int mi = 0; mi < 2; mi++) {
            const int mrow = mrow0 + mi * 16;
            af[mi][0] = __float_as_uint(Ks[(mrow + g)     * OH_KPITCH + kk + t]);
            af[mi][1] = __float_as_uint(Ks[(mrow + g + 8) * OH_KPITCH + kk + t]);
            af[mi][2] = __float_as_uint(Ks[(mrow + g)     * OH_KPITCH + kk + t + 4]);
            af[mi][3] = __float_as_uint(Ks[(mrow + g + 8) * OH_KPITCH + kk + t + 4]);
        }
        #pragma unroll
        for (int ni = 0; ni < 8; ni++) {
            bf[ni][0] = __float_as_uint(McT[(ni * 8 + g) * OH_KPITCH + kk + t]);
            bf[ni][1] = __float_as_uint(McT[(ni * 8 + g) * OH_KPITCH + kk + t + 4]);
        }
        #pragma unroll
        for (int mi = 0; mi < 2; mi++)
            #pragma unroll
            for (int ni = 0; ni < 8; ni++)
                mma_tf32_16x8x8(acc[mi][ni][0], acc[mi][ni][1],
                                acc[mi][ni][2], acc[mi][ni][3],
                                af[mi][0], af[mi][1], af[mi][2], af[mi][3],
                                bf[ni][0], bf[ni][1]);
    }

    const float cadd = -STEP_F * LAMBD_F;
    #pragma unroll
    for (int mi = 0; mi < 2; mi++) {
        #pragma unroll
        for (int ni = 0; ni < 8; ni++) {
            const int d0 = ni * 8 + 2 * t;
            const int p0 = perm8(d0);
            const int p1 = perm8(d0 + 1);
            #pragma unroll
            for (int half = 0; half < 2; half++) {
                const int tok = b * NSEQ + n0 + mrow0 + mi * 16 + g + half * 8;
                const float2 v = *(const float2*)(
                    g_qkv + (size_t)tok * C3 + 1536 + h * 64 + d0);
                const float r0 = fmaxf(v.x + acc[mi][ni][half * 2 + 0] + cadd, 0.0f);
                const float r1 = fmaxf(v.y + acc[mi][ni][half * 2 + 1] + cadd, 0.0f);
                float* dst = g_ao + (size_t)tok * CDIM + h * 64;
                dst[p0] = rtf(r0);
                dst[p1] = rtf(r1);
            }
        }
    }
}

// ---------------------------------------------------------------------------
extern "C" void kernel_launch(void* const* d_in, const int* in_sizes, int n_in,
                              void* d_out, int out_size)
{
    const float* x     = (const float*)d_in[0];
    const float* Wqkv  = (const float*)d_in[1];
    const float* Wproj = (const float*)d_in[2];
    const float* bproj = (const float*)d_in[3];
    float* out = (float*)d_out;

    float* qkv;  cudaGetSymbolAddress((void**)&qkv,  g_qkv);
    float* ao;   cudaGetSymbolAddress((void**)&ao,   g_ao);
    float* xr;   cudaGetSymbolAddress((void**)&xr,   g_xr);
    float* wqr;  cudaGetSymbolAddress((void**)&wqr,  g_wqkvr);
    float* wpr;  cudaGetSymbolAddress((void**)&wpr,  g_wprojr);

    cudaFuncSetAttribute(gemm_tf32_pipe,
                         cudaFuncAttributeMaxDynamicSharedMemorySize,
                         GSMEM_BYTES);
    cudaFuncSetAttribute(outhead_mma_kernel,
                         cudaFuncAttributeMaxDynamicSharedMemorySize,
                         OH_SMEM_BYTES);

    // 0. Pre-round + K-permute all GEMM operands
    round_perm_kernel<<<(RG3 + 255) / 256, 256>>>(x, Wqkv, Wproj);

    // 1. qkv = x @ Wqkv^T  (raw, normalization fused downstream)
    gemm_tf32_pipe<<<dim3(C3 / 128, TOKENS / 128), 128, GSMEM_BYTES>>>(
        xr, wqr, nullptr, qkv, TOKENS, C3, CDIM);
    // 2. Per-head moments via mma with fused q/k normalization
    moments_mma_kernel<<<dim3(BH, MCH), 192>>>();
    // 3. Mc = STEP*(SCALE*M2 - SCALE^2 * M3@M1)
    combine_kernel<<<BH, 256>>>();
    // 4. relu(V + norm(K)@Mc - STEP*LAMBD) via mma, K-permuted output
    outhead_mma_kernel<<<dim3(NSEQ / 128, BH), 128, OH_SMEM_BYTES>>>();
    // 5. out = ao @ Wproj^T + bproj
    gemm_tf32_pipe<<<dim3(CDIM / 128, TOKENS / 128), 128, GSMEM_BYTES>>>(
        ao, wpr, bproj, out, TOKENS, CDIM, CDIM);
}

// round 10
// speedup vs baseline: 2.8774x; 1.0080x over previous
#include <cuda_runtime.h>
#include <cuda_bf16.h>
#include <cstdint>
#include <math.h>

// Problem constants
#define BATCH   2
#define NSEQ    2048
#define CDIM    768
#define HEADS_H 12
#define DHEAD   64
#define TOKENS  (BATCH * NSEQ)          // 4096
#define C3      (3 * CDIM)              // 2304
#define BH      (BATCH * HEADS_H)       // 24
#define MCH     16                      // moments token-split chunks

#define SCALE_F 0.125f
#define STEP_F  0.1f
#define LAMBD_F 0.5f
#define EPS_F   1e-12f

// Scratch (static device globals — no allocation)
__device__ float g_qkv[TOKENS * C3];    // RAW qkv (normalization fused downstream)
__device__ float g_mpart[MCH * BH * 3 * DHEAD * DHEAD];
__device__ float g_msum[BH * 3 * DHEAD * DHEAD];
__device__ float g_mc[BH * DHEAD * DHEAD];
__device__ float g_ao[TOKENS * CDIM];   // K-permuted layout for GEMM2
__device__ float g_xr[TOKENS * CDIM];   // K-permuted, tf32-rounded
__device__ float g_wqkvr[C3 * CDIM];
__device__ float g_wprojr[CDIM * CDIM];

__device__ __forceinline__ uint32_t f2tf32(float f) {
    uint32_t u;
    asm("cvt.rna.tf32.f32 %0, %1;" : "=r"(u) : "f"(f));
    return u;
}
__device__ __forceinline__ float rtf(float f) {
    return __uint_as_float(f2tf32(f));
}
__device__ __forceinline__ uint32_t smem_u32(const void* p) {
    uint32_t a;
    asm("{ .reg .u64 t; cvta.to.shared.u64 t, %1; cvt.u32.u64 %0, t; }"
        : "=r"(a) : "l"(p));
    return a;
}
// K-permutation within an 8-column group: col c -> (c&3)*2 + (c>>2)
__device__ __forceinline__ int perm8(int d) {
    return (d & ~7) | (((d & 3) << 1) | ((d >> 2) & 1));
}

__device__ __forceinline__ void mma_tf32_16x8x8(
    float& c0, float& c1, float& c2, float& c3,
    uint32_t a0, uint32_t a1, uint32_t a2, uint32_t a3,
    uint32_t b0, uint32_t b1)
{
    asm volatile(
        "mma.sync.aligned.m16n8k8.row.col.f32.tf32.tf32.f32 "
        "{%0,%1,%2,%3}, {%4,%5,%6,%7}, {%8,%9}, {%0,%1,%2,%3};"
        : "+f"(c0), "+f"(c1), "+f"(c2), "+f"(c3)
        : "r"(a0), "r"(a1), "r"(a2), "r"(a3), "r"(b0), "r"(b1));
}

// ---------------------------------------------------------------------------
// Fused pre-round + K-permute for x, Wqkv, Wproj.
// ---------------------------------------------------------------------------
#define RG1 (TOKENS * CDIM / 8)              // 393216
#define RG2 (RG1 + C3 * CDIM / 8)            // 614400
#define RG3 (RG2 + CDIM * CDIM / 8)          // 688128

__global__ void __launch_bounds__(256) round_perm_kernel(
    const float* __restrict__ x, const float* __restrict__ wq,
    const float* __restrict__ wp)
{
    const int gidx = blockIdx.x * 256 + threadIdx.x;
    const float* src; float* dst; int off;
    if (gidx < RG1)      { src = x;  dst = g_xr;     off = gidx; }
    else if (gidx < RG2) { src = wq; dst = g_wqkvr;  off = gidx - RG1; }
    else if (gidx < RG3) { src = wp; dst = g_wprojr; off = gidx - RG2; }
    else return;

    const float4 a = ((const float4*)src)[off * 2];
    const float4 b = ((const float4*)src)[off * 2 + 1];
    float4 o0, o1;
    o0.x = rtf(a.x); o0.y = rtf(b.x); o0.z = rtf(a.y); o0.w = rtf(b.y);
    o1.x = rtf(a.z); o1.y = rtf(b.z); o1.z = rtf(a.w); o1.w = rtf(b.w);
    ((float4*)dst)[off * 2]     = o0;
    ((float4*)dst)[off * 2 + 1] = o1;
}

// ---------------------------------------------------------------------------
// tf32 mma.sync NT GEMM, cp.async 4-stage pipeline, K-PERMUTED operands.
// CTA 128x128, 4 warps, warp tile 64x64, K-chunk 16, pitch-24 smem, LDS.64.
// ---------------------------------------------------------------------------
#define PITCH   24
#define STAGES  4
#define STG_U32 (128 * PITCH)
#define GSMEM_BYTES (STAGES * STG_U32 * 4 * 2)      // 98304

__global__ void __launch_bounds__(128, 2) gemm_tf32_pipe(
    const float* __restrict__ A, const float* __restrict__ Bw,
    const float* __restrict__ bias, float* __restrict__ C,
    int M, int N, int K)
{
    extern __shared__ uint32_t sm[];
    uint32_t* As = sm;
    uint32_t* Bs = sm + STAGES * STG_U32;

    const int tid  = threadIdx.x;
    const int wid  = tid >> 5;
    const int lane = tid & 31;
    const int g    = lane >> 2;
    const int t    = lane & 3;
    const int row0 = blockIdx.y * 128;
    const int col0 = blockIdx.x * 128;
    const int wm0  = (wid >> 1) * 64;
    const int wn0  = (wid & 1) * 64;

    float acc[4][8][4];
    #pragma unroll
    for (int mi = 0; mi < 4; mi++)
        #pragma unroll
        for (int ni = 0; ni < 8; ni++)
            #pragma unroll
            for (int c = 0; c < 4; c++) acc[mi][ni][c] = 0.0f;

    const int lrow = tid >> 2;            // 0..31
    const int lseg = (tid & 3) << 2;      // 0,4,8,12

    const float* aptr = A  + (size_t)(row0 + lrow) * K + lseg;
    const float* bptr = Bw + (size_t)(col0 + lrow) * K + lseg;
    const uint32_t a_sb = smem_u32(As) + (lrow * PITCH + lseg) * 4;
    const uint32_t b_sb = smem_u32(Bs) + (lrow * PITCH + lseg) * 4;

    const int nc = K >> 4;

    #pragma unroll
    for (int s = 0; s < STAGES - 1; s++) {
        const int k0 = s << 4;
        #pragma unroll
        for (int i = 0; i < 4; i++) {
            const uint32_t so = s * STG_U32 * 4 + i * 32 * PITCH * 4;
            asm volatile("cp.async.cg.shared.global [%0], [%1], 16;"
                :: "r"(a_sb + so), "l"(aptr + (size_t)i * 32 * K + k0) : "memory");
            asm volatile("cp.async.cg.shared.global [%0], [%1], 16;"
                :: "r"(b_sb + so), "l"(bptr + (size_t)i * 32 * K + k0) : "memory");
        }
        asm volatile("cp.async.commit_group;" ::: "memory");
    }

    for (int c = 0; c < nc; c++) {
        asm volatile("cp.async.wait_group %0;" :: "n"(STAGES - 2) : "memory");
        __syncthreads();

        const int cn = c + STAGES - 1;
        if (cn < nc) {
            const int s  = cn & (STAGES - 1);
            const int k0 = cn << 4;
            #pragma unroll
            for (int i = 0; i < 4; i++) {
                const uint32_t so = s * STG_U32 * 4 + i * 32 * PITCH * 4;
                asm volatile("cp.async.cg.shared.global [%0], [%1], 16;"
                    :: "r"(a_sb + so), "l"(aptr + (size_t)i * 32 * K + k0) : "memory");
                asm volatile("cp.async.cg.shared.global [%0], [%1], 16;"
                    :: "r"(b_sb + so), "l"(bptr + (size_t)i * 32 * K + k0) : "memory");
            }
        }
        asm volatile("cp.async.commit_group;" ::: "memory");

        const uint32_t* as = As + (c & (STAGES - 1)) * STG_U32;
        const uint32_t* bs = Bs + (c & (STAGES - 1)) * STG_U32;
        #pragma unroll
        for (int ks = 0; ks < 2; ks++) {
            const int kk = ks * 8;
            uint32_t af[4][4], bf[8][2];
            #pragma unroll
            for (int mi = 0; mi < 4; mi++) {
                const int mrow = wm0 + mi * 16;
                const uint2 av0 = *(const uint2*)&as[(mrow + g)     * PITCH + kk + 2 * t];
                const uint2 av1 = *(const uint2*)&as[(mrow + g + 8) * PITCH + kk + 2 * t];
                af[mi][0] = av0.x; af[mi][2] = av0.y;
                af[mi][1] = av1.x; af[mi][3] = av1.y;
            }
            #pragma unroll
            for (int ni = 0; ni < 8; ni++) {
                const int nrow = wn0 + ni * 8 + g;
                const uint2 bv = *(const uint2*)&bs[nrow * PITCH + kk + 2 * t];
                bf[ni][0] = bv.x; bf[ni][1] = bv.y;
            }
            #pragma unroll
            for (int mi = 0; mi < 4; mi++)
                #pragma unroll
                for (int ni = 0; ni < 8; ni++)
                    mma_tf32_16x8x8(acc[mi][ni][0], acc[mi][ni][1],
                                    acc[mi][ni][2], acc[mi][ni][3],
                                    af[mi][0], af[mi][1], af[mi][2], af[mi][3],
                                    bf[ni][0], bf[ni][1]);
        }
    }

    #pragma unroll
    for (int mi = 0; mi < 4; mi++) {
        #pragma unroll
        for (int ni = 0; ni < 8; ni++) {
            const int col = col0 + wn0 + ni * 8 + 2 * t;
            float b0 = 0.f, b1 = 0.f;
            if (bias) { b0 = bias[col]; b1 = bias[col + 1]; }
            const int r0 = row0 + wm0 + mi * 16 + g;
            *(float2*)(C + (size_t)r0 * N + col) =
                make_float2(acc[mi][ni][0] + b0, acc[mi][ni][1] + b1);
            *(float2*)(C + (size_t)(r0 + 8) * N + col) =
                make_float2(acc[mi][ni][2] + b0, acc[mi][ni][3] + b1);
        }
    }
}

// ---------------------------------------------------------------------------
// Moments via tf32 mma with FUSED L2-normalization of q,k.
// Per (b,h,chunk of 128 tokens): partial M1=K^T V, M2=Q^T V, M3=Q^T Q.
// grid (BH, MCH), 192 threads (6 warps). Double-buffered smem, 1 sync/iter.
// ---------------------------------------------------------------------------
#define MTOK (NSEQ / MCH)                // 128 tokens per chunk
#define MNIT (MTOK / 16)                 // 8 iters of 16 tokens

__global__ void __launch_bounds__(192) moments_mma_kernel()
{
    __shared__ float QT[2][64][17];
    __shared__ float KT[2][64][17];
    __shared__ float VT[2][64][17];

    const int bh = blockIdx.x;
    const int ch = blockIdx.y;
    const int b = bh / HEADS_H, h = bh % HEADS_H;
    const int tid  = threadIdx.x;
    const int wid  = tid >> 5;           // 0..5
    const int lane = tid & 31;
    const int g    = lane >> 2;
    const int t    = lane & 3;
    const int o    = wid >> 1;           // 0=M1,1=M2,2=M3
    const int mhalf = (wid & 1) * 32;

    const int mat  = tid >> 6;           // 0=Q,1=K,2=V
    const int idx  = tid & 63;
    const int ltok = idx >> 2;           // 0..15
    const int ldg  = (idx & 3) << 4;     // 0,16,32,48

    const size_t base = (size_t)(b * NSEQ + ch * MTOK) * C3 + mat * 768 + h * 64;

    float acc[2][8][4];
    #pragma unroll
    for (int mi = 0; mi < 2; mi++)
        #pragma unroll
        for (int ni = 0; ni < 8; ni++)
            #pragma unroll
            for (int c = 0; c < 4; c++) acc[mi][ni][c] = 0.0f;

    float4 v[4];
    {
        const float* src = g_qkv + base + (size_t)ltok * C3 + ldg;
        #pragma unroll
        for (int j = 0; j < 4; j++) v[j] = *(const float4*)(src + j * 4);
    }

    for (int it = 0; it < MNIT; it++) {
        float inv = 1.0f;
        if (mat < 2) {
            float ss = 0.f;
            #pragma unroll
            for (int j = 0; j < 4; j++)
                ss += v[j].x * v[j].x + v[j].y * v[j].y
                    + v[j].z * v[j].z + v[j].w * v[j].w;
            ss += __shfl_xor_sync(0xffffffffu, ss, 1);
            ss += __shfl_xor_sync(0xffffffffu, ss, 2);
            inv = 1.0f / fmaxf(sqrtf(ss), EPS_F);
        }
        {
            float (*Td)[17] = (mat == 0) ? QT[it & 1]
                            : (mat == 1) ? KT[it & 1] : VT[it & 1];
            #pragma unroll
            for (int j = 0; j < 4; j++) {
                Td[ldg + j * 4 + 0][ltok] = rtf(v[j].x * inv);
                Td[ldg + j * 4 + 1][ltok] = rtf(v[j].y * inv);
                Td[ldg + j * 4 + 2][ltok] = rtf(v[j].z * inv);
                Td[ldg + j * 4 + 3][ltok] = rtf(v[j].w * inv);
            }
        }
        float4 vn[4];
        if (it + 1 < MNIT) {
            const float* src = g_qkv + base + (size_t)((it + 1) * 16 + ltok) * C3 + ldg;
            #pragma unroll
            for (int j = 0; j < 4; j++) vn[j] = *(const float4*)(src + j * 4);
        }
        __syncthreads();

        const float (*Am)[17] = (o == 0) ? KT[it & 1] : QT[it & 1];
        const float (*Bm)[17] = (o == 2) ? QT[it & 1] : VT[it & 1];
        #pragma unroll
        for (int kk = 0; kk < 16; kk += 8) {
            uint32_t af[2][4], bf[8][2];
            #pragma unroll
            for (int mi = 0; mi < 2; mi++) {
                const int mrow = mhalf + mi * 16;
                af[mi][0] = __float_as_uint(Am[mrow + g][kk + t]);
                af[mi][1] = __float_as_uint(Am[mrow + g + 8][kk + t]);
                af[mi][2] = __float_as_uint(Am[mrow + g][kk + t + 4]);
                af[mi][3] = __float_as_uint(Am[mrow + g + 8][kk + t + 4]);
            }
            #pragma unroll
            for (int ni = 0; ni < 8; ni++) {
                bf[ni][0] = __float_as_uint(Bm[ni * 8 + g][kk + t]);
                bf[ni][1] = __float_as_uint(Bm[ni * 8 + g][kk + t + 4]);
            }
            #pragma unroll
            for (int mi = 0; mi < 2; mi++)
                #pragma unroll
                for (int ni = 0; ni < 8; ni++)
                    mma_tf32_16x8x8(acc[mi][ni][0], acc[mi][ni][1],
                                    acc[mi][ni][2], acc[mi][ni][3],
                                    af[mi][0], af[mi][1], af[mi][2], af[mi][3],
                                    bf[ni][0], bf[ni][1]);
        }
        #pragma unroll
        for (int j = 0; j < 4; j++) v[j] = vn[j];
    }

    float* outp = g_mpart + ((size_t)(ch * BH + bh) * 3 + o) * 4096;
    #pragma unroll
    for (int mi = 0; mi < 2; mi++) {
        #pragma unroll
        for (int ni = 0; ni < 8; ni++) {
            const int row = mhalf + mi * 16 + g;
            const int col = ni * 8 + 2 * t;
            *(float2*)(outp + row * 64 + col) =
                make_float2(acc[mi][ni][0], acc[mi][ni][1]);
            *(float2*)(outp + (row + 8) * 64 + col) =
                make_float2(acc[mi][ni][2], acc[mi][ni][3]);
        }
    }
}

// ---------------------------------------------------------------------------
// Parallel reduce of g_mpart over MCH chunks -> g_msum[(bh*3+o)*4096 + i]
// grid 288 x 256: one float4 per thread, 16 strided loads.
// ---------------------------------------------------------------------------
#define RED_F4 (BH * 3 * DHEAD * DHEAD / 4)   // 73728

__global__ void __launch_bounds__(256) reduce_mpart_kernel()
{
    const int f4 = blockIdx.x * 256 + threadIdx.x;   // 0..73727
    if (f4 >= RED_F4) return;
    const int elem = f4 * 4;
    const int bh_o = elem >> 12;          // (bh*3+o)
    const int bh   = bh_o / 3;
    const int o    = bh_o - bh * 3;
    const int i    = elem & 4095;

    float4 s = make_float4(0, 0, 0, 0);
    #pragma unroll
    for (int ch = 0; ch < MCH; ch++) {
        const float4 v = *(const float4*)(
            g_mpart + ((size_t)(ch * BH + bh) * 3 + o) * 4096 + i);
        s.x += v.x; s.y += v.y; s.z += v.z; s.w += v.w;
    }
    *(float4*)(g_msum + (size_t)bh_o * 4096 + i) = s;
}

// ---------------------------------------------------------------------------
// Small combine: Mc = STEP*(SCALE*M2 - SCALE^2*M3@M1) from summed moments.
// grid BH x 256. Reads 48KB total.
// ---------------------------------------------------------------------------
__global__ void __launch_bounds__(256) combine_small_kernel()
{
    const int bh  = blockIdx.x;
    const int tid = threadIdx.x;
    __shared__ float m1s[4096];
    __shared__ float m3s[4096];

    const float* src = g_msum + (size_t)bh * 3 * 4096;
    #pragma unroll
    for (int i = 0; i < 4; i++) {
        const int o4 = tid + i * 256;
        ((float4*)m1s)[o4] = ((const float4*)src)[o4];
        ((float4*)m3s)[o4] = ((const float4*)(src + 8192))[o4];
    }
    __syncthreads();

    const int tr = tid >> 4, tc = tid & 15;
    float p[4][4];
    #pragma unroll
    for (int i = 0; i < 4; i++)
        #pragma unroll
        for (int j = 0; j < 4; j++) p[i][j] = 0.f;

    for (int e = 0; e < 64; e++) {
        float a[4], bb[4];
        #pragma unroll
        for (int i = 0; i < 4; i++) a[i] = m3s[(tr * 4 + i) * 64 + e];
        #pragma unroll
        for (int j = 0; j < 4; j++) bb[j] = m1s[e * 64 + tc * 4 + j];
        #pragma unroll
        for (int i = 0; i < 4; i++)
            #pragma unroll
            for (int j = 0; j < 4; j++) p[i][j] += a[i] * bb[j];
    }

    const float c1 = STEP_F * SCALE_F;
    const float c2 = STEP_F * SCALE_F * SCALE_F;
    const float* m2p = src + 4096;
    #pragma unroll
    for (int i = 0; i < 4; i++)
        #pragma unroll
        for (int j = 0; j < 4; j++) {
            const int idx = (tr * 4 + i) * 64 + (tc * 4 + j);
            g_mc[(size_t)bh * 4096 + idx] = c1 * m2p[idx] - c2 * p[i][j];
        }
}

// ---------------------------------------------------------------------------
// outhead via tf32 mma with FUSED K-normalization:
// relu(V + norm(K)@Mc - STEP*LAMBD), tf32-rounded, K-PERMUTED into g_ao.
// ---------------------------------------------------------------------------
#define OH_KPITCH   68
#define OH_KS_FL    (128 * OH_KPITCH)
#define OH_MC_FL    (64 * OH_KPITCH)
#define OH_SMEM_BYTES ((OH_KS_FL + OH_MC_FL) * 4)   // 52224

__global__ void __launch_bounds__(128) outhead_mma_kernel()
{
    extern __shared__ float osm[];
    float* Ks  = osm;                    // [128][OH_KPITCH]  (tok, d)
    float* McT = osm + OH_KS_FL;         // [64][OH_KPITCH]   (d2, d1)

    const int bh   = blockIdx.y;
    const int tile = blockIdx.x;
    const int b = bh / HEADS_H, h = bh % HEADS_H;
    const int tid  = threadIdx.x;
    const int wid  = tid >> 5;
    const int lane = tid & 31;
    const int g    = lane >> 2;
    const int t    = lane & 3;
    const int n0   = tile * 128;

    {
        const int d1  = tid >> 1;
        const int d2g = (tid & 1) * 32;
        const float* src = g_mc + (size_t)bh * 4096 + d1 * 64 + d2g;
        #pragma unroll
        for (int j = 0; j < 8; j++) {
            float4 v = *(const float4*)(src + j * 4);
            McT[(d2g + j * 4 + 0) * OH_KPITCH + d1] = rtf(v.x);
            McT[(d2g + j * 4 + 1) * OH_KPITCH + d1] = rtf(v.y);
            McT[(d2g + j * 4 + 2) * OH_KPITCH + d1] = rtf(v.z);
            McT[(d2g + j * 4 + 3) * OH_KPITCH + d1] = rtf(v.w);
        }
    }
    {
        const float* src = g_qkv + (size_t)(b * NSEQ + n0 + tid) * C3 + 768 + h * 64;
        float4 kv[16];
        float ss = 0.f;
        #pragma unroll
        for (int j = 0; j < 16; j++) {
            kv[j] = *(const float4*)(src + j * 4);
            ss += kv[j].x * kv[j].x + kv[j].y * kv[j].y
                + kv[j].z * kv[j].z + kv[j].w * kv[j].w;
        }
        const float inv = 1.0f / fmaxf(sqrtf(ss), EPS_F);
        #pragma unroll
        for (int j = 0; j < 16; j++) {
            Ks[tid * OH_KPITCH + j * 4 + 0] = rtf(kv[j].x * inv);
            Ks[tid * OH_KPITCH + j * 4 + 1] = rtf(kv[j].y * inv);
            Ks[tid * OH_KPITCH + j * 4 + 2] = rtf(kv[j].z * inv);
            Ks[tid * OH_KPITCH + j * 4 + 3] = rtf(kv[j].w * inv);
        }
    }
    __syncthreads();

    const int mrow0 = wid * 32;
    float acc[2][8][4];
    #pragma unroll
    for (int mi = 0; mi < 2; mi++)
        #pragma unroll
        for (int ni = 0; ni < 8; ni++)
            #pragma unroll
            for (int c = 0; c < 4; c++) acc[mi][ni][c] = 0.0f;

    #pragma unroll
    for (int kk = 0; kk < 64; kk += 8) {
        uint32_t af[2][4], bf[8][2];
        #pragma unroll
        for (int mi = 0; mi < 2; mi++) {
            const int mrow = mrow0 + mi * 16;
            af[mi][0] = __float_as_uint(Ks[(mrow + g)     * OH_KPITCH + kk + t]);
            af[mi][1] = __float_as_uint(Ks[(mrow + g + 8) * OH_KPITCH + kk + t]);
            af[mi][2] = __float_as_uint(Ks[(mrow + g)     * OH_KPITCH + kk + t + 4]);
            af[mi][3] = __float_as_uint(Ks[(mrow + g + 8) * OH_KPITCH + kk + t + 4]);
        }
        #pragma unroll
        for (int ni = 0; ni < 8; ni++) {
            bf[ni][0] = __float_as_uint(McT[(ni * 8 + g) * OH_KPITCH + kk + t]);
            bf[ni][1] = __float_as_uint(McT[(ni * 8 + g) * OH_KPITCH + kk + t + 4]);
        }
        #pragma unroll
        for (int mi = 0; mi < 2; mi++)
            #pragma unroll
            for (int ni = 0; ni < 8; ni++)
                mma_tf32_16x8x8(acc[mi][ni][0], acc[mi][ni][1],
                                acc[mi][ni][2], acc[mi][ni][3],
                                af[mi][0], af[mi][1], af[mi][2], af[mi][3],
                                bf[ni][0], bf[ni][1]);
    }

    const float cadd = -STEP_F * LAMBD_F;
    #pragma unroll
    for (int mi = 0; mi < 2; mi++) {
        #pragma unroll
        for (int ni = 0; ni < 8; ni++) {
            const int d0 = ni * 8 + 2 * t;
            const int p0 = perm8(d0);
            const int p1 = perm8(d0 + 1);
            #pragma unroll
            for (int half = 0; half < 2; half++) {
                const int tok = b * NSEQ + n0 + mrow0 + mi * 16 + g + half * 8;
                const float2 v = *(const float2*)(
                    g_qkv + (size_t)tok * C3 + 1536 + h * 64 + d0);
                const float r0 = fmaxf(v.x + acc[mi][ni][half * 2 + 0] + cadd, 0.0f);
                const float r1 = fmaxf(v.y + acc[mi][ni][half * 2 + 1] + cadd, 0.0f);
                float* dst = g_ao + (size_t)tok * CDIM + h * 64;
                dst[p0] = rtf(r0);
                dst[p1] = rtf(r1);
            }
        }
    }
}

// ---------------------------------------------------------------------------
extern "C" void kernel_launch(void* const* d_in, const int* in_sizes, int n_in,
                              void* d_out, int out_size)
{
    const float* x     = (const float*)d_in[0];
    const float* Wqkv  = (const float*)d_in[1];
    const float* Wproj = (const float*)d_in[2];
    const float* bproj = (const float*)d_in[3];
    float* out = (float*)d_out;

    float* qkv;  cudaGetSymbolAddress((void**)&qkv,  g_qkv);
    float* ao;   cudaGetSymbolAddress((void**)&ao,   g_ao);
    float* xr;   cudaGetSymbolAddress((void**)&xr,   g_xr);
    float* wqr;  cudaGetSymbolAddress((void**)&wqr,  g_wqkvr);
    float* wpr;  cudaGetSymbolAddress((void**)&wpr,  g_wprojr);

    cudaFuncSetAttribute(gemm_tf32_pipe,
                         cudaFuncAttributeMaxDynamicSharedMemorySize,
                         GSMEM_BYTES);
    cudaFuncSetAttribute(outhead_mma_kernel,
                         cudaFuncAttributeMaxDynamicSharedMemorySize,
                         OH_SMEM_BYTES);

    // 0. Pre-round + K-permute all GEMM operands
    round_perm_kernel<<<(RG3 + 255) / 256, 256>>>(x, Wqkv, Wproj);

    // 1. qkv = x @ Wqkv^T  (raw, normalization fused downstream)
    gemm_tf32_pipe<<<dim3(C3 / 128, TOKENS / 128), 128, GSMEM_BYTES>>>(
        xr, wqr, nullptr, qkv, TOKENS, C3, CDIM);
    // 2. Per-head moments via mma with fused q/k normalization
    moments_mma_kernel<<<dim3(BH, MCH), 192>>>();
    // 3a. Parallel reduce of chunk partials
    reduce_mpart_kernel<<<(RED_F4 + 255) / 256, 256>>>();
    // 3b. Mc = STEP*(SCALE*M2 - SCALE^2 * M3@M1)
    combine_small_kernel<<<BH, 256>>>();
    // 4. relu(V + norm(K)@Mc - STEP*LAMBD) via mma, K-permuted output
    outhead_mma_kernel<<<dim3(NSEQ / 128, BH), 128, OH_SMEM_BYTES>>>();
    // 5. out = ao @ Wproj^T + bproj
    gemm_tf32_pipe<<<dim3(CDIM / 128, TOKENS / 128), 128, GSMEM_BYTES>>>(
        ao, wpr, bproj, out, TOKENS, CDIM, CDIM);
}

// round 11
// speedup vs baseline: 4.4625x; 1.5509x over previous
#include <cuda_runtime.h>
#include <cuda_fp16.h>
#include <cstdint>
#include <math.h>

// Problem constants
#define BATCH   2
#define NSEQ    2048
#define CDIM    768
#define HEADS_H 12
#define DHEAD   64
#define TOKENS  (BATCH * NSEQ)          // 4096
#define C3      (3 * CDIM)              // 2304
#define BH      (BATCH * HEADS_H)       // 24
#define MCH     16                      // moments token-split chunks

#define SCALE_F 0.125f
#define STEP_F  0.1f
#define LAMBD_F 0.5f
#define EPS_F   1e-12f

// Scratch (static device globals — no allocation)
__device__ float  g_qkv[TOKENS * C3];   // RAW qkv fp32
__device__ float  g_mpart[MCH * BH * 3 * DHEAD * DHEAD];
__device__ float  g_msum[BH * 3 * DHEAD * DHEAD];
__device__ float  g_mc[BH * DHEAD * DHEAD];
__device__ __half g_aoh[TOKENS * CDIM];     // fp16, K-permuted
__device__ __half g_xh[TOKENS * CDIM];      // fp16, K-permuted
__device__ __half g_wqkvh[C3 * CDIM];
__device__ __half g_wprojh[CDIM * CDIM];

__device__ __forceinline__ uint32_t f2tf32(float f) {
    uint32_t u;
    asm("cvt.rna.tf32.f32 %0, %1;" : "=r"(u) : "f"(f));
    return u;
}
__device__ __forceinline__ float rtf(float f) {
    return __uint_as_float(f2tf32(f));
}
__device__ __forceinline__ uint32_t smem_u32(const void* p) {
    uint32_t a;
    asm("{ .reg .u64 t; cvta.to.shared.u64 t, %1; cvt.u32.u64 %0, t; }"
        : "=r"(a) : "l"(p));
    return a;
}
__device__ __forceinline__ uint32_t h2u(float a, float b) {
    __half2 h = __floats2half2_rn(a, b);
    return *reinterpret_cast<uint32_t*>(&h);
}

// fp16 m16n8k16 MMA, fp32 accumulate
__device__ __forceinline__ void mma_f16_16x8x16(
    float& c0, float& c1, float& c2, float& c3,
    uint32_t a0, uint32_t a1, uint32_t a2, uint32_t a3,
    uint32_t b0, uint32_t b1)
{
    asm volatile(
        "mma.sync.aligned.m16n8k16.row.col.f32.f16.f16.f32 "
        "{%0,%1,%2,%3}, {%4,%5,%6,%7}, {%8,%9}, {%0,%1,%2,%3};"
        : "+f"(c0), "+f"(c1), "+f"(c2), "+f"(c3)
        : "r"(a0), "r"(a1), "r"(a2), "r"(a3), "r"(b0), "r"(b1));
}
// tf32 m16n8k8 MMA (moments/outhead path, unchanged)
__device__ __forceinline__ void mma_tf32_16x8x8(
    float& c0, float& c1, float& c2, float& c3,
    uint32_t a0, uint32_t a1, uint32_t a2, uint32_t a3,
    uint32_t b0, uint32_t b1)
{
    asm volatile(
        "mma.sync.aligned.m16n8k8.row.col.f32.tf32.tf32.f32 "
        "{%0,%1,%2,%3}, {%4,%5,%6,%7}, {%8,%9}, {%0,%1,%2,%3};"
        : "+f"(c0), "+f"(c1), "+f"(c2), "+f"(c3)
        : "r"(a0), "r"(a1), "r"(a2), "r"(a3), "r"(b0), "r"(b1));
}

// ---------------------------------------------------------------------------
// Fused fp32->fp16 convert + 16-wide K-permute for x, Wqkv, Wproj.
// Per 16-col group, output order (by position) = cols
//   [0,1,8,9,2,3,10,11,4,5,12,13,6,7,14,15]
// so thread t's m16n8k16 fragment halves (2t,2t+1,2t+8,2t+9) are contiguous.
// ---------------------------------------------------------------------------
#define HG1 (TOKENS * CDIM / 16)             // 196608
#define HG2 (HG1 + C3 * CDIM / 16)           // 307200
#define HG3 (HG2 + CDIM * CDIM / 16)         // 344064

__global__ void __launch_bounds__(256) round_perm_kernel(
    const float* __restrict__ x, const float* __restrict__ wq,
    const float* __restrict__ wp)
{
    const int gidx = blockIdx.x * 256 + threadIdx.x;
    const float* src; __half* dst; int off;
    if (gidx < HG1)      { src = x;  dst = g_xh;     off = gidx; }
    else if (gidx < HG2) { src = wq; dst = g_wqkvh;  off = gidx - HG1; }
    else if (gidx < HG3) { src = wp; dst = g_wprojh; off = gidx - HG2; }
    else return;

    const float4* s4 = (const float4*)(src) + off * 4;
    const float4 f0 = s4[0];   // cols 0-3
    const float4 f1 = s4[1];   // cols 4-7
    const float4 f2 = s4[2];   // cols 8-11
    const float4 f3 = s4[3];   // cols 12-15

    uint4 u0, u1;
    u0.x = h2u(f0.x, f0.y);  u0.y = h2u(f2.x, f2.y);   // 0,1 | 8,9
    u0.z = h2u(f0.z, f0.w);  u0.w = h2u(f2.z, f2.w);   // 2,3 | 10,11
    u1.x = h2u(f1.x, f1.y);  u1.y = h2u(f3.x, f3.y);   // 4,5 | 12,13
    u1.z = h2u(f1.z, f1.w);  u1.w = h2u(f3.z, f3.w);   // 6,7 | 14,15
    uint4* d4 = (uint4*)(dst + (size_t)off * 16);
    d4[0] = u0;
    d4[1] = u1;
}

// ---------------------------------------------------------------------------
// fp16 mma.sync NT GEMM, cp.async 4-stage pipeline, K-PERMUTED fp16 operands.
// CTA 128x128, 4 warps, warp tile 64x64, K-chunk 32, pitch 48 halves (96B).
// Fragment loads are LDS.64, conflict-free (dbank = 12g+t mod 16).
// ---------------------------------------------------------------------------
#define HP        48                          // smem pitch in halves
#define HSTAGES   4
#define HSTG_B    (128 * HP * 2)              // 12288 bytes per matrix stage
#define HGSMEM    (HSTAGES * HSTG_B * 2)      // 98304

__global__ void __launch_bounds__(128, 2) gemm_f16_pipe(
    const __half* __restrict__ A, const __half* __restrict__ Bw,
    const float* __restrict__ bias, float* __restrict__ C,
    int M, int N, int K)
{
    extern __shared__ __half hsm[];
    __half* As = hsm;
    __half* Bs = hsm + HSTAGES * 128 * HP;

    const int tid  = threadIdx.x;
    const int wid  = tid >> 5;
    const int lane = tid & 31;
    const int g    = lane >> 2;
    const int t    = lane & 3;
    const int row0 = blockIdx.y * 128;
    const int col0 = blockIdx.x * 128;
    const int wm0  = (wid >> 1) * 64;
    const int wn0  = (wid & 1) * 64;

    float acc[4][8][4];
    #pragma unroll
    for (int mi = 0; mi < 4; mi++)
        #pragma unroll
        for (int ni = 0; ni < 8; ni++)
            #pragma unroll
            for (int c = 0; c < 4; c++) acc[mi][ni][c] = 0.0f;

    // Loader: 128 rows x 64B per matrix per chunk; thread -> 4 rows (+32i),
    // 16B (8 halves) per row segment.
    const int lrow = tid >> 2;            // 0..31
    const int lseg = (tid & 3) << 3;      // 0,8,16,24 halves

    const __half* aptr = A  + (size_t)(row0 + lrow) * K + lseg;
    const __half* bptr = Bw + (size_t)(col0 + lrow) * K + lseg;
    const uint32_t a_sb = smem_u32(As) + (lrow * HP + lseg) * 2;
    const uint32_t b_sb = smem_u32(Bs) + (lrow * HP + lseg) * 2;

    const int nc = K >> 5;

    #pragma unroll
    for (int s = 0; s < HSTAGES - 1; s++) {
        const int k0 = s << 5;
        #pragma unroll
        for (int i = 0; i < 4; i++) {
            const uint32_t so = s * HSTG_B + i * 32 * HP * 2;
            asm volatile("cp.async.cg.shared.global [%0], [%1], 16;"
                :: "r"(a_sb + so), "l"(aptr + (size_t)i * 32 * K + k0) : "memory");
            asm volatile("cp.async.cg.shared.global [%0], [%1], 16;"
                :: "r"(b_sb + so), "l"(bptr + (size_t)i * 32 * K + k0) : "memory");
        }
        asm volatile("cp.async.commit_group;" ::: "memory");
    }

    for (int c = 0; c < nc; c++) {
        asm volatile("cp.async.wait_group %0;" :: "n"(HSTAGES - 2) : "memory");
        __syncthreads();

        const int cn = c + HSTAGES - 1;
        if (cn < nc) {
            const int s  = cn & (HSTAGES - 1);
            const int k0 = cn << 5;
            #pragma unroll
            for (int i = 0; i < 4; i++) {
                const uint32_t so = s * HSTG_B + i * 32 * HP * 2;
                asm volatile("cp.async.cg.shared.global [%0], [%1], 16;"
                    :: "r"(a_sb + so), "l"(aptr + (size_t)i * 32 * K + k0) : "memory");
                asm volatile("cp.async.cg.shared.global [%0], [%1], 16;"
                    :: "r"(b_sb + so), "l"(bptr + (size_t)i * 32 * K + k0) : "memory");
            }
        }
        asm volatile("cp.async.commit_group;" ::: "memory");

        const __half* as = As + (c & (HSTAGES - 1)) * 128 * HP;
        const __half* bs = Bs + (c & (HSTAGES - 1)) * 128 * HP;
        #pragma unroll
        for (int kk = 0; kk < 2; kk++) {          // two K=16 groups per chunk
            const int ko = kk * 16 + t * 4;       // permuted: 4 contig halves
            uint32_t af[4][4], bf[8][2];
            #pragma unroll
            for (int mi = 0; mi < 4; mi++) {
                const int mrow = wm0 + mi * 16;
                const uint2 av0 = *(const uint2*)(as + (mrow + g)     * HP + ko);
                const uint2 av1 = *(const uint2*)(as + (mrow + g + 8) * HP + ko);
                af[mi][0] = av0.x; af[mi][2] = av0.y;   // a0,a2 (row g)
                af[mi][1] = av1.x; af[mi][3] = av1.y;   // a1,a3 (row g+8)
            }
            #pragma unroll
            for (int ni = 0; ni < 8; ni++) {
                const uint2 bv = *(const uint2*)(bs + (wn0 + ni * 8 + g) * HP + ko);
                bf[ni][0] = bv.x; bf[ni][1] = bv.y;
            }
            #pragma unroll
            for (int mi = 0; mi < 4; mi++)
                #pragma unroll
                for (int ni = 0; ni < 8; ni++)
                    mma_f16_16x8x16(acc[mi][ni][0], acc[mi][ni][1],
                                    acc[mi][ni][2], acc[mi][ni][3],
                                    af[mi][0], af[mi][1], af[mi][2], af[mi][3],
                                    bf[ni][0], bf[ni][1]);
        }
    }

    #pragma unroll
    for (int mi = 0; mi < 4; mi++) {
        #pragma unroll
        for (int ni = 0; ni < 8; ni++) {
            const int col = col0 + wn0 + ni * 8 + 2 * t;
            float b0 = 0.f, b1 = 0.f;
            if (bias) { b0 = bias[col]; b1 = bias[col + 1]; }
            const int r0 = row0 + wm0 + mi * 16 + g;
            *(float2*)(C + (size_t)r0 * N + col) =
                make_float2(acc[mi][ni][0] + b0, acc[mi][ni][1] + b1);
            *(float2*)(C + (size_t)(r0 + 8) * N + col) =
                make_float2(acc[mi][ni][2] + b0, acc[mi][ni][3] + b1);
        }
    }
}

// ---------------------------------------------------------------------------
// Moments via tf32 mma with FUSED L2-normalization of q,k (unchanged).
// ---------------------------------------------------------------------------
#define MTOK (NSEQ / MCH)                // 128 tokens per chunk
#define MNIT (MTOK / 16)                 // 8 iters of 16 tokens

__global__ void __launch_bounds__(192) moments_mma_kernel()
{
    __shared__ float QT[2][64][17];
    __shared__ float KT[2][64][17];
    __shared__ float VT[2][64][17];

    const int bh = blockIdx.x;
    const int ch = blockIdx.y;
    const int b = bh / HEADS_H, h = bh % HEADS_H;
    const int tid  = threadIdx.x;
    const int wid  = tid >> 5;
    const int lane = tid & 31;
    const int g    = lane >> 2;
    const int t    = lane & 3;
    const int o    = wid >> 1;
    const int mhalf = (wid & 1) * 32;

    const int mat  = tid >> 6;
    const int idx  = tid & 63;
    const int ltok = idx >> 2;
    const int ldg  = (idx & 3) << 4;

    const size_t base = (size_t)(b * NSEQ + ch * MTOK) * C3 + mat * 768 + h * 64;

    float acc[2][8][4];
    #pragma unroll
    for (int mi = 0; mi < 2; mi++)
        #pragma unroll
        for (int ni = 0; ni < 8; ni++)
            #pragma unroll
            for (int c = 0; c < 4; c++) acc[mi][ni][c] = 0.0f;

    float4 v[4];
    {
        const float* src = g_qkv + base + (size_t)ltok * C3 + ldg;
        #pragma unroll
        for (int j = 0; j < 4; j++) v[j] = *(const float4*)(src + j * 4);
    }

    for (int it = 0; it < MNIT; it++) {
        float inv = 1.0f;
        if (mat < 2) {
            float ss = 0.f;
            #pragma unroll
            for (int j = 0; j < 4; j++)
                ss += v[j].x * v[j].x + v[j].y * v[j].y
                    + v[j].z * v[j].z + v[j].w * v[j].w;
            ss += __shfl_xor_sync(0xffffffffu, ss, 1);
            ss += __shfl_xor_sync(0xffffffffu, ss, 2);
            inv = 1.0f / fmaxf(sqrtf(ss), EPS_F);
        }
        {
            float (*Td)[17] = (mat == 0) ? QT[it & 1]
                            : (mat == 1) ? KT[it & 1] : VT[it & 1];
            #pragma unroll
            for (int j = 0; j < 4; j++) {
                Td[ldg + j * 4 + 0][ltok] = rtf(v[j].x * inv);
                Td[ldg + j * 4 + 1][ltok] = rtf(v[j].y * inv);
                Td[ldg + j * 4 + 2][ltok] = rtf(v[j].z * inv);
                Td[ldg + j * 4 + 3][ltok] = rtf(v[j].w * inv);
            }
        }
        float4 vn[4];
        if (it + 1 < MNIT) {
            const float* src = g_qkv + base + (size_t)((it + 1) * 16 + ltok) * C3 + ldg;
            #pragma unroll
            for (int j = 0; j < 4; j++) vn[j] = *(const float4*)(src + j * 4);
        }
        __syncthreads();

        const float (*Am)[17] = (o == 0) ? KT[it & 1] : QT[it & 1];
        const float (*Bm)[17] = (o == 2) ? QT[it & 1] : VT[it & 1];
        #pragma unroll
        for (int kk = 0; kk < 16; kk += 8) {
            uint32_t af[2][4], bf[8][2];
            #pragma unroll
            for (int mi = 0; mi < 2; mi++) {
                const int mrow = mhalf + mi * 16;
                af[mi][0] = __float_as_uint(Am[mrow + g][kk + t]);
                af[mi][1] = __float_as_uint(Am[mrow + g + 8][kk + t]);
                af[mi][2] = __float_as_uint(Am[mrow + g][kk + t + 4]);
                af[mi][3] = __float_as_uint(Am[mrow + g + 8][kk + t + 4]);
            }
            #pragma unroll
            for (int ni = 0; ni < 8; ni++) {
                bf[ni][0] = __float_as_uint(Bm[ni * 8 + g][kk + t]);
                bf[ni][1] = __float_as_uint(Bm[ni * 8 + g][kk + t + 4]);
            }
            #pragma unroll
            for (int mi = 0; mi < 2; mi++)
                #pragma unroll
                for (int ni = 0; ni < 8; ni++)
                    mma_tf32_16x8x8(acc[mi][ni][0], acc[mi][ni][1],
                                    acc[mi][ni][2], acc[mi][ni][3],
                                    af[mi][0], af[mi][1], af[mi][2], af[mi][3],
                                    bf[ni][0], bf[ni][1]);
        }
        #pragma unroll
        for (int j = 0; j < 4; j++) v[j] = vn[j];
    }

    float* outp = g_mpart + ((size_t)(ch * BH + bh) * 3 + o) * 4096;
    #pragma unroll
    for (int mi = 0; mi < 2; mi++) {
        #pragma unroll
        for (int ni = 0; ni < 8; ni++) {
            const int row = mhalf + mi * 16 + g;
            const int col = ni * 8 + 2 * t;
            *(float2*)(outp + row * 64 + col) =
                make_float2(acc[mi][ni][0], acc[mi][ni][1]);
            *(float2*)(outp + (row + 8) * 64 + col) =
                make_float2(acc[mi][ni][2], acc[mi][ni][3]);
        }
    }
}

// ---------------------------------------------------------------------------
// Parallel reduce of g_mpart over MCH chunks -> g_msum
// ---------------------------------------------------------------------------
#define RED_F4 (BH * 3 * DHEAD * DHEAD / 4)   // 73728

__global__ void __launch_bounds__(256) reduce_mpart_kernel()
{
    const int f4 = blockIdx.x * 256 + threadIdx.x;
    if (f4 >= RED_F4) return;
    const int elem = f4 * 4;
    const int bh_o = elem >> 12;
    const int bh   = bh_o / 3;
    const int o    = bh_o - bh * 3;
    const int i    = elem & 4095;

    float4 s = make_float4(0, 0, 0, 0);
    #pragma unroll
    for (int ch = 0; ch < MCH; ch++) {
        const float4 v = *(const float4*)(
            g_mpart + ((size_t)(ch * BH + bh) * 3 + o) * 4096 + i);
        s.x += v.x; s.y += v.y; s.z += v.z; s.w += v.w;
    }
    *(float4*)(g_msum + (size_t)bh_o * 4096 + i) = s;
}

// ---------------------------------------------------------------------------
// Small combine: Mc = STEP*(SCALE*M2 - SCALE^2*M3@M1)
// ---------------------------------------------------------------------------
__global__ void __launch_bounds__(256) combine_small_kernel()
{
    const int bh  = blockIdx.x;
    const int tid = threadIdx.x;
    __shared__ float m1s[4096];
    __shared__ float m3s[4096];

    const float* src = g_msum + (size_t)bh * 3 * 4096;
    #pragma unroll
    for (int i = 0; i < 4; i++) {
        const int o4 = tid + i * 256;
        ((float4*)m1s)[o4] = ((const float4*)src)[o4];
        ((float4*)m3s)[o4] = ((const float4*)(src + 8192))[o4];
    }
    __syncthreads();

    const int tr = tid >> 4, tc = tid & 15;
    float p[4][4];
    #pragma unroll
    for (int i = 0; i < 4; i++)
        #pragma unroll
        for (int j = 0; j < 4; j++) p[i][j] = 0.f;

    for (int e = 0; e < 64; e++) {
        float a[4], bb[4];
        #pragma unroll
        for (int i = 0; i < 4; i++) a[i] = m3s[(tr * 4 + i) * 64 + e];
        #pragma unroll
        for (int j = 0; j < 4; j++) bb[j] = m1s[e * 64 + tc * 4 + j];
        #pragma unroll
        for (int i = 0; i < 4; i++)
            #pragma unroll
            for (int j = 0; j < 4; j++) p[i][j] += a[i] * bb[j];
    }

    const float c1 = STEP_F * SCALE_F;
    const float c2 = STEP_F * SCALE_F * SCALE_F;
    const float* m2p = src + 4096;
    #pragma unroll
    for (int i = 0; i < 4; i++)
        #pragma unroll
        for (int j = 0; j < 4; j++) {
            const int idx = (tr * 4 + i) * 64 + (tc * 4 + j);
            g_mc[(size_t)bh * 4096 + idx] = c1 * m2p[idx] - c2 * p[i][j];
        }
}

// ---------------------------------------------------------------------------
// outhead via tf32 mma with FUSED K-normalization. Output: fp16 K-permuted
// (16-wide perm) half2 stores into g_aoh for GEMM2.
// ---------------------------------------------------------------------------
#define OH_KPITCH   68
#define OH_KS_FL    (128 * OH_KPITCH)
#define OH_MC_FL    (64 * OH_KPITCH)
#define OH_SMEM_BYTES ((OH_KS_FL + OH_MC_FL) * 4)   // 52224

__global__ void __launch_bounds__(128) outhead_mma_kernel()
{
    extern __shared__ float osm[];
    float* Ks  = osm;
    float* McT = osm + OH_KS_FL;

    const int bh   = blockIdx.y;
    const int tile = blockIdx.x;
    const int b = bh / HEADS_H, h = bh % HEADS_H;
    const int tid  = threadIdx.x;
    const int wid  = tid >> 5;
    const int lane = tid & 31;
    const int g    = lane >> 2;
    const int t    = lane & 3;
    const int n0   = tile * 128;

    {
        const int d1  = tid >> 1;
        const int d2g = (tid & 1) * 32;
        const float* src = g_mc + (size_t)bh * 4096 + d1 * 64 + d2g;
        #pragma unroll
        for (int j = 0; j < 8; j++) {
            float4 v = *(const float4*)(src + j * 4);
            McT[(d2g + j * 4 + 0) * OH_KPITCH + d1] = rtf(v.x);
            McT[(d2g + j * 4 + 1) * OH_KPITCH + d1] = rtf(v.y);
            McT[(d2g + j * 4 + 2) * OH_KPITCH + d1] = rtf(v.z);
            McT[(d2g + j * 4 + 3) * OH_KPITCH + d1] = rtf(v.w);
        }
    }
    {
        const float* src = g_qkv + (size_t)(b * NSEQ + n0 + tid) * C3 + 768 + h * 64;
        float4 kv[16];
        float ss = 0.f;
        #pragma unroll
        for (int j = 0; j < 16; j++) {
            kv[j] = *(const float4*)(src + j * 4);
            ss += kv[j].x * kv[j].x + kv[j].y * kv[j].y
                + kv[j].z * kv[j].z + kv[j].w * kv[j].w;
        }
        const float inv = 1.0f / fmaxf(sqrtf(ss), EPS_F);
        #pragma unroll
        for (int j = 0; j < 16; j++) {
            Ks[tid * OH_KPITCH + j * 4 + 0] = rtf(kv[j].x * inv);
            Ks[tid * OH_KPITCH + j * 4 + 1] = rtf(kv[j].y * inv);
            Ks[tid * OH_KPITCH + j * 4 + 2] = rtf(kv[j].z * inv);
            Ks[tid * OH_KPITCH + j * 4 + 3] = rtf(kv[j].w * inv);
        }
    }
    __syncthreads();

    const int mrow0 = wid * 32;
    float acc[2][8][4];
    #pragma unroll
    for (int mi = 0; mi < 2; mi++)
        #pragma unroll
        for (int ni = 0; ni < 8; ni++)
            #pragma unroll
            for (int c = 0; c < 4; c++) acc[mi][ni][c] = 0.0f;

    #pragma unroll
    for (int kk = 0; kk < 64; kk += 8) {
        uint32_t af[2][4], bf[8][2];
        #pragma unroll
        for (int mi = 0; mi < 2; mi++) {
            const int mrow = mrow0 + mi * 16;
            af[mi][0] = __float_as_uint(Ks[(mrow + g)     * OH_KPITCH + kk + t]);
            af[mi][1] = __float_as_uint(Ks[(mrow + g + 8) * OH_KPITCH + kk + t]);
            af[mi][2] = __float_as_uint(Ks[(mrow + g)     * OH_KPITCH + kk + t + 4]);
            af[mi][3] = __float_as_uint(Ks[(mrow + g + 8) * OH_KPITCH + kk + t + 4]);
        }
        #pragma unroll
        for (int ni = 0; ni < 8; ni++) {
            bf[ni][0] = __float_as_uint(McT[(ni * 8 + g) * OH_KPITCH + kk + t]);
            bf[ni][1] = __float_as_uint(McT[(ni * 8 + g) * OH_KPITCH + kk + t + 4]);
        }
        #pragma unroll
        for (int mi = 0; mi < 2; mi++)
            #pragma unroll
            for (int ni = 0; ni < 8; ni++)
                mma_tf32_16x8x8(acc[mi][ni][0], acc[mi][ni][1],
                                acc[mi][ni][2], acc[mi][ni][3],
                                af[mi][0], af[mi][1], af[mi][2], af[mi][3],
                                bf[ni][0], bf[ni][1]);
    }

    const float cadd = -STEP_F * LAMBD_F;
    #pragma unroll
    for (int mi = 0; mi < 2; mi++) {
        #pragma unroll
        for (int ni = 0; ni < 8; ni++) {
            const int d0 = ni * 8 + 2 * t;       // even
            // fp16 16-wide K-permutation position (c even -> pair contiguous)
            const int c16 = d0 & 15;
            const int pos = (d0 & ~15) + 4 * ((c16 & 7) >> 1) + 2 * (c16 >> 3);
            #pragma unroll
            for (int half = 0; half < 2; half++) {
                const int tok = b * NSEQ + n0 + mrow0 + mi * 16 + g + half * 8;
                const float2 v = *(const float2*)(
                    g_qkv + (size_t)tok * C3 + 1536 + h * 64 + d0);
                const float r0 = fmaxf(v.x + acc[mi][ni][half * 2 + 0] + cadd, 0.0f);
                const float r1 = fmaxf(v.y + acc[mi][ni][half * 2 + 1] + cadd, 0.0f);
                __half2* dst = (__half2*)(g_aoh + (size_t)tok * CDIM + h * 64 + pos);
                *dst = __floats2half2_rn(r0, r1);
            }
        }
    }
}

// ---------------------------------------------------------------------------
extern "C" void kernel_launch(void* const* d_in, const int* in_sizes, int n_in,
                              void* d_out, int out_size)
{
    const float* x     = (const float*)d_in[0];
    const float* Wqkv  = (const float*)d_in[1];
    const float* Wproj = (const float*)d_in[2];
    const float* bproj = (const float*)d_in[3];
    float* out = (float*)d_out;

    float*  qkv; cudaGetSymbolAddress((void**)&qkv, g_qkv);
    __half* aoh; cudaGetSymbolAddress((void**)&aoh, g_aoh);
    __half* xh;  cudaGetSymbolAddress((void**)&xh,  g_xh);
    __half* wqh; cudaGetSymbolAddress((void**)&wqh, g_wqkvh);
    __half* wph; cudaGetSymbolAddress((void**)&wph, g_wprojh);

    cudaFuncSetAttribute(gemm_f16_pipe,
                         cudaFuncAttributeMaxDynamicSharedMemorySize, HGSMEM);
    cudaFuncSetAttribute(outhead_mma_kernel,
                         cudaFuncAttributeMaxDynamicSharedMemorySize,
                         OH_SMEM_BYTES);

    // 0. Convert + K-permute all GEMM operands to fp16
    round_perm_kernel<<<(HG3 + 255) / 256, 256>>>(x, Wqkv, Wproj);

    // 1. qkv = x @ Wqkv^T  (fp16 MMA, fp32 accum)
    gemm_f16_pipe<<<dim3(C3 / 128, TOKENS / 128), 128, HGSMEM>>>(
        xh, wqh, nullptr, qkv, TOKENS, C3, CDIM);
    // 2. Per-head moments (tf32 mma, fused q/k normalization)
    moments_mma_kernel<<<dim3(BH, MCH), 192>>>();
    // 3a. Parallel reduce of chunk partials
    reduce_mpart_kernel<<<(RED_F4 + 255) / 256, 256>>>();
    // 3b. Mc = STEP*(SCALE*M2 - SCALE^2 * M3@M1)
    combine_small_kernel<<<BH, 256>>>();
    // 4. relu(V + norm(K)@Mc - STEP*LAMBD), fp16 K-permuted output
    outhead_mma_kernel<<<dim3(NSEQ / 128, BH), 128, OH_SMEM_BYTES>>>();
    // 5. out = ao @ Wproj^T + bproj  (fp16 MMA)
    gemm_f16_pipe<<<dim3(CDIM / 128, TOKENS / 128), 128, HGSMEM>>>(
        aoh, wph, bproj, out, TOKENS, CDIM, CDIM);
}

// round 12
// speedup vs baseline: 4.5221x; 1.0133x over previous
#include <cuda_runtime.h>
#include <cuda_fp16.h>
#include <cstdint>
#include <math.h>

// Problem constants
#define BATCH   2
#define NSEQ    2048
#define CDIM    768
#define HEADS_H 12
#define DHEAD   64
#define TOKENS  (BATCH * NSEQ)          // 4096
#define C3      (3 * CDIM)              // 2304
#define BH      (BATCH * HEADS_H)       // 24
#define MCH     16                      // moments token-split chunks

#define SCALE_F 0.125f
#define STEP_F  0.1f
#define LAMBD_F 0.5f
#define EPS_F   1e-12f

// Scratch (static device globals — no allocation)
__device__ __half g_qkvh[TOKENS * C3];  // qkv in fp16 (raw; norm fused downstream)
__device__ float  g_mpart[MCH * BH * 3 * DHEAD * DHEAD];
__device__ float  g_msum[BH * 3 * DHEAD * DHEAD];
__device__ float  g_mc[BH * DHEAD * DHEAD];
__device__ __half g_aoh[TOKENS * CDIM];     // fp16, K-permuted
__device__ __half g_xh[TOKENS * CDIM];      // fp16, K-permuted
__device__ __half g_wqkvh[C3 * CDIM];
__device__ __half g_wprojh[CDIM * CDIM];

__device__ __forceinline__ uint32_t f2tf32(float f) {
    uint32_t u;
    asm("cvt.rna.tf32.f32 %0, %1;" : "=r"(u) : "f"(f));
    return u;
}
__device__ __forceinline__ float rtf(float f) {
    return __uint_as_float(f2tf32(f));
}
__device__ __forceinline__ uint32_t smem_u32(const void* p) {
    uint32_t a;
    asm("{ .reg .u64 t; cvta.to.shared.u64 t, %1; cvt.u32.u64 %0, t; }"
        : "=r"(a) : "l"(p));
    return a;
}
__device__ __forceinline__ uint32_t h2u(float a, float b) {
    __half2 h = __floats2half2_rn(a, b);
    return *reinterpret_cast<uint32_t*>(&h);
}
__device__ __forceinline__ float2 u2f2(uint32_t u) {
    return __half22float2(*reinterpret_cast<__half2*>(&u));
}

// fp16 m16n8k16 MMA, fp32 accumulate
__device__ __forceinline__ void mma_f16_16x8x16(
    float& c0, float& c1, float& c2, float& c3,
    uint32_t a0, uint32_t a1, uint32_t a2, uint32_t a3,
    uint32_t b0, uint32_t b1)
{
    asm volatile(
        "mma.sync.aligned.m16n8k16.row.col.f32.f16.f16.f32 "
        "{%0,%1,%2,%3}, {%4,%5,%6,%7}, {%8,%9}, {%0,%1,%2,%3};"
        : "+f"(c0), "+f"(c1), "+f"(c2), "+f"(c3)
        : "r"(a0), "r"(a1), "r"(a2), "r"(a3), "r"(b0), "r"(b1));
}
// tf32 m16n8k8 MMA (moments/outhead path)
__device__ __forceinline__ void mma_tf32_16x8x8(
    float& c0, float& c1, float& c2, float& c3,
    uint32_t a0, uint32_t a1, uint32_t a2, uint32_t a3,
    uint32_t b0, uint32_t b1)
{
    asm volatile(
        "mma.sync.aligned.m16n8k8.row.col.f32.tf32.tf32.f32 "
        "{%0,%1,%2,%3}, {%4,%5,%6,%7}, {%8,%9}, {%0,%1,%2,%3};"
        : "+f"(c0), "+f"(c1), "+f"(c2), "+f"(c3)
        : "r"(a0), "r"(a1), "r"(a2), "r"(a3), "r"(b0), "r"(b1));
}

// ---------------------------------------------------------------------------
// Fused fp32->fp16 convert + 16-wide K-permute for x, Wqkv, Wproj.
// Output order per 16-group: [0,1,8,9,2,3,10,11,4,5,12,13,6,7,14,15]
// ---------------------------------------------------------------------------
#define HG1 (TOKENS * CDIM / 16)             // 196608
#define HG2 (HG1 + C3 * CDIM / 16)           // 307200
#define HG3 (HG2 + CDIM * CDIM / 16)         // 344064

__global__ void __launch_bounds__(256) round_perm_kernel(
    const float* __restrict__ x, const float* __restrict__ wq,
    const float* __restrict__ wp)
{
    const int gidx = blockIdx.x * 256 + threadIdx.x;
    const float* src; __half* dst; int off;
    if (gidx < HG1)      { src = x;  dst = g_xh;     off = gidx; }
    else if (gidx < HG2) { src = wq; dst = g_wqkvh;  off = gidx - HG1; }
    else if (gidx < HG3) { src = wp; dst = g_wprojh; off = gidx - HG2; }
    else return;

    const float4* s4 = (const float4*)(src) + off * 4;
    const float4 f0 = s4[0];
    const float4 f1 = s4[1];
    const float4 f2 = s4[2];
    const float4 f3 = s4[3];

    uint4 u0, u1;
    u0.x = h2u(f0.x, f0.y);  u0.y = h2u(f2.x, f2.y);
    u0.z = h2u(f0.z, f0.w);  u0.w = h2u(f2.z, f2.w);
    u1.x = h2u(f1.x, f1.y);  u1.y = h2u(f3.x, f3.y);
    u1.z = h2u(f1.z, f1.w);  u1.w = h2u(f3.z, f3.w);
    uint4* d4 = (uint4*)(dst + (size_t)off * 16);
    d4[0] = u0;
    d4[1] = u1;
}

// ---------------------------------------------------------------------------
// fp16 mma.sync NT GEMM, cp.async 4-stage pipeline, K-PERMUTED fp16 operands.
// CTA 128x128, 4 warps, warp tile 64x64, K-chunk 32, pitch 48 halves.
// HOUT=true: write fp16 (no bias). HOUT=false: write fp32 (+bias).
// ---------------------------------------------------------------------------
#define HP        48
#define HSTAGES   4
#define HSTG_B    (128 * HP * 2)
#define HGSMEM    (HSTAGES * HSTG_B * 2)      // 98304

template<bool HOUT>
__global__ void __launch_bounds__(128, 2) gemm_f16_pipe(
    const __half* __restrict__ A, const __half* __restrict__ Bw,
    const float* __restrict__ bias, void* __restrict__ Cv,
    int M, int N, int K)
{
    extern __shared__ __half hsm[];
    __half* As = hsm;
    __half* Bs = hsm + HSTAGES * 128 * HP;

    const int tid  = threadIdx.x;
    const int wid  = tid >> 5;
    const int lane = tid & 31;
    const int g    = lane >> 2;
    const int t    = lane & 3;
    const int row0 = blockIdx.y * 128;
    const int col0 = blockIdx.x * 128;
    const int wm0  = (wid >> 1) * 64;
    const int wn0  = (wid & 1) * 64;

    float acc[4][8][4];
    #pragma unroll
    for (int mi = 0; mi < 4; mi++)
        #pragma unroll
        for (int ni = 0; ni < 8; ni++)
            #pragma unroll
            for (int c = 0; c < 4; c++) acc[mi][ni][c] = 0.0f;

    const int lrow = tid >> 2;            // 0..31
    const int lseg = (tid & 3) << 3;      // 0,8,16,24 halves

    const __half* aptr = A  + (size_t)(row0 + lrow) * K + lseg;
    const __half* bptr = Bw + (size_t)(col0 + lrow) * K + lseg;
    const uint32_t a_sb = smem_u32(As) + (lrow * HP + lseg) * 2;
    const uint32_t b_sb = smem_u32(Bs) + (lrow * HP + lseg) * 2;

    const int nc = K >> 5;

    #pragma unroll
    for (int s = 0; s < HSTAGES - 1; s++) {
        const int k0 = s << 5;
        #pragma unroll
        for (int i = 0; i < 4; i++) {
            const uint32_t so = s * HSTG_B + i * 32 * HP * 2;
            asm volatile("cp.async.cg.shared.global [%0], [%1], 16;"
                :: "r"(a_sb + so), "l"(aptr + (size_t)i * 32 * K + k0) : "memory");
            asm volatile("cp.async.cg.shared.global [%0], [%1], 16;"
                :: "r"(b_sb + so), "l"(bptr + (size_t)i * 32 * K + k0) : "memory");
        }
        asm volatile("cp.async.commit_group;" ::: "memory");
    }

    for (int c = 0; c < nc; c++) {
        asm volatile("cp.async.wait_group %0;" :: "n"(HSTAGES - 2) : "memory");
        __syncthreads();

        const int cn = c + HSTAGES - 1;
        if (cn < nc) {
            const int s  = cn & (HSTAGES - 1);
            const int k0 = cn << 5;
            #pragma unroll
            for (int i = 0; i < 4; i++) {
                const uint32_t so = s * HSTG_B + i * 32 * HP * 2;
                asm volatile("cp.async.cg.shared.global [%0], [%1], 16;"
                    :: "r"(a_sb + so), "l"(aptr + (size_t)i * 32 * K + k0) : "memory");
                asm volatile("cp.async.cg.shared.global [%0], [%1], 16;"
                    :: "r"(b_sb + so), "l"(bptr + (size_t)i * 32 * K + k0) : "memory");
            }
        }
        asm volatile("cp.async.commit_group;" ::: "memory");

        const __half* as = As + (c & (HSTAGES - 1)) * 128 * HP;
        const __half* bs = Bs + (c & (HSTAGES - 1)) * 128 * HP;
        #pragma unroll
        for (int kk = 0; kk < 2; kk++) {
            const int ko = kk * 16 + t * 4;
            uint32_t af[4][4], bf[8][2];
            #pragma unroll
            for (int mi = 0; mi < 4; mi++) {
                const int mrow = wm0 + mi * 16;
                const uint2 av0 = *(const uint2*)(as + (mrow + g)     * HP + ko);
                const uint2 av1 = *(const uint2*)(as + (mrow + g + 8) * HP + ko);
                af[mi][0] = av0.x; af[mi][2] = av0.y;
                af[mi][1] = av1.x; af[mi][3] = av1.y;
            }
            #pragma unroll
            for (int ni = 0; ni < 8; ni++) {
                const uint2 bv = *(const uint2*)(bs + (wn0 + ni * 8 + g) * HP + ko);
                bf[ni][0] = bv.x; bf[ni][1] = bv.y;
            }
            #pragma unroll
            for (int mi = 0; mi < 4; mi++)
                #pragma unroll
                for (int ni = 0; ni < 8; ni++)
                    mma_f16_16x8x16(acc[mi][ni][0], acc[mi][ni][1],
                                    acc[mi][ni][2], acc[mi][ni][3],
                                    af[mi][0], af[mi][1], af[mi][2], af[mi][3],
                                    bf[ni][0], bf[ni][1]);
        }
    }

    #pragma unroll
    for (int mi = 0; mi < 4; mi++) {
        #pragma unroll
        for (int ni = 0; ni < 8; ni++) {
            const int col = col0 + wn0 + ni * 8 + 2 * t;
            const int r0 = row0 + wm0 + mi * 16 + g;
            if (HOUT) {
                __half* C = (__half*)Cv;
                *(__half2*)(C + (size_t)r0 * N + col) =
                    __floats2half2_rn(acc[mi][ni][0], acc[mi][ni][1]);
                *(__half2*)(C + (size_t)(r0 + 8) * N + col) =
                    __floats2half2_rn(acc[mi][ni][2], acc[mi][ni][3]);
            } else {
                float* C = (float*)Cv;
                float b0 = 0.f, b1 = 0.f;
                if (bias) { b0 = bias[col]; b1 = bias[col + 1]; }
                *(float2*)(C + (size_t)r0 * N + col) =
                    make_float2(acc[mi][ni][0] + b0, acc[mi][ni][1] + b1);
                *(float2*)(C + (size_t)(r0 + 8) * N + col) =
                    make_float2(acc[mi][ni][2] + b0, acc[mi][ni][3] + b1);
            }
        }
    }
}

// ---------------------------------------------------------------------------
// Moments via tf32 mma with FUSED L2-normalization of q,k; fp16 qkv input.
// Per (b,h,chunk of 128 tokens): partial M1=K^T V, M2=Q^T V, M3=Q^T Q.
// grid (BH, MCH), 192 threads. Double-buffered, 1 sync/iter.
// ---------------------------------------------------------------------------
#define MTOK (NSEQ / MCH)                // 128 tokens per chunk
#define MNIT (MTOK / 16)                 // 8 iters of 16 tokens

__global__ void __launch_bounds__(192) moments_mma_kernel()
{
    __shared__ float QT[2][64][17];
    __shared__ float KT[2][64][17];
    __shared__ float VT[2][64][17];

    const int bh = blockIdx.x;
    const int ch = blockIdx.y;
    const int b = bh / HEADS_H, h = bh % HEADS_H;
    const int tid  = threadIdx.x;
    const int wid  = tid >> 5;
    const int lane = tid & 31;
    const int g    = lane >> 2;
    const int t    = lane & 3;
    const int o    = wid >> 1;
    const int mhalf = (wid & 1) * 32;

    const int mat  = tid >> 6;           // 0=Q,1=K,2=V
    const int idx  = tid & 63;
    const int ltok = idx >> 2;           // 0..15
    const int ldg  = (idx & 3) << 4;     // 0,16,32,48 (halves)

    const size_t base = (size_t)(b * NSEQ + ch * MTOK) * C3 + mat * 768 + h * 64;

    float acc[2][8][4];
    #pragma unroll
    for (int mi = 0; mi < 2; mi++)
        #pragma unroll
        for (int ni = 0; ni < 8; ni++)
            #pragma unroll
            for (int c = 0; c < 4; c++) acc[mi][ni][c] = 0.0f;

    uint4 ra, rb;   // 16 halves per thread
    {
        const __half* src = g_qkvh + base + (size_t)ltok * C3 + ldg;
        ra = *(const uint4*)(src);
        rb = *(const uint4*)(src + 8);
    }

    for (int it = 0; it < MNIT; it++) {
        float vals[16];
        {
            const uint32_t* u = &ra.x;
            #pragma unroll
            for (int j = 0; j < 4; j++) {
                const float2 f = u2f2(u[j]);
                vals[j * 2] = f.x; vals[j * 2 + 1] = f.y;
            }
            const uint32_t* w = &rb.x;
            #pragma unroll
            for (int j = 0; j < 4; j++) {
                const float2 f = u2f2(w[j]);
                vals[8 + j * 2] = f.x; vals[8 + j * 2 + 1] = f.y;
            }
        }
        float inv = 1.0f;
        if (mat < 2) {
            float ss = 0.f;
            #pragma unroll
            for (int j = 0; j < 16; j++) ss += vals[j] * vals[j];
            ss += __shfl_xor_sync(0xffffffffu, ss, 1);
            ss += __shfl_xor_sync(0xffffffffu, ss, 2);
            inv = 1.0f / fmaxf(sqrtf(ss), EPS_F);
        }
        {
            float (*Td)[17] = (mat == 0) ? QT[it & 1]
                            : (mat == 1) ? KT[it & 1] : VT[it & 1];
            #pragma unroll
            for (int j = 0; j < 16; j++)
                Td[ldg + j][ltok] = rtf(vals[j] * inv);
        }
        uint4 rna, rnb;
        if (it + 1 < MNIT) {
            const __half* src = g_qkvh + base + (size_t)((it + 1) * 16 + ltok) * C3 + ldg;
            rna = *(const uint4*)(src);
            rnb = *(const uint4*)(src + 8);
        }
        __syncthreads();

        const float (*Am)[17] = (o == 0) ? KT[it & 1] : QT[it & 1];
        const float (*Bm)[17] = (o == 2) ? QT[it & 1] : VT[it & 1];
        #pragma unroll
        for (int kk = 0; kk < 16; kk += 8) {
            uint32_t af[2][4], bf[8][2];
            #pragma unroll
            for (int mi = 0; mi < 2; mi++) {
                const int mrow = mhalf + mi * 16;
                af[mi][0] = __float_as_uint(Am[mrow + g][kk + t]);
                af[mi][1] = __float_as_uint(Am[mrow + g + 8][kk + t]);
                af[mi][2] = __float_as_uint(Am[mrow + g][kk + t + 4]);
                af[mi][3] = __float_as_uint(Am[mrow + g + 8][kk + t + 4]);
            }
            #pragma unroll
            for (int ni = 0; ni < 8; ni++) {
                bf[ni][0] = __float_as_uint(Bm[ni * 8 + g][kk + t]);
                bf[ni][1] = __float_as_uint(Bm[ni * 8 + g][kk + t + 4]);
            }
            #pragma unroll
            for (int mi = 0; mi < 2; mi++)
                #pragma unroll
                for (int ni = 0; ni < 8; ni++)
                    mma_tf32_16x8x8(acc[mi][ni][0], acc[mi][ni][1],
                                    acc[mi][ni][2], acc[mi][ni][3],
                                    af[mi][0], af[mi][1], af[mi][2], af[mi][3],
                                    bf[ni][0], bf[ni][1]);
        }
        ra = rna; rb = rnb;
    }

    float* outp = g_mpart + ((size_t)(ch * BH + bh) * 3 + o) * 4096;
    #pragma unroll
    for (int mi = 0; mi < 2; mi++) {
        #pragma unroll
        for (int ni = 0; ni < 8; ni++) {
            const int row = mhalf + mi * 16 + g;
            const int col = ni * 8 + 2 * t;
            *(float2*)(outp + row * 64 + col) =
                make_float2(acc[mi][ni][0], acc[mi][ni][1]);
            *(float2*)(outp + (row + 8) * 64 + col) =
                make_float2(acc[mi][ni][2], acc[mi][ni][3]);
        }
    }
}

// ---------------------------------------------------------------------------
// Parallel reduce of g_mpart over MCH chunks -> g_msum
// ---------------------------------------------------------------------------
#define RED_F4 (BH * 3 * DHEAD * DHEAD / 4)   // 73728

__global__ void __launch_bounds__(256) reduce_mpart_kernel()
{
    const int f4 = blockIdx.x * 256 + threadIdx.x;
    if (f4 >= RED_F4) return;
    const int elem = f4 * 4;
    const int bh_o = elem >> 12;
    const int bh   = bh_o / 3;
    const int o    = bh_o - bh * 3;
    const int i    = elem & 4095;

    float4 s = make_float4(0, 0, 0, 0);
    #pragma unroll
    for (int ch = 0; ch < MCH; ch++) {
        const float4 v = *(const float4*)(
            g_mpart + ((size_t)(ch * BH + bh) * 3 + o) * 4096 + i);
        s.x += v.x; s.y += v.y; s.z += v.z; s.w += v.w;
    }
    *(float4*)(g_msum + (size_t)bh_o * 4096 + i) = s;
}

// ---------------------------------------------------------------------------
// Small combine: Mc = STEP*(SCALE*M2 - SCALE^2*M3@M1)
// ---------------------------------------------------------------------------
__global__ void __launch_bounds__(256) combine_small_kernel()
{
    const int bh  = blockIdx.x;
    const int tid = threadIdx.x;
    __shared__ float m1s[4096];
    __shared__ float m3s[4096];

    const float* src = g_msum + (size_t)bh * 3 * 4096;
    #pragma unroll
    for (int i = 0; i < 4; i++) {
        const int o4 = tid + i * 256;
        ((float4*)m1s)[o4] = ((const float4*)src)[o4];
        ((float4*)m3s)[o4] = ((const float4*)(src + 8192))[o4];
    }
    __syncthreads();

    const int tr = tid >> 4, tc = tid & 15;
    float p[4][4];
    #pragma unroll
    for (int i = 0; i < 4; i++)
        #pragma unroll
        for (int j = 0; j < 4; j++) p[i][j] = 0.f;

    for (int e = 0; e < 64; e++) {
        float a[4], bb[4];
        #pragma unroll
        for (int i = 0; i < 4; i++) a[i] = m3s[(tr * 4 + i) * 64 + e];
        #pragma unroll
        for (int j = 0; j < 4; j++) bb[j] = m1s[e * 64 + tc * 4 + j];
        #pragma unroll
        for (int i = 0; i < 4; i++)
            #pragma unroll
            for (int j = 0; j < 4; j++) p[i][j] += a[i] * bb[j];
    }

    const float c1 = STEP_F * SCALE_F;
    const float c2 = STEP_F * SCALE_F * SCALE_F;
    const float* m2p = src + 4096;
    #pragma unroll
    for (int i = 0; i < 4; i++)
        #pragma unroll
        for (int j = 0; j < 4; j++) {
            const int idx = (tr * 4 + i) * 64 + (tc * 4 + j);
            g_mc[(size_t)bh * 4096 + idx] = c1 * m2p[idx] - c2 * p[i][j];
        }
}

// ---------------------------------------------------------------------------
// outhead via tf32 mma with FUSED K-normalization; fp16 qkv input.
// Output: fp16 K-permuted (16-wide perm) half2 stores into g_aoh.
// ---------------------------------------------------------------------------
#define OH_KPITCH   68
#define OH_KS_FL    (128 * OH_KPITCH)
#define OH_MC_FL    (64 * OH_KPITCH)
#define OH_SMEM_BYTES ((OH_KS_FL + OH_MC_FL) * 4)   // 52224

__global__ void __launch_bounds__(128) outhead_mma_kernel()
{
    extern __shared__ float osm[];
    float* Ks  = osm;
    float* McT = osm + OH_KS_FL;

    const int bh   = blockIdx.y;
    const int tile = blockIdx.x;
    const int b = bh / HEADS_H, h = bh % HEADS_H;
    const int tid  = threadIdx.x;
    const int wid  = tid >> 5;
    const int lane = tid & 31;
    const int g    = lane >> 2;
    const int t    = lane & 3;
    const int n0   = tile * 128;

    {
        const int d1  = tid >> 1;
        const int d2g = (tid & 1) * 32;
        const float* src = g_mc + (size_t)bh * 4096 + d1 * 64 + d2g;
        #pragma unroll
        for (int j = 0; j < 8; j++) {
            float4 v = *(const float4*)(src + j * 4);
            McT[(d2g + j * 4 + 0) * OH_KPITCH + d1] = rtf(v.x);
            McT[(d2g + j * 4 + 1) * OH_KPITCH + d1] = rtf(v.y);
            McT[(d2g + j * 4 + 2) * OH_KPITCH + d1] = rtf(v.z);
            McT[(d2g + j * 4 + 3) * OH_KPITCH + d1] = rtf(v.w);
        }
    }
    {
        // one full fp16 K row per thread: 8 x LDG.128, in-register norm
        const __half* src = g_qkvh + (size_t)(b * NSEQ + n0 + tid) * C3 + 768 + h * 64;
        float kv[64];
        float ss = 0.f;
        #pragma unroll
        for (int j = 0; j < 8; j++) {
            const uint4 r = *(const uint4*)(src + j * 8);
            const uint32_t* u = &r.x;
            #pragma unroll
            for (int q = 0; q < 4; q++) {
                const float2 f = u2f2(u[q]);
                kv[j * 8 + q * 2]     = f.x;
                kv[j * 8 + q * 2 + 1] = f.y;
                ss += f.x * f.x + f.y * f.y;
            }
        }
        const float inv = 1.0f / fmaxf(sqrtf(ss), EPS_F);
        #pragma unroll
        for (int j = 0; j < 64; j++)
            Ks[tid * OH_KPITCH + j] = rtf(kv[j] * inv);
    }
    __syncthreads();

    const int mrow0 = wid * 32;
    float acc[2][8][4];
    #pragma unroll
    for (int mi = 0; mi < 2; mi++)
        #pragma unroll
        for (int ni = 0; ni < 8; ni++)
            #pragma unroll
            for (int c = 0; c < 4; c++) acc[mi][ni][c] = 0.0f;

    #pragma unroll
    for (int kk = 0; kk < 64; kk += 8) {
        uint32_t af[2][4], bf[8][2];
        #pragma unroll
        for (int mi = 0; mi < 2; mi++) {
            const int mrow = mrow0 + mi * 16;
            af[mi][0] = __float_as_uint(Ks[(mrow + g)     * OH_KPITCH + kk + t]);
            af[mi][1] = __float_as_uint(Ks[(mrow + g + 8) * OH_KPITCH + kk + t]);
            af[mi][2] = __float_as_uint(Ks[(mrow + g)     * OH_KPITCH + kk + t + 4]);
            af[mi][3] = __float_as_uint(Ks[(mrow + g + 8) * OH_KPITCH + kk + t + 4]);
        }
        #pragma unroll
        for (int ni = 0; ni < 8; ni++) {
            bf[ni][0] = __float_as_uint(McT[(ni * 8 + g) * OH_KPITCH + kk + t]);
            bf[ni][1] = __float_as_uint(McT[(ni * 8 + g) * OH_KPITCH + kk + t + 4]);
        }
        #pragma unroll
        for (int mi = 0; mi < 2; mi++)
            #pragma unroll
            for (int ni = 0; ni < 8; ni++)
                mma_tf32_16x8x8(acc[mi][ni][0], acc[mi][ni][1],
                                acc[mi][ni][2], acc[mi][ni][3],
                                af[mi][0], af[mi][1], af[mi][2], af[mi][3],
                                bf[ni][0], bf[ni][1]);
    }

    const float cadd = -STEP_F * LAMBD_F;
    #pragma unroll
    for (int mi = 0; mi < 2; mi++) {
        #pragma unroll
        for (int ni = 0; ni < 8; ni++) {
            const int d0 = ni * 8 + 2 * t;       // even
            const int c16 = d0 & 15;
            const int pos = (d0 & ~15) + 4 * ((c16 & 7) >> 1) + 2 * (c16 >> 3);
            #pragma unroll
            for (int half = 0; half < 2; half++) {
                const int tok = b * NSEQ + n0 + mrow0 + mi * 16 + g + half * 8;
                const __half2 vh = *(const __half2*)(
                    g_qkvh + (size_t)tok * C3 + 1536 + h * 64 + d0);
                const float2 v = __half22float2(vh);
                const float r0 = fmaxf(v.x + acc[mi][ni][half * 2 + 0] + cadd, 0.0f);
                const float r1 = fmaxf(v.y + acc[mi][ni][half * 2 + 1] + cadd, 0.0f);
                __half2* dst = (__half2*)(g_aoh + (size_t)tok * CDIM + h * 64 + pos);
                *dst = __floats2half2_rn(r0, r1);
            }
        }
    }
}

// ---------------------------------------------------------------------------
extern "C" void kernel_launch(void* const* d_in, const int* in_sizes, int n_in,
                              void* d_out, int out_size)
{
    const float* x     = (const float*)d_in[0];
    const float* Wqkv  = (const float*)d_in[1];
    const float* Wproj = (const float*)d_in[2];
    const float* bproj = (const float*)d_in[3];
    float* out = (float*)d_out;

    __half* qkvh; cudaGetSymbolAddress((void**)&qkvh, g_qkvh);
    __half* aoh;  cudaGetSymbolAddress((void**)&aoh,  g_aoh);
    __half* xh;   cudaGetSymbolAddress((void**)&xh,   g_xh);
    __half* wqh;  cudaGetSymbolAddress((void**)&wqh,  g_wqkvh);
    __half* wph;  cudaGetSymbolAddress((void**)&wph,  g_wprojh);

    cudaFuncSetAttribute(gemm_f16_pipe<true>,
                         cudaFuncAttributeMaxDynamicSharedMemorySize, HGSMEM);
    cudaFuncSetAttribute(gemm_f16_pipe<false>,
                         cudaFuncAttributeMaxDynamicSharedMemorySize, HGSMEM);
    cudaFuncSetAttribute(outhead_mma_kernel,
                         cudaFuncAttributeMaxDynamicSharedMemorySize,
                         OH_SMEM_BYTES);

    // 0. Convert + K-permute all GEMM operands to fp16
    round_perm_kernel<<<(HG3 + 255) / 256, 256>>>(x, Wqkv, Wproj);

    // 1. qkv = x @ Wqkv^T  (fp16 MMA, fp16 output)
    gemm_f16_pipe<true><<<dim3(C3 / 128, TOKENS / 128), 128, HGSMEM>>>(
        xh, wqh, nullptr, qkvh, TOKENS, C3, CDIM);
    // 2. Per-head moments (tf32 mma, fused q/k normalization, fp16 input)
    moments_mma_kernel<<<dim3(BH, MCH), 192>>>();
    // 3a. Parallel reduce of chunk partials
    reduce_mpart_kernel<<<(RED_F4 + 255) / 256, 256>>>();
    // 3b. Mc = STEP*(SCALE*M2 - SCALE^2 * M3@M1)
    combine_small_kernel<<<BH, 256>>>();
    // 4. relu(V + norm(K)@Mc - STEP*LAMBD), fp16 K-permuted output
    outhead_mma_kernel<<<dim3(NSEQ / 128, BH), 128, OH_SMEM_BYTES>>>();
    // 5. out = ao @ Wproj^T + bproj  (fp16 MMA, fp32 output)
    gemm_f16_pipe<false><<<dim3(CDIM / 128, TOKENS / 128), 128, HGSMEM>>>(
        aoh, wph, bproj, out, TOKENS, CDIM, CDIM);
}

// round 13
// speedup vs baseline: 4.9495x; 1.0945x over previous
#include <cuda_runtime.h>
#include <cuda_fp16.h>
#include <cstdint>
#include <math.h>

// Problem constants
#define BATCH   2
#define NSEQ    2048
#define CDIM    768
#define HEADS_H 12
#define DHEAD   64
#define TOKENS  (BATCH * NSEQ)          // 4096
#define C3      (3 * CDIM)              // 2304
#define BH      (BATCH * HEADS_H)       // 24
#define MCH     16                      // moments token-split chunks

#define SCALE_F 0.125f
#define STEP_F  0.1f
#define LAMBD_F 0.5f
#define EPS_F   1e-12f

// Scratch (static device globals — no allocation)
__device__ __half g_qkvh[TOKENS * C3];  // qkv in fp16 (raw; norm fused downstream)
__device__ __half g_mparth[MCH * BH * 3 * DHEAD * DHEAD];   // fp16 partials
__device__ float  g_msum[BH * 3 * DHEAD * DHEAD];
__device__ float  g_mc[BH * DHEAD * DHEAD];
__device__ __half g_aoh[TOKENS * CDIM];     // fp16, K-permuted
__device__ __half g_xh[TOKENS * CDIM];      // fp16, K-permuted
__device__ __half g_wqkvh[C3 * CDIM];
__device__ __half g_wprojh[CDIM * CDIM];

__device__ __forceinline__ uint32_t f2tf32(float f) {
    uint32_t u;
    asm("cvt.rna.tf32.f32 %0, %1;" : "=r"(u) : "f"(f));
    return u;
}
__device__ __forceinline__ float rtf(float f) {
    return __uint_as_float(f2tf32(f));
}
__device__ __forceinline__ uint32_t smem_u32(const void* p) {
    uint32_t a;
    asm("{ .reg .u64 t; cvta.to.shared.u64 t, %1; cvt.u32.u64 %0, t; }"
        : "=r"(a) : "l"(p));
    return a;
}
__device__ __forceinline__ uint32_t h2u(float a, float b) {
    __half2 h = __floats2half2_rn(a, b);
    return *reinterpret_cast<uint32_t*>(&h);
}
__device__ __forceinline__ float2 u2f2(uint32_t u) {
    return __half22float2(*reinterpret_cast<__half2*>(&u));
}
__device__ __forceinline__ void ldsm_x4_trans(
    uint32_t& r0, uint32_t& r1, uint32_t& r2, uint32_t& r3, uint32_t addr)
{
    asm volatile("ldmatrix.sync.aligned.m8n8.x4.trans.shared.b16 "
                 "{%0,%1,%2,%3}, [%4];"
                 : "=r"(r0), "=r"(r1), "=r"(r2), "=r"(r3) : "r"(addr));
}

// fp16 m16n8k16 MMA, fp32 accumulate
__device__ __forceinline__ void mma_f16_16x8x16(
    float& c0, float& c1, float& c2, float& c3,
    uint32_t a0, uint32_t a1, uint32_t a2, uint32_t a3,
    uint32_t b0, uint32_t b1)
{
    asm volatile(
        "mma.sync.aligned.m16n8k16.row.col.f32.f16.f16.f32 "
        "{%0,%1,%2,%3}, {%4,%5,%6,%7}, {%8,%9}, {%0,%1,%2,%3};"
        : "+f"(c0), "+f"(c1), "+f"(c2), "+f"(c3)
        : "r"(a0), "r"(a1), "r"(a2), "r"(a3), "r"(b0), "r"(b1));
}
// tf32 m16n8k8 MMA (outhead path)
__device__ __forceinline__ void mma_tf32_16x8x8(
    float& c0, float& c1, float& c2, float& c3,
    uint32_t a0, uint32_t a1, uint32_t a2, uint32_t a3,
    uint32_t b0, uint32_t b1)
{
    asm volatile(
        "mma.sync.aligned.m16n8k8.row.col.f32.tf32.tf32.f32 "
        "{%0,%1,%2,%3}, {%4,%5,%6,%7}, {%8,%9}, {%0,%1,%2,%3};"
        : "+f"(c0), "+f"(c1), "+f"(c2), "+f"(c3)
        : "r"(a0), "r"(a1), "r"(a2), "r"(a3), "r"(b0), "r"(b1));
}

// ---------------------------------------------------------------------------
// Fused fp32->fp16 convert + 16-wide K-permute for x, Wqkv, Wproj.
// Output order per 16-group: [0,1,8,9,2,3,10,11,4,5,12,13,6,7,14,15]
// ---------------------------------------------------------------------------
#define HG1 (TOKENS * CDIM / 16)             // 196608
#define HG2 (HG1 + C3 * CDIM / 16)           // 307200
#define HG3 (HG2 + CDIM * CDIM / 16)         // 344064

__global__ void __launch_bounds__(256) round_perm_kernel(
    const float* __restrict__ x, const float* __restrict__ wq,
    const float* __restrict__ wp)
{
    const int gidx = blockIdx.x * 256 + threadIdx.x;
    const float* src; __half* dst; int off;
    if (gidx < HG1)      { src = x;  dst = g_xh;     off = gidx; }
    else if (gidx < HG2) { src = wq; dst = g_wqkvh;  off = gidx - HG1; }
    else if (gidx < HG3) { src = wp; dst = g_wprojh; off = gidx - HG2; }
    else return;

    const float4* s4 = (const float4*)(src) + off * 4;
    const float4 f0 = s4[0];
    const float4 f1 = s4[1];
    const float4 f2 = s4[2];
    const float4 f3 = s4[3];

    uint4 u0, u1;
    u0.x = h2u(f0.x, f0.y);  u0.y = h2u(f2.x, f2.y);
    u0.z = h2u(f0.z, f0.w);  u0.w = h2u(f2.z, f2.w);
    u1.x = h2u(f1.x, f1.y);  u1.y = h2u(f3.x, f3.y);
    u1.z = h2u(f1.z, f1.w);  u1.w = h2u(f3.z, f3.w);
    uint4* d4 = (uint4*)(dst + (size_t)off * 16);
    d4[0] = u0;
    d4[1] = u1;
}

// ---------------------------------------------------------------------------
// fp16 mma.sync NT GEMM, cp.async 4-stage pipeline, K-PERMUTED fp16 operands.
// CTA 128x128, 4 warps, warp tile 64x64, K-chunk 32, pitch 48 halves.
// HOUT=true: write fp16 (no bias). HOUT=false: write fp32 (+bias).
// ---------------------------------------------------------------------------
#define HP        48
#define HSTAGES   4
#define HSTG_B    (128 * HP * 2)
#define HGSMEM    (HSTAGES * HSTG_B * 2)      // 98304

template<bool HOUT>
__global__ void __launch_bounds__(128, 2) gemm_f16_pipe(
    const __half* __restrict__ A, const __half* __restrict__ Bw,
    const float* __restrict__ bias, void* __restrict__ Cv,
    int M, int N, int K)
{
    extern __shared__ __half hsm[];
    __half* As = hsm;
    __half* Bs = hsm + HSTAGES * 128 * HP;

    const int tid  = threadIdx.x;
    const int wid  = tid >> 5;
    const int lane = tid & 31;
    const int g    = lane >> 2;
    const int t    = lane & 3;
    const int row0 = blockIdx.y * 128;
    const int col0 = blockIdx.x * 128;
    const int wm0  = (wid >> 1) * 64;
    const int wn0  = (wid & 1) * 64;

    float acc[4][8][4];
    #pragma unroll
    for (int mi = 0; mi < 4; mi++)
        #pragma unroll
        for (int ni = 0; ni < 8; ni++)
            #pragma unroll
            for (int c = 0; c < 4; c++) acc[mi][ni][c] = 0.0f;

    const int lrow = tid >> 2;            // 0..31
    const int lseg = (tid & 3) << 3;      // 0,8,16,24 halves

    const __half* aptr = A  + (size_t)(row0 + lrow) * K + lseg;
    const __half* bptr = Bw + (size_t)(col0 + lrow) * K + lseg;
    const uint32_t a_sb = smem_u32(As) + (lrow * HP + lseg) * 2;
    const uint32_t b_sb = smem_u32(Bs) + (lrow * HP + lseg) * 2;

    const int nc = K >> 5;

    #pragma unroll
    for (int s = 0; s < HSTAGES - 1; s++) {
        const int k0 = s << 5;
        #pragma unroll
        for (int i = 0; i < 4; i++) {
            const uint32_t so = s * HSTG_B + i * 32 * HP * 2;
            asm volatile("cp.async.cg.shared.global [%0], [%1], 16;"
                :: "r"(a_sb + so), "l"(aptr + (size_t)i * 32 * K + k0) : "memory");
            asm volatile("cp.async.cg.shared.global [%0], [%1], 16;"
                :: "r"(b_sb + so), "l"(bptr + (size_t)i * 32 * K + k0) : "memory");
        }
        asm volatile("cp.async.commit_group;" ::: "memory");
    }

    for (int c = 0; c < nc; c++) {
        asm volatile("cp.async.wait_group %0;" :: "n"(HSTAGES - 2) : "memory");
        __syncthreads();

        const int cn = c + HSTAGES - 1;
        if (cn < nc) {
            const int s  = cn & (HSTAGES - 1);
            const int k0 = cn << 5;
            #pragma unroll
            for (int i = 0; i < 4; i++) {
                const uint32_t so = s * HSTG_B + i * 32 * HP * 2;
                asm volatile("cp.async.cg.shared.global [%0], [%1], 16;"
                    :: "r"(a_sb + so), "l"(aptr + (size_t)i * 32 * K + k0) : "memory");
                asm volatile("cp.async.cg.shared.global [%0], [%1], 16;"
                    :: "r"(b_sb + so), "l"(bptr + (size_t)i * 32 * K + k0) : "memory");
            }
        }
        asm volatile("cp.async.commit_group;" ::: "memory");

        const __half* as = As + (c & (HSTAGES - 1)) * 128 * HP;
        const __half* bs = Bs + (c & (HSTAGES - 1)) * 128 * HP;
        #pragma unroll
        for (int kk = 0; kk < 2; kk++) {
            const int ko = kk * 16 + t * 4;
            uint32_t af[4][4], bf[8][2];
            #pragma unroll
            for (int mi = 0; mi < 4; mi++) {
                const int mrow = wm0 + mi * 16;
                const uint2 av0 = *(const uint2*)(as + (mrow + g)     * HP + ko);
                const uint2 av1 = *(const uint2*)(as + (mrow + g + 8) * HP + ko);
                af[mi][0] = av0.x; af[mi][2] = av0.y;
                af[mi][1] = av1.x; af[mi][3] = av1.y;
            }
            #pragma unroll
            for (int ni = 0; ni < 8; ni++) {
                const uint2 bv = *(const uint2*)(bs + (wn0 + ni * 8 + g) * HP + ko);
                bf[ni][0] = bv.x; bf[ni][1] = bv.y;
            }
            #pragma unroll
            for (int mi = 0; mi < 4; mi++)
                #pragma unroll
                for (int ni = 0; ni < 8; ni++)
                    mma_f16_16x8x16(acc[mi][ni][0], acc[mi][ni][1],
                                    acc[mi][ni][2], acc[mi][ni][3],
                                    af[mi][0], af[mi][1], af[mi][2], af[mi][3],
                                    bf[ni][0], bf[ni][1]);
        }
    }

    #pragma unroll
    for (int mi = 0; mi < 4; mi++) {
        #pragma unroll
        for (int ni = 0; ni < 8; ni++) {
            const int col = col0 + wn0 + ni * 8 + 2 * t;
            const int r0 = row0 + wm0 + mi * 16 + g;
            if (HOUT) {
                __half* C = (__half*)Cv;
                *(__half2*)(C + (size_t)r0 * N + col) =
                    __floats2half2_rn(acc[mi][ni][0], acc[mi][ni][1]);
                *(__half2*)(C + (size_t)(r0 + 8) * N + col) =
                    __floats2half2_rn(acc[mi][ni][2], acc[mi][ni][3]);
            } else {
                float* C = (float*)Cv;
                float b0 = 0.f, b1 = 0.f;
                if (bias) { b0 = bias[col]; b1 = bias[col + 1]; }
                *(float2*)(C + (size_t)r0 * N + col) =
                    make_float2(acc[mi][ni][0] + b0, acc[mi][ni][1] + b1);
                *(float2*)(C + (size_t)(r0 + 8) * N + col) =
                    make_float2(acc[mi][ni][2] + b0, acc[mi][ni][3] + b1);
            }
        }
    }
}

// ---------------------------------------------------------------------------
// Moments via fp16 mma + ldmatrix.trans, FUSED q/k L2-normalization.
// Per (b,h,chunk of 128 tokens): partial M1=K^T V, M2=Q^T V, M3=Q^T Q.
// grid (BH, MCH), 192 threads (6 warps; warp w: output o=w>>1, m-half (w&1)*32).
// Tiles stored token-major fp16 [32 tok][72 halves]; fragments via ldmatrix.
// Partials stored fp16 to g_mparth.
// ---------------------------------------------------------------------------
#define MTOK (NSEQ / MCH)                // 128 tokens per chunk
#define MNIT (MTOK / 32)                 // 4 iters of 32 tokens
#define TPITCH 72                        // halves per smem row

__global__ void __launch_bounds__(192, 2) moments_mma_kernel()
{
    __shared__ __half TQ[2][32][TPITCH];
    __shared__ __half TK[2][32][TPITCH];
    __shared__ __half TV[2][32][TPITCH];

    const int bh = blockIdx.x;
    const int ch = blockIdx.y;
    const int b = bh / HEADS_H, h = bh % HEADS_H;
    const int tid  = threadIdx.x;
    const int wid  = tid >> 5;           // 0..5
    const int lane = tid & 31;
    const int g    = lane >> 2;
    const int t    = lane & 3;
    const int o    = wid >> 1;           // 0=M1,1=M2,2=M3
    const int mhalf = (wid & 1) * 32;

    // loader: mat = tid/64 (0=Q,1=K,2=V); trow = token row 0..31; dh half-range
    const int mat  = tid >> 6;
    const int trow = (tid & 63) >> 1;    // 0..31
    const int dh   = (tid & 1) * 32;     // 0 or 32

    const size_t base = (size_t)(b * NSEQ + ch * MTOK) * C3
                      + mat * 768 + h * 64 + dh;

    // ldmatrix lane->tile address offsets
    const int a_tok = ((lane >> 4) << 3) + (lane & 7);
    const int a_d   = ((lane >> 3) & 1) << 3;
    const int b_tok = (((lane >> 3) & 1) << 3) + (lane & 7);
    const int b_d   = (lane >> 4) << 3;

    float acc[2][8][4];
    #pragma unroll
    for (int mi = 0; mi < 2; mi++)
        #pragma unroll
        for (int ni = 0; ni < 8; ni++)
            #pragma unroll
            for (int c = 0; c < 4; c++) acc[mi][ni][c] = 0.0f;

    uint4 r[4];
    {
        const __half* src = g_qkvh + base + (size_t)trow * C3;
        #pragma unroll
        for (int j = 0; j < 4; j++) r[j] = ((const uint4*)src)[j];
    }

    for (int it = 0; it < MNIT; it++) {
        // fused L2 norm (q,k): 2 lanes hold this token's 64 halves
        float inv = 1.0f;
        if (mat < 2) {
            float ss = 0.f;
            #pragma unroll
            for (int j = 0; j < 4; j++) {
                const uint32_t* u = &r[j].x;
                #pragma unroll
                for (int q = 0; q < 4; q++) {
                    const float2 f = u2f2(u[q]);
                    ss += f.x * f.x + f.y * f.y;
                }
            }
            ss += __shfl_xor_sync(0xffffffffu, ss, 1);
            inv = 1.0f / fmaxf(sqrtf(ss), EPS_F);
        }
        {
            __half* Td = ((mat == 0) ? TQ[it & 1]
                        : (mat == 1) ? TK[it & 1] : TV[it & 1])[trow] + dh;
            #pragma unroll
            for (int j = 0; j < 4; j++) {
                const uint32_t* u = &r[j].x;
                uint4 w;
                const float2 f0 = u2f2(u[0]);
                const float2 f1 = u2f2(u[1]);
                const float2 f2 = u2f2(u[2]);
                const float2 f3 = u2f2(u[3]);
                w.x = h2u(f0.x * inv, f0.y * inv);
                w.y = h2u(f1.x * inv, f1.y * inv);
                w.z = h2u(f2.x * inv, f2.y * inv);
                w.w = h2u(f3.x * inv, f3.y * inv);
                ((uint4*)Td)[j] = w;
            }
        }
        uint4 rn[4];
        if (it + 1 < MNIT) {
            const __half* src = g_qkvh + base + (size_t)((it + 1) * 32 + trow) * C3;
            #pragma unroll
            for (int j = 0; j < 4; j++) rn[j] = ((const uint4*)src)[j];
        }
        __syncthreads();

        const uint32_t am = smem_u32((o == 0) ? TK[it & 1] : TQ[it & 1]);
        const uint32_t bm = smem_u32((o == 2) ? TQ[it & 1] : TV[it & 1]);
        #pragma unroll
        for (int ks = 0; ks < 2; ks++) {
            const int tokb = ks * 16;
            uint32_t af[2][4], bf[8][2];
            #pragma unroll
            for (int mi = 0; mi < 2; mi++) {
                const uint32_t addr = am +
                    ((tokb + a_tok) * TPITCH + mhalf + mi * 16 + a_d) * 2;
                ldsm_x4_trans(af[mi][0], af[mi][1], af[mi][2], af[mi][3], addr);
            }
            #pragma unroll
            for (int j = 0; j < 4; j++) {
                const uint32_t addr = bm +
                    ((tokb + b_tok) * TPITCH + j * 16 + b_d) * 2;
                ldsm_x4_trans(bf[2 * j][0], bf[2 * j][1],
                              bf[2 * j + 1][0], bf[2 * j + 1][1], addr);
            }
            #pragma unroll
            for (int mi = 0; mi < 2; mi++)
                #pragma unroll
                for (int ni = 0; ni < 8; ni++)
                    mma_f16_16x8x16(acc[mi][ni][0], acc[mi][ni][1],
                                    acc[mi][ni][2], acc[mi][ni][3],
                                    af[mi][0], af[mi][1], af[mi][2], af[mi][3],
                                    bf[ni][0], bf[ni][1]);
        }
        #pragma unroll
        for (int j = 0; j < 4; j++) r[j] = rn[j];
    }

    __half* outp = g_mparth + ((size_t)(ch * BH + bh) * 3 + o) * 4096;
    #pragma unroll
    for (int mi = 0; mi < 2; mi++) {
        #pragma unroll
        for (int ni = 0; ni < 8; ni++) {
            const int row = mhalf + mi * 16 + g;
            const int col = ni * 8 + 2 * t;
            *(__half2*)(outp + row * 64 + col) =
                __floats2half2_rn(acc[mi][ni][0], acc[mi][ni][1]);
            *(__half2*)(outp + (row + 8) * 64 + col) =
                __floats2half2_rn(acc[mi][ni][2], acc[mi][ni][3]);
        }
    }
}

// ---------------------------------------------------------------------------
// Parallel reduce of fp16 g_mparth over MCH chunks -> fp32 g_msum
// ---------------------------------------------------------------------------
#define RED_H8 (BH * 3 * DHEAD * DHEAD / 8)   // 36864

__global__ void __launch_bounds__(256) reduce_mpart_kernel()
{
    const int f8 = blockIdx.x * 256 + threadIdx.x;
    if (f8 >= RED_H8) return;
    const int elem = f8 * 8;
    const int bh_o = elem >> 12;          // bh*3+o
    const int i    = elem & 4095;

    float s[8];
    #pragma unroll
    for (int j = 0; j < 8; j++) s[j] = 0.f;
    #pragma unroll
    for (int ch = 0; ch < MCH; ch++) {
        const uint4 v = *(const uint4*)(
            g_mparth + ((size_t)(ch * 72 + bh_o)) * 4096 + i);
        const uint32_t* u = &v.x;
        #pragma unroll
        for (int q = 0; q < 4; q++) {
            const float2 f = u2f2(u[q]);
            s[q * 2]     += f.x;
            s[q * 2 + 1] += f.y;
        }
    }
    float* dst = g_msum + (size_t)bh_o * 4096 + i;
    *(float4*)(dst)     = make_float4(s[0], s[1], s[2], s[3]);
    *(float4*)(dst + 4) = make_float4(s[4], s[5], s[6], s[7]);
}

// ---------------------------------------------------------------------------
// Small combine: Mc = STEP*(SCALE*M2 - SCALE^2*M3@M1)
// ---------------------------------------------------------------------------
__global__ void __launch_bounds__(256) combine_small_kernel()
{
    const int bh  = blockIdx.x;
    const int tid = threadIdx.x;
    __shared__ float m1s[4096];
    __shared__ float m3s[4096];

    const float* src = g_msum + (size_t)bh * 3 * 4096;
    #pragma unroll
    for (int i = 0; i < 4; i++) {
        const int o4 = tid + i * 256;
        ((float4*)m1s)[o4] = ((const float4*)src)[o4];
        ((float4*)m3s)[o4] = ((const float4*)(src + 8192))[o4];
    }
    __syncthreads();

    const int tr = tid >> 4, tc = tid & 15;
    float p[4][4];
    #pragma unroll
    for (int i = 0; i < 4; i++)
        #pragma unroll
        for (int j = 0; j < 4; j++) p[i][j] = 0.f;

    for (int e = 0; e < 64; e++) {
        float a[4], bb[4];
        #pragma unroll
        for (int i = 0; i < 4; i++) a[i] = m3s[(tr * 4 + i) * 64 + e];
        #pragma unroll
        for (int j = 0; j < 4; j++) bb[j] = m1s[e * 64 + tc * 4 + j];
        #pragma unroll
        for (int i = 0; i < 4; i++)
            #pragma unroll
            for (int j = 0; j < 4; j++) p[i][j] += a[i] * bb[j];
    }

    const float c1 = STEP_F * SCALE_F;
    const float c2 = STEP_F * SCALE_F * SCALE_F;
    const float* m2p = src + 4096;
    #pragma unroll
    for (int i = 0; i < 4; i++)
        #pragma unroll
        for (int j = 0; j < 4; j++) {
            const int idx = (tr * 4 + i) * 64 + (tc * 4 + j);
            g_mc[(size_t)bh * 4096 + idx] = c1 * m2p[idx] - c2 * p[i][j];
        }
}

// ---------------------------------------------------------------------------
// outhead via tf32 mma with FUSED K-normalization; fp16 qkv input.
// Output: fp16 K-permuted (16-wide perm) half2 stores into g_aoh.
// ---------------------------------------------------------------------------
#define OH_KPITCH   68
#define OH_KS_FL    (128 * OH_KPITCH)
#define OH_MC_FL    (64 * OH_KPITCH)
#define OH_SMEM_BYTES ((OH_KS_FL + OH_MC_FL) * 4)   // 52224

__global__ void __launch_bounds__(128) outhead_mma_kernel()
{
    extern __shared__ float osm[];
    float* Ks  = osm;
    float* McT = osm + OH_KS_FL;

    const int bh   = blockIdx.y;
    const int tile = blockIdx.x;
    const int b = bh / HEADS_H, h = bh % HEADS_H;
    const int tid  = threadIdx.x;
    const int wid  = tid >> 5;
    const int lane = tid & 31;
    const int g    = lane >> 2;
    const int t    = lane & 3;
    const int n0   = tile * 128;

    {
        const int d1  = tid >> 1;
        const int d2g = (tid & 1) * 32;
        const float* src = g_mc + (size_t)bh * 4096 + d1 * 64 + d2g;
        #pragma unroll
        for (int j = 0; j < 8; j++) {
            float4 v = *(const float4*)(src + j * 4);
            McT[(d2g + j * 4 + 0) * OH_KPITCH + d1] = rtf(v.x);
            McT[(d2g + j * 4 + 1) * OH_KPITCH + d1] = rtf(v.y);
            McT[(d2g + j * 4 + 2) * OH_KPITCH + d1] = rtf(v.z);
            McT[(d2g + j * 4 + 3) * OH_KPITCH + d1] = rtf(v.w);
        }
    }
    {
        const __half* src = g_qkvh + (size_t)(b * NSEQ + n0 + tid) * C3 + 768 + h * 64;
        float kv[64];
        float ss = 0.f;
        #pragma unroll
        for (int j = 0; j < 8; j++) {
            const uint4 r = *(const uint4*)(src + j * 8);
            const uint32_t* u = &r.x;
            #pragma unroll
            for (int q = 0; q < 4; q++) {
                const float2 f = u2f2(u[q]);
                kv[j * 8 + q * 2]     = f.x;
                kv[j * 8 + q * 2 + 1] = f.y;
                ss += f.x * f.x + f.y * f.y;
            }
        }
        const float inv = 1.0f / fmaxf(sqrtf(ss), EPS_F);
        #pragma unroll
        for (int j = 0; j < 64; j++)
            Ks[tid * OH_KPITCH + j] = rtf(kv[j] * inv);
    }
    __syncthreads();

    const int mrow0 = wid * 32;
    float acc[2][8][4];
    #pragma unroll
    for (int mi = 0; mi < 2; mi++)
        #pragma unroll
        for (int ni = 0; ni < 8; ni++)
            #pragma unroll
            for (int c = 0; c < 4; c++) acc[mi][ni][c] = 0.0f;

    #pragma unroll
    for (int kk = 0; kk < 64; kk += 8) {
        uint32_t af[2][4], bf[8][2];
        #pragma unroll
        for (int mi = 0; mi < 2; mi++) {
            const int mrow = mrow0 + mi * 16;
            af[mi][0] = __float_as_uint(Ks[(mrow + g)     * OH_KPITCH + kk + t]);
            af[mi][1] = __float_as_uint(Ks[(mrow + g + 8) * OH_KPITCH + kk + t]);
            af[mi][2] = __float_as_uint(Ks[(mrow + g)     * OH_KPITCH + kk + t + 4]);
            af[mi][3] = __float_as_uint(Ks[(mrow + g + 8) * OH_KPITCH + kk + t + 4]);
        }
        #pragma unroll
        for (int ni = 0; ni < 8; ni++) {
            bf[ni][0] = __float_as_uint(McT[(ni * 8 + g) * OH_KPITCH + kk + t]);
            bf[ni][1] = __float_as_uint(McT[(ni * 8 + g) * OH_KPITCH + kk + t + 4]);
        }
        #pragma unroll
        for (int mi = 0; mi < 2; mi++)
            #pragma unroll
            for (int ni = 0; ni < 8; ni++)
                mma_tf32_16x8x8(acc[mi][ni][0], acc[mi][ni][1],
                                acc[mi][ni][2], acc[mi][ni][3],
                                af[mi][0], af[mi][1], af[mi][2], af[mi][3],
                                bf[ni][0], bf[ni][1]);
    }

    const float cadd = -STEP_F * LAMBD_F;
    #pragma unroll
    for (int mi = 0; mi < 2; mi++) {
        #pragma unroll
        for (int ni = 0; ni < 8; ni++) {
            const int d0 = ni * 8 + 2 * t;       // even
            const int c16 = d0 & 15;
            const int pos = (d0 & ~15) + 4 * ((c16 & 7) >> 1) + 2 * (c16 >> 3);
            #pragma unroll
            for (int half = 0; half < 2; half++) {
                const int tok = b * NSEQ + n0 + mrow0 + mi * 16 + g + half * 8;
                const __half2 vh = *(const __half2*)(
                    g_qkvh + (size_t)tok * C3 + 1536 + h * 64 + d0);
                const float2 v = __half22float2(vh);
                const float r0 = fmaxf(v.x + acc[mi][ni][half * 2 + 0] + cadd, 0.0f);
                const float r1 = fmaxf(v.y + acc[mi][ni][half * 2 + 1] + cadd, 0.0f);
                __half2* dst = (__half2*)(g_aoh + (size_t)tok * CDIM + h * 64 + pos);
                *dst = __floats2half2_rn(r0, r1);
            }
        }
    }
}

// ---------------------------------------------------------------------------
extern "C" void kernel_launch(void* const* d_in, const int* in_sizes, int n_in,
                              void* d_out, int out_size)
{
    const float* x     = (const float*)d_in[0];
    const float* Wqkv  = (const float*)d_in[1];
    const float* Wproj = (const float*)d_in[2];
    const float* bproj = (const float*)d_in[3];
    float* out = (float*)d_out;

    __half* qkvh; cudaGetSymbolAddress((void**)&qkvh, g_qkvh);
    __half* aoh;  cudaGetSymbolAddress((void**)&aoh,  g_aoh);
    __half* xh;   cudaGetSymbolAddress((void**)&xh,   g_xh);
    __half* wqh;  cudaGetSymbolAddress((void**)&wqh,  g_wqkvh);
    __half* wph;  cudaGetSymbolAddress((void**)&wph,  g_wprojh);

    cudaFuncSetAttribute(gemm_f16_pipe<true>,
                         cudaFuncAttributeMaxDynamicSharedMemorySize, HGSMEM);
    cudaFuncSetAttribute(gemm_f16_pipe<false>,
                         cudaFuncAttributeMaxDynamicSharedMemorySize, HGSMEM);
    cudaFuncSetAttribute(outhead_mma_kernel,
                         cudaFuncAttributeMaxDynamicSharedMemorySize,
                         OH_SMEM_BYTES);

    // 0. Convert + K-permute all GEMM operands to fp16
    round_perm_kernel<<<(HG3 + 255) / 256, 256>>>(x, Wqkv, Wproj);

    // 1. qkv = x @ Wqkv^T  (fp16 MMA, fp16 output)
    gemm_f16_pipe<true><<<dim3(C3 / 128, TOKENS / 128), 128, HGSMEM>>>(
        xh, wqh, nullptr, qkvh, TOKENS, C3, CDIM);
    // 2. Per-head moments (fp16 mma + ldmatrix, fused q/k normalization)
    moments_mma_kernel<<<dim3(BH, MCH), 192>>>();
    // 3a. Parallel reduce of fp16 chunk partials
    reduce_mpart_kernel<<<(RED_H8 + 255) / 256, 256>>>();
    // 3b. Mc = STEP*(SCALE*M2 - SCALE^2 * M3@M1)
    combine_small_kernel<<<BH, 256>>>();
    // 4. relu(V + norm(K)@Mc - STEP*LAMBD), fp16 K-permuted output
    outhead_mma_kernel<<<dim3(NSEQ / 128, BH), 128, OH_SMEM_BYTES>>>();
    // 5. out = ao @ Wproj^T + bproj  (fp16 MMA, fp32 output)
    gemm_f16_pipe<false><<<dim3(CDIM / 128, TOKENS / 128), 128, HGSMEM>>>(
        aoh, wph, bproj, out, TOKENS, CDIM, CDIM);
}